// round 1
// baseline (speedup 1.0000x reference)
#include <cuda_runtime.h>
#include <math.h>

#define BATCH   4
#define SEQ     2048
#define DMODEL  2048
#define NHEADS  16
#define NKV     4
#define DHEAD   128

// Scratch (allocation-free rule: __device__ globals)
__device__ float g_q[BATCH * SEQ * NHEADS * DHEAD];   // [b,s,h,d]  64 MB
__device__ float g_k[BATCH * SEQ * NKV * DHEAD];      // [b,s,kv,d] 16 MB
__device__ float g_v[BATCH * SEQ * NKV * DHEAD];      // 16 MB
__device__ float g_o[BATCH * SEQ * NHEADS * DHEAD];   // 64 MB

// ---------------------------------------------------------------------------
// SGEMM: C[M,N] = A[M,K] @ B[K,N], all row-major fp32.
// BM=BN=128, BK=16, 256 threads, 8x8 per thread.
// M, N assumed multiples of 128; K multiple of 16. (Holds for all calls here.)
// ---------------------------------------------------------------------------
__global__ __launch_bounds__(256) void sgemm_kernel(
    const float* __restrict__ A, const float* __restrict__ B,
    float* __restrict__ C, int M, int N, int K)
{
    constexpr int BM = 128, BN = 128, BK = 16;
    __shared__ float As[BK][BM];   // transposed: As[k][m]
    __shared__ float Bs[BK][BN];

    const int t  = threadIdx.x;
    const int tx = t & 15, ty = t >> 4;
    const int aRow = t >> 2;          // 0..63
    const int aCol = (t & 3) << 2;    // 0,4,8,12
    const int bRow = t >> 5;          // 0..7
    const int bCol = (t & 31) << 2;   // 0..124

    const float* Ab = A + (size_t)(blockIdx.y * BM) * K;
    const float* Bb = B + blockIdx.x * BN;

    float acc[8][8];
#pragma unroll
    for (int i = 0; i < 8; i++)
#pragma unroll
        for (int j = 0; j < 8; j++) acc[i][j] = 0.f;

    for (int k0 = 0; k0 < K; k0 += BK) {
#pragma unroll
        for (int r2 = 0; r2 < 2; r2++) {
            int r = aRow + r2 * 64;
            float4 av = *(const float4*)(Ab + (size_t)r * K + k0 + aCol);
            As[aCol + 0][r] = av.x;
            As[aCol + 1][r] = av.y;
            As[aCol + 2][r] = av.z;
            As[aCol + 3][r] = av.w;
        }
#pragma unroll
        for (int r2 = 0; r2 < 2; r2++) {
            int r = bRow + r2 * 8;
            *(float4*)(&Bs[r][bCol]) = *(const float4*)(Bb + (size_t)(k0 + r) * N + bCol);
        }
        __syncthreads();
#pragma unroll
        for (int kk = 0; kk < BK; kk++) {
            float a[8], b[8];
            *(float4*)(a)     = *(const float4*)(&As[kk][ty * 8]);
            *(float4*)(a + 4) = *(const float4*)(&As[kk][ty * 8 + 4]);
            *(float4*)(b)     = *(const float4*)(&Bs[kk][tx * 8]);
            *(float4*)(b + 4) = *(const float4*)(&Bs[kk][tx * 8 + 4]);
#pragma unroll
            for (int i = 0; i < 8; i++)
#pragma unroll
                for (int j = 0; j < 8; j++)
                    acc[i][j] = fmaf(a[i], b[j], acc[i][j]);
        }
        __syncthreads();
    }

    float* Cb = C + (size_t)(blockIdx.y * BM) * N + blockIdx.x * BN;
#pragma unroll
    for (int i = 0; i < 8; i++) {
        int r = ty * 8 + i;
        *(float4*)(Cb + (size_t)r * N + tx * 8) =
            make_float4(acc[i][0], acc[i][1], acc[i][2], acc[i][3]);
        *(float4*)(Cb + (size_t)r * N + tx * 8 + 4) =
            make_float4(acc[i][4], acc[i][5], acc[i][6], acc[i][7]);
    }
}

// ---------------------------------------------------------------------------
// RoPE in-place on [B*S, heads, 128]. One thread per (row, freq-index i<64),
// loops over heads. fp64 trig to stay centered on the true rotation.
// ---------------------------------------------------------------------------
__global__ void rope_kernel(float* __restrict__ buf, int heads)
{
    int idx = blockIdx.x * blockDim.x + threadIdx.x;
    const int total = BATCH * SEQ * (DHEAD / 2);
    if (idx >= total) return;
    int i   = idx & 63;
    int row = idx >> 6;              // b*SEQ + s
    int s   = row & (SEQ - 1);
    // inv_freq = 10000^(-i/64) = exp(-i * ln(10000)/64)
    double inv = exp(-0.14391156831212787 * (double)i);
    double sd, cd;
    sincos((double)s * inv, &sd, &cd);
    float c = (float)cd, sn = (float)sd;
    float* p = buf + (size_t)row * heads * DHEAD;
    for (int hh = 0; hh < heads; hh++, p += DHEAD) {
        float x1 = p[i], x2 = p[i + 64];
        p[i]      = x1 * c - x2 * sn;
        p[i + 64] = x2 * c + x1 * sn;
    }
}

// ---------------------------------------------------------------------------
// Causal flash attention, fp32 SIMT.
// Block = one (b, h, 64-query tile). 128 threads (8x16 grid, 8 rows x 8 dcols
// of O per thread). K tiles of 64 keys. Online softmax.
// smem: Qst[128][64] d-major, Kst[128][64] d-major, Vs[64][128], Ps[64][64].
// ---------------------------------------------------------------------------
#define ATT_SMEM ((128 * 64 + 128 * 64 + 64 * 128 + 64 * 64 + 3 * 64) * 4)

__global__ __launch_bounds__(128) void attn_kernel(const float* __restrict__ tptr)
{
    extern __shared__ float sm[];
    float* Qst  = sm;                  // [128][64]
    float* Kst  = Qst + 128 * 64;      // [128][64]
    float* Vs   = Kst + 128 * 64;      // [64][128]
    float* Ps   = Vs + 64 * 128;       // [64][64]
    float* m_s  = Ps + 64 * 64;        // [64]
    float* l_s  = m_s + 64;            // [64]
    float* al_s = l_s + 64;            // [64]

    const int t  = threadIdx.x;
    const int ty = t >> 4, tx = t & 15;
    const int qt = blockIdx.x, h = blockIdx.y, b = blockIdx.z;
    const int kv = h >> 2;             // GROUPS = 4
    const int q0 = qt * 64;
    const float scale = 0.08838834764831845f / fmaxf(fabsf(tptr[0]), 1e-6f);

    const float* qb = g_q + ((size_t)b * SEQ * NHEADS + h) * DHEAD;  // row stride 2048
    const float* kb = g_k + ((size_t)b * SEQ * NKV + kv) * DHEAD;    // row stride 512
    const float* vb = g_v + ((size_t)b * SEQ * NKV + kv) * DHEAD;

    // Load Q tile transposed (lane-per-row mapping -> conflict-free STS)
#pragma unroll
    for (int it = 0; it < 16; it++) {
        int fid = t + 128 * it;            // 0..2047 float4 ids
        int row = fid & 63;
        int dq  = (fid >> 6) << 2;         // 0..124
        float4 v = *(const float4*)(qb + (size_t)(q0 + row) * (NHEADS * DHEAD) + dq);
        Qst[(dq + 0) * 64 + row] = v.x;
        Qst[(dq + 1) * 64 + row] = v.y;
        Qst[(dq + 2) * 64 + row] = v.z;
        Qst[(dq + 3) * 64 + row] = v.w;
    }
    if (t < 64) { m_s[t] = -3.0e38f; l_s[t] = 0.f; }

    float o[8][8];
#pragma unroll
    for (int i = 0; i < 8; i++)
#pragma unroll
        for (int j = 0; j < 8; j++) o[i][j] = 0.f;

    for (int kt = 0; kt <= qt; kt++) {
        __syncthreads();                   // protect Kst/Vs from prev readers; Q/m init
        const int k0 = kt * 64;
#pragma unroll
        for (int it = 0; it < 16; it++) {
            int fid = t + 128 * it;
            {   // K transposed (lane-per-row)
                int row = fid & 63;
                int dq  = (fid >> 6) << 2;
                float4 v = *(const float4*)(kb + (size_t)(k0 + row) * (NKV * DHEAD) + dq);
                Kst[(dq + 0) * 64 + row] = v.x;
                Kst[(dq + 1) * 64 + row] = v.y;
                Kst[(dq + 2) * 64 + row] = v.z;
                Kst[(dq + 3) * 64 + row] = v.w;
            }
            {   // V natural (coalesced)
                int row = fid >> 5;
                int dq  = (fid & 31) << 2;
                *(float4*)(&Vs[row * 128 + dq]) =
                    *(const float4*)(vb + (size_t)(k0 + row) * (NKV * DHEAD) + dq);
            }
        }
        __syncthreads();

        // S[8x4 per thread] = Q K^T
        float sacc[8][4];
#pragma unroll
        for (int i = 0; i < 8; i++)
#pragma unroll
            for (int j = 0; j < 4; j++) sacc[i][j] = 0.f;

#pragma unroll 8
        for (int d = 0; d < 128; d++) {
            float a[8], kr[4];
            *(float4*)(a)     = *(const float4*)(&Qst[d * 64 + ty * 8]);
            *(float4*)(a + 4) = *(const float4*)(&Qst[d * 64 + ty * 8 + 4]);
            *(float4*)(kr)    = *(const float4*)(&Kst[d * 64 + tx * 4]);
#pragma unroll
            for (int i = 0; i < 8; i++)
#pragma unroll
                for (int j = 0; j < 4; j++)
                    sacc[i][j] = fmaf(a[i], kr[j], sacc[i][j]);
        }

        // scale + causal mask + store S tile
#pragma unroll
        for (int i = 0; i < 8; i++) {
            int qi = q0 + ty * 8 + i;
            float v0 = sacc[i][0] * scale; if (k0 + tx * 4 + 0 > qi) v0 = -3.0e38f;
            float v1 = sacc[i][1] * scale; if (k0 + tx * 4 + 1 > qi) v1 = -3.0e38f;
            float v2 = sacc[i][2] * scale; if (k0 + tx * 4 + 2 > qi) v2 = -3.0e38f;
            float v3 = sacc[i][3] * scale; if (k0 + tx * 4 + 3 > qi) v3 = -3.0e38f;
            *(float4*)(&Ps[(ty * 8 + i) * 64 + tx * 4]) = make_float4(v0, v1, v2, v3);
        }
        __syncthreads();

        // Online softmax per row (threads 0..63; staggered cols -> no bank conflicts)
        if (t < 64) {
            float mx = m_s[t];
#pragma unroll 8
            for (int c0 = 0; c0 < 64; c0++) {
                int c = (c0 + t) & 63;
                mx = fmaxf(mx, Ps[t * 64 + c]);
            }
            float alpha = __expf(m_s[t] - mx);
            float l = l_s[t] * alpha;
#pragma unroll 8
            for (int c0 = 0; c0 < 64; c0++) {
                int c = (c0 + t) & 63;
                float p = __expf(Ps[t * 64 + c] - mx);
                Ps[t * 64 + c] = p;
                l += p;
            }
            m_s[t] = mx; l_s[t] = l; al_s[t] = alpha;
        }
        __syncthreads();

        // rescale O
#pragma unroll
        for (int i = 0; i < 8; i++) {
            float a = al_s[ty * 8 + i];
#pragma unroll
            for (int j = 0; j < 8; j++) o[i][j] *= a;
        }

        // O += P V
#pragma unroll 4
        for (int j4 = 0; j4 < 16; j4++) {
            float4 p4[8];
#pragma unroll
            for (int i = 0; i < 8; i++)
                p4[i] = *(const float4*)(&Ps[(ty * 8 + i) * 64 + j4 * 4]);
#pragma unroll
            for (int u = 0; u < 4; u++) {
                float vr[8];
                *(float4*)(vr)     = *(const float4*)(&Vs[(j4 * 4 + u) * 128 + tx * 8]);
                *(float4*)(vr + 4) = *(const float4*)(&Vs[(j4 * 4 + u) * 128 + tx * 8 + 4]);
#pragma unroll
                for (int i = 0; i < 8; i++) {
                    float p = (u == 0) ? p4[i].x : (u == 1) ? p4[i].y
                            : (u == 2) ? p4[i].z : p4[i].w;
#pragma unroll
                    for (int j = 0; j < 8; j++)
                        o[i][j] = fmaf(p, vr[j], o[i][j]);
                }
            }
        }
    }

    // Normalize + write O tile: g_o layout [b,s,h,d]
    float* ob = g_o + ((size_t)b * SEQ * NHEADS + h) * DHEAD;
#pragma unroll
    for (int i = 0; i < 8; i++) {
        int qi = q0 + ty * 8 + i;
        float inv = 1.0f / l_s[ty * 8 + i];
        *(float4*)(ob + (size_t)qi * (NHEADS * DHEAD) + tx * 8) =
            make_float4(o[i][0] * inv, o[i][1] * inv, o[i][2] * inv, o[i][3] * inv);
        *(float4*)(ob + (size_t)qi * (NHEADS * DHEAD) + tx * 8 + 4) =
            make_float4(o[i][4] * inv, o[i][5] * inv, o[i][6] * inv, o[i][7] * inv);
    }
}

// ---------------------------------------------------------------------------
extern "C" void kernel_launch(void* const* d_in, const int* in_sizes, int n_in,
                              void* d_out, int out_size)
{
    const float* x  = (const float*)d_in[0];
    const float* wq = (const float*)d_in[1];
    const float* wk = (const float*)d_in[2];
    const float* wv = (const float*)d_in[3];
    const float* wo = (const float*)d_in[4];
    const float* tp = (const float*)d_in[5];
    float* out = (float*)d_out;

    float *qp, *kp, *vp, *op;
    cudaGetSymbolAddress((void**)&qp, g_q);
    cudaGetSymbolAddress((void**)&kp, g_k);
    cudaGetSymbolAddress((void**)&vp, g_v);
    cudaGetSymbolAddress((void**)&op, g_o);

    const int M = BATCH * SEQ;  // 8192

    // QKV projections (write straight into [b,s,h,d] layouts)
    sgemm_kernel<<<dim3(DMODEL / 128, M / 128), 256>>>(x, wq, qp, M, DMODEL, DMODEL);
    sgemm_kernel<<<dim3((NKV * DHEAD) / 128, M / 128), 256>>>(x, wk, kp, M, NKV * DHEAD, DMODEL);
    sgemm_kernel<<<dim3((NKV * DHEAD) / 128, M / 128), 256>>>(x, wv, vp, M, NKV * DHEAD, DMODEL);

    // RoPE (in-place)
    const int rthreads = BATCH * SEQ * (DHEAD / 2);
    rope_kernel<<<(rthreads + 255) / 256, 256>>>(qp, NHEADS);
    rope_kernel<<<(rthreads + 255) / 256, 256>>>(kp, NKV);

    // Causal grouped attention
    cudaFuncSetAttribute(attn_kernel, cudaFuncAttributeMaxDynamicSharedMemorySize, ATT_SMEM);
    attn_kernel<<<dim3(SEQ / 64, NHEADS, BATCH), 128, ATT_SMEM>>>(tp);

    // Output projection
    sgemm_kernel<<<dim3(DMODEL / 128, M / 128), 256>>>(op, wo, out, M, DMODEL, DMODEL);
}

// round 3
// speedup vs baseline: 1.7365x; 1.7365x over previous
#include <cuda_runtime.h>
#include <cuda_bf16.h>
#include <math.h>
#include <stdint.h>

#define BATCH   4
#define SEQ     2048
#define DMODEL  2048
#define NHEADS  16
#define NKV     4
#define DHEAD   128
#define MTOT    (BATCH * SEQ)          // 8192
#define NKVD    (NKV * DHEAD)          // 512

// ---------------- scratch (allocation-free rule: device globals) ----------
__device__ float g_q[MTOT * NHEADS * DHEAD];
__device__ float g_k[MTOT * NKVD];
__device__ float g_v[MTOT * NKVD];
__device__ float g_o[MTOT * NHEADS * DHEAD];

__device__ __nv_bfloat16 g_xh[MTOT * DMODEL], g_xl[MTOT * DMODEL];
__device__ __nv_bfloat16 g_oh[MTOT * DMODEL], g_ol[MTOT * DMODEL];
__device__ __nv_bfloat16 g_wqh[DMODEL * DMODEL], g_wql[DMODEL * DMODEL];
__device__ __nv_bfloat16 g_wkh[NKVD * DMODEL],  g_wkl[NKVD * DMODEL];
__device__ __nv_bfloat16 g_wvh[NKVD * DMODEL],  g_wvl[NKVD * DMODEL];
__device__ __nv_bfloat16 g_woh[DMODEL * DMODEL], g_wol[DMODEL * DMODEL];

// ---------------- helpers ---------------------------------------------
__device__ __forceinline__ uint32_t smem_u32(const void* p) {
    uint32_t a;
    asm("{ .reg .u64 t; cvta.to.shared.u64 t, %1; cvt.u32.u64 %0, t; }"
        : "=r"(a) : "l"(p));
    return a;
}
#define SWZ128(o) ((o) ^ (((o) >> 3) & 0x70))

__device__ __forceinline__ void ldsm4(uint32_t& r0, uint32_t& r1,
                                      uint32_t& r2, uint32_t& r3, uint32_t addr) {
    asm volatile("ldmatrix.sync.aligned.m8n8.x4.shared.b16 {%0,%1,%2,%3}, [%4];"
                 : "=r"(r0), "=r"(r1), "=r"(r2), "=r"(r3) : "r"(addr));
}
__device__ __forceinline__ void mma16816(float* c, uint32_t a0, uint32_t a1,
                                         uint32_t a2, uint32_t a3,
                                         uint32_t b0, uint32_t b1) {
    asm volatile(
        "mma.sync.aligned.m16n8k16.row.col.f32.bf16.bf16.f32 "
        "{%0,%1,%2,%3},{%4,%5,%6,%7},{%8,%9},{%0,%1,%2,%3};"
        : "+f"(c[0]), "+f"(c[1]), "+f"(c[2]), "+f"(c[3])
        : "r"(a0), "r"(a1), "r"(a2), "r"(a3), "r"(b0), "r"(b1));
}

// ---------------------------------------------------------------------------
// HMMA split-bf16 GEMM: C[M,N] = A[M,K] @ B[N,K]^T.
// A,B as bf16 (hi,lo); C = Ah*Bh + Ah*Bl + Al*Bh (fp32 accum).
// CTA 128x128, 8 warps (2x4), warp tile 64x32, BK=64, 2-stage cp.async.
// ---------------------------------------------------------------------------
#define GKC      64
#define TILEB    16384                    // 128 rows x 128B
#define STAGEB   (4 * TILEB)              // Ah, Al, Bh, Bl
#define GSMEM    (2 * STAGEB)             // 131072

__device__ __forceinline__ void gemm_issue_loads(
    uint32_t sb, int stage, int it,
    const __nv_bfloat16* __restrict__ Ah, const __nv_bfloat16* __restrict__ Al,
    const __nv_bfloat16* __restrict__ Bh, const __nv_bfloat16* __restrict__ Bl,
    int m0, int n0, int K, int tid)
{
    const int k0 = it * GKC;
    const __nv_bfloat16* srcs[4] = { Ah, Al, Bh, Bl };
#pragma unroll
    for (int mtx = 0; mtx < 4; mtx++) {
        const __nv_bfloat16* src = srcs[mtx];
        const int rowbase = (mtx < 2) ? m0 : n0;
        const uint32_t smb = sb + stage * STAGEB + mtx * TILEB;
#pragma unroll
        for (int j = 0; j < 4; j++) {
            int chunk = tid + j * 256;          // 0..1023
            int row = chunk >> 3;               // 0..127
            int c16 = chunk & 7;                // 0..7 (16B units)
            const void* gp = src + (size_t)(rowbase + row) * K + k0 + c16 * 8;
            uint32_t sp = smb + SWZ128(row * 128 + c16 * 16);
            asm volatile("cp.async.cg.shared.global [%0], [%1], 16;"
                         :: "r"(sp), "l"(gp));
        }
    }
    asm volatile("cp.async.commit_group;" ::: "memory");
}

__global__ __launch_bounds__(256, 1) void hmma_gemm_kernel(
    const __nv_bfloat16* __restrict__ Ah, const __nv_bfloat16* __restrict__ Al,
    const __nv_bfloat16* __restrict__ Bh, const __nv_bfloat16* __restrict__ Bl,
    float* __restrict__ C, int M, int N, int K)
{
    extern __shared__ char smem[];
    const uint32_t sb = smem_u32(smem);
    const int tid = threadIdx.x;
    const int wid = tid >> 5;
    const int l   = tid & 31;
    const int wm  = wid >> 2;              // 0..1
    const int wn  = wid & 3;               // 0..3
    const int m0  = blockIdx.y * 128;
    const int n0  = blockIdx.x * 128;

    float acc[4][4][4];                    // [mt][nt][frag]
#pragma unroll
    for (int i = 0; i < 4; i++)
#pragma unroll
        for (int j = 0; j < 4; j++)
#pragma unroll
            for (int f = 0; f < 4; f++) acc[i][j][f] = 0.f;

    // per-lane ldmatrix row/col components
    const int a_row_l = (l & 7) + (l & 8);          // row within m16 tile
    const int a_col_l = ((l >> 4) & 1) * 16;        // byte offset (k 8..15 half)
    const int b_row_l = (l & 7) + ((l >> 4) & 1) * 8;
    const int b_col_l = ((l >> 3) & 1) * 16;

    const int niter = K / GKC;
    gemm_issue_loads(sb, 0, 0, Ah, Al, Bh, Bl, m0, n0, K, tid);

    for (int it = 0; it < niter; it++) {
        if (it + 1 < niter) {
            gemm_issue_loads(sb, (it + 1) & 1, it + 1, Ah, Al, Bh, Bl, m0, n0, K, tid);
            asm volatile("cp.async.wait_group 1;" ::: "memory");
        } else {
            asm volatile("cp.async.wait_group 0;" ::: "memory");
        }
        __syncthreads();

        const uint32_t stg = sb + (it & 1) * STAGEB;
        const uint32_t sAh = stg;
        const uint32_t sAl = stg + TILEB;
        const uint32_t sBh = stg + 2 * TILEB;
        const uint32_t sBl = stg + 3 * TILEB;

#pragma unroll
        for (int kk = 0; kk < 4; kk++) {
            const int kb = kk * 32;        // byte offset of this k16 step
            uint32_t ah[4][4], al[4][4], bh[8], bl[8];
#pragma unroll
            for (int mt = 0; mt < 4; mt++) {
                int row = wm * 64 + mt * 16 + a_row_l;
                uint32_t off = SWZ128(row * 128 + kb + a_col_l);
                ldsm4(ah[mt][0], ah[mt][1], ah[mt][2], ah[mt][3], sAh + off);
                ldsm4(al[mt][0], al[mt][1], al[mt][2], al[mt][3], sAl + off);
            }
#pragma unroll
            for (int nt2 = 0; nt2 < 2; nt2++) {
                int row = wn * 32 + nt2 * 16 + b_row_l;
                uint32_t off = SWZ128(row * 128 + kb + b_col_l);
                ldsm4(bh[nt2 * 4 + 0], bh[nt2 * 4 + 1], bh[nt2 * 4 + 2], bh[nt2 * 4 + 3], sBh + off);
                ldsm4(bl[nt2 * 4 + 0], bl[nt2 * 4 + 1], bl[nt2 * 4 + 2], bl[nt2 * 4 + 3], sBl + off);
            }
#pragma unroll
            for (int mt = 0; mt < 4; mt++)
#pragma unroll
                for (int nt = 0; nt < 4; nt++) {
                    uint32_t b0h = bh[(nt >> 1) * 4 + (nt & 1) * 2];
                    uint32_t b1h = bh[(nt >> 1) * 4 + (nt & 1) * 2 + 1];
                    uint32_t b0l = bl[(nt >> 1) * 4 + (nt & 1) * 2];
                    uint32_t b1l = bl[(nt >> 1) * 4 + (nt & 1) * 2 + 1];
                    mma16816(acc[mt][nt], ah[mt][0], ah[mt][1], ah[mt][2], ah[mt][3], b0h, b1h);
                    mma16816(acc[mt][nt], ah[mt][0], ah[mt][1], ah[mt][2], ah[mt][3], b0l, b1l);
                    mma16816(acc[mt][nt], al[mt][0], al[mt][1], al[mt][2], al[mt][3], b0h, b1h);
                }
        }
        __syncthreads();
    }

    // epilogue
#pragma unroll
    for (int mt = 0; mt < 4; mt++) {
        int r0 = m0 + wm * 64 + mt * 16 + (l >> 2);
        int r1 = r0 + 8;
#pragma unroll
        for (int nt = 0; nt < 4; nt++) {
            int c = n0 + wn * 32 + nt * 8 + (l & 3) * 2;
            *(float2*)(C + (size_t)r0 * N + c) = make_float2(acc[mt][nt][0], acc[mt][nt][1]);
            *(float2*)(C + (size_t)r1 * N + c) = make_float2(acc[mt][nt][2], acc[mt][nt][3]);
        }
    }
}

// ---------------------------------------------------------------------------
// fp32 -> (bf16 hi, bf16 lo) elementwise split
// ---------------------------------------------------------------------------
__global__ void split_kernel(const float4* __restrict__ in,
                             uint2* __restrict__ hi, uint2* __restrict__ lo, int n4)
{
    int i = blockIdx.x * blockDim.x + threadIdx.x;
    if (i >= n4) return;
    float4 v = in[i];
    __nv_bfloat16 h[4], lw[4];
    float x[4] = { v.x, v.y, v.z, v.w };
#pragma unroll
    for (int j = 0; j < 4; j++) {
        h[j] = __float2bfloat16(x[j]);
        lw[j] = __float2bfloat16(x[j] - __bfloat162float(h[j]));
    }
    hi[i] = *(uint2*)h;
    lo[i] = *(uint2*)lw;
}

// ---------------------------------------------------------------------------
// weight transpose + split: w[K,N] fp32 -> Wh/Wl[N,K] bf16
// ---------------------------------------------------------------------------
__global__ void tsplit_kernel(const float* __restrict__ w,
                              __nv_bfloat16* __restrict__ th,
                              __nv_bfloat16* __restrict__ tl, int Kd, int Nd)
{
    __shared__ float tile[32][33];
    int n0 = blockIdx.x * 32, k0 = blockIdx.y * 32;
    int tx = threadIdx.x, ty = threadIdx.y;   // 32 x 8
#pragma unroll
    for (int j = 0; j < 32; j += 8)
        tile[ty + j][tx] = w[(size_t)(k0 + ty + j) * Nd + n0 + tx];
    __syncthreads();
#pragma unroll
    for (int j = 0; j < 32; j += 8) {
        float x = tile[tx][ty + j];
        __nv_bfloat16 h = __float2bfloat16(x);
        size_t idx = (size_t)(n0 + ty + j) * Kd + k0 + tx;
        th[idx] = h;
        tl[idx] = __float2bfloat16(x - __bfloat162float(h));
    }
}

// ---------------------------------------------------------------------------
// RoPE in-place on [B*S, heads, 128]
// ---------------------------------------------------------------------------
__global__ void rope_kernel(float* __restrict__ buf, int heads)
{
    int idx = blockIdx.x * blockDim.x + threadIdx.x;
    const int total = BATCH * SEQ * (DHEAD / 2);
    if (idx >= total) return;
    int i   = idx & 63;
    int row = idx >> 6;
    int s   = row & (SEQ - 1);
    double inv = exp(-0.14391156831212787 * (double)i);
    double sd, cd;
    sincos((double)s * inv, &sd, &cd);
    float c = (float)cd, sn = (float)sd;
    float* p = buf + (size_t)row * heads * DHEAD;
    for (int hh = 0; hh < heads; hh++, p += DHEAD) {
        float x1 = p[i], x2 = p[i + 64];
        p[i]      = x1 * c - x2 * sn;
        p[i + 64] = x2 * c + x1 * sn;
    }
}

// ---------------------------------------------------------------------------
// Causal flash attention, fp32 SIMT
// ---------------------------------------------------------------------------
#define ATT_SMEM ((128 * 64 + 128 * 64 + 64 * 128 + 64 * 64 + 3 * 64) * 4)

__global__ __launch_bounds__(128) void attn_kernel(const float* __restrict__ tptr)
{
    extern __shared__ float sm[];
    float* Qst  = sm;
    float* Kst  = Qst + 128 * 64;
    float* Vs   = Kst + 128 * 64;
    float* Ps   = Vs + 64 * 128;
    float* m_s  = Ps + 64 * 64;
    float* l_s  = m_s + 64;
    float* al_s = l_s + 64;

    const int t  = threadIdx.x;
    const int ty = t >> 4, tx = t & 15;
    const int qt = blockIdx.x, h = blockIdx.y, b = blockIdx.z;
    const int kv = h >> 2;
    const int q0 = qt * 64;
    const float scale = 0.08838834764831845f / fmaxf(fabsf(tptr[0]), 1e-6f);

    const float* qb = g_q + ((size_t)b * SEQ * NHEADS + h) * DHEAD;
    const float* kb = g_k + ((size_t)b * SEQ * NKV + kv) * DHEAD;
    const float* vb = g_v + ((size_t)b * SEQ * NKV + kv) * DHEAD;

#pragma unroll
    for (int it = 0; it < 16; it++) {
        int fid = t + 128 * it;
        int row = fid & 63;
        int dq  = (fid >> 6) << 2;
        float4 v = *(const float4*)(qb + (size_t)(q0 + row) * (NHEADS * DHEAD) + dq);
        Qst[(dq + 0) * 64 + row] = v.x;
        Qst[(dq + 1) * 64 + row] = v.y;
        Qst[(dq + 2) * 64 + row] = v.z;
        Qst[(dq + 3) * 64 + row] = v.w;
    }
    if (t < 64) { m_s[t] = -3.0e38f; l_s[t] = 0.f; }

    float o[8][8];
#pragma unroll
    for (int i = 0; i < 8; i++)
#pragma unroll
        for (int j = 0; j < 8; j++) o[i][j] = 0.f;

    for (int kt = 0; kt <= qt; kt++) {
        __syncthreads();
        const int k0 = kt * 64;
#pragma unroll
        for (int it = 0; it < 16; it++) {
            int fid = t + 128 * it;
            {
                int row = fid & 63;
                int dq  = (fid >> 6) << 2;
                float4 v = *(const float4*)(kb + (size_t)(k0 + row) * NKVD + dq);
                Kst[(dq + 0) * 64 + row] = v.x;
                Kst[(dq + 1) * 64 + row] = v.y;
                Kst[(dq + 2) * 64 + row] = v.z;
                Kst[(dq + 3) * 64 + row] = v.w;
            }
            {
                int row = fid >> 5;
                int dq  = (fid & 31) << 2;
                *(float4*)(&Vs[row * 128 + dq]) =
                    *(const float4*)(vb + (size_t)(k0 + row) * NKVD + dq);
            }
        }
        __syncthreads();

        float sacc[8][4];
#pragma unroll
        for (int i = 0; i < 8; i++)
#pragma unroll
            for (int j = 0; j < 4; j++) sacc[i][j] = 0.f;

#pragma unroll 8
        for (int d = 0; d < 128; d++) {
            float a[8], kr[4];
            *(float4*)(a)     = *(const float4*)(&Qst[d * 64 + ty * 8]);
            *(float4*)(a + 4) = *(const float4*)(&Qst[d * 64 + ty * 8 + 4]);
            *(float4*)(kr)    = *(const float4*)(&Kst[d * 64 + tx * 4]);
#pragma unroll
            for (int i = 0; i < 8; i++)
#pragma unroll
                for (int j = 0; j < 4; j++)
                    sacc[i][j] = fmaf(a[i], kr[j], sacc[i][j]);
        }

#pragma unroll
        for (int i = 0; i < 8; i++) {
            int qi = q0 + ty * 8 + i;
            float v0 = sacc[i][0] * scale; if (k0 + tx * 4 + 0 > qi) v0 = -3.0e38f;
            float v1 = sacc[i][1] * scale; if (k0 + tx * 4 + 1 > qi) v1 = -3.0e38f;
            float v2 = sacc[i][2] * scale; if (k0 + tx * 4 + 2 > qi) v2 = -3.0e38f;
            float v3 = sacc[i][3] * scale; if (k0 + tx * 4 + 3 > qi) v3 = -3.0e38f;
            *(float4*)(&Ps[(ty * 8 + i) * 64 + tx * 4]) = make_float4(v0, v1, v2, v3);
        }
        __syncthreads();

        if (t < 64) {
            float mx = m_s[t];
#pragma unroll 8
            for (int c0 = 0; c0 < 64; c0++) {
                int c = (c0 + t) & 63;
                mx = fmaxf(mx, Ps[t * 64 + c]);
            }
            float alpha = __expf(m_s[t] - mx);
            float lsum = l_s[t] * alpha;
#pragma unroll 8
            for (int c0 = 0; c0 < 64; c0++) {
                int c = (c0 + t) & 63;
                float p = __expf(Ps[t * 64 + c] - mx);
                Ps[t * 64 + c] = p;
                lsum += p;
            }
            m_s[t] = mx; l_s[t] = lsum; al_s[t] = alpha;
        }
        __syncthreads();

#pragma unroll
        for (int i = 0; i < 8; i++) {
            float a = al_s[ty * 8 + i];
#pragma unroll
            for (int j = 0; j < 8; j++) o[i][j] *= a;
        }

#pragma unroll 4
        for (int j4 = 0; j4 < 16; j4++) {
            float4 p4[8];
#pragma unroll
            for (int i = 0; i < 8; i++)
                p4[i] = *(const float4*)(&Ps[(ty * 8 + i) * 64 + j4 * 4]);
#pragma unroll
            for (int u = 0; u < 4; u++) {
                float vr[8];
                *(float4*)(vr)     = *(const float4*)(&Vs[(j4 * 4 + u) * 128 + tx * 8]);
                *(float4*)(vr + 4) = *(const float4*)(&Vs[(j4 * 4 + u) * 128 + tx * 8 + 4]);
#pragma unroll
                for (int i = 0; i < 8; i++) {
                    float p = (u == 0) ? p4[i].x : (u == 1) ? p4[i].y
                            : (u == 2) ? p4[i].z : p4[i].w;
#pragma unroll
                    for (int j = 0; j < 8; j++)
                        o[i][j] = fmaf(p, vr[j], o[i][j]);
                }
            }
        }
    }

    float* ob = g_o + ((size_t)b * SEQ * NHEADS + h) * DHEAD;
#pragma unroll
    for (int i = 0; i < 8; i++) {
        int qi = q0 + ty * 8 + i;
        float inv = 1.0f / l_s[ty * 8 + i];
        *(float4*)(ob + (size_t)qi * (NHEADS * DHEAD) + tx * 8) =
            make_float4(o[i][0] * inv, o[i][1] * inv, o[i][2] * inv, o[i][3] * inv);
        *(float4*)(ob + (size_t)qi * (NHEADS * DHEAD) + tx * 8 + 4) =
            make_float4(o[i][4] * inv, o[i][5] * inv, o[i][6] * inv, o[i][7] * inv);
    }
}

// ---------------------------------------------------------------------------
extern "C" void kernel_launch(void* const* d_in, const int* in_sizes, int n_in,
                              void* d_out, int out_size)
{
    const float* x  = (const float*)d_in[0];
    const float* wq = (const float*)d_in[1];
    const float* wk = (const float*)d_in[2];
    const float* wv = (const float*)d_in[3];
    const float* wo = (const float*)d_in[4];
    const float* tp = (const float*)d_in[5];
    float* out = (float*)d_out;

    float *qp, *kp, *vp, *op;
    cudaGetSymbolAddress((void**)&qp, g_q);
    cudaGetSymbolAddress((void**)&kp, g_k);
    cudaGetSymbolAddress((void**)&vp, g_v);
    cudaGetSymbolAddress((void**)&op, g_o);
    __nv_bfloat16 *xh, *xl, *oh, *ol, *wqh, *wql, *wkh, *wkl, *wvh, *wvl, *woh, *wol;
    cudaGetSymbolAddress((void**)&xh, g_xh);   cudaGetSymbolAddress((void**)&xl, g_xl);
    cudaGetSymbolAddress((void**)&oh, g_oh);   cudaGetSymbolAddress((void**)&ol, g_ol);
    cudaGetSymbolAddress((void**)&wqh, g_wqh); cudaGetSymbolAddress((void**)&wql, g_wql);
    cudaGetSymbolAddress((void**)&wkh, g_wkh); cudaGetSymbolAddress((void**)&wkl, g_wkl);
    cudaGetSymbolAddress((void**)&wvh, g_wvh); cudaGetSymbolAddress((void**)&wvl, g_wvl);
    cudaGetSymbolAddress((void**)&woh, g_woh); cudaGetSymbolAddress((void**)&wol, g_wol);

    cudaFuncSetAttribute(hmma_gemm_kernel, cudaFuncAttributeMaxDynamicSharedMemorySize, GSMEM);
    cudaFuncSetAttribute(attn_kernel, cudaFuncAttributeMaxDynamicSharedMemorySize, ATT_SMEM);

    // split x, transpose+split weights
    {
        int n4 = MTOT * DMODEL / 4;
        split_kernel<<<(n4 + 255) / 256, 256>>>((const float4*)x, (uint2*)xh, (uint2*)xl, n4);
        tsplit_kernel<<<dim3(DMODEL / 32, DMODEL / 32), dim3(32, 8)>>>(wq, wqh, wql, DMODEL, DMODEL);
        tsplit_kernel<<<dim3(NKVD / 32, DMODEL / 32), dim3(32, 8)>>>(wk, wkh, wkl, DMODEL, NKVD);
        tsplit_kernel<<<dim3(NKVD / 32, DMODEL / 32), dim3(32, 8)>>>(wv, wvh, wvl, DMODEL, NKVD);
        tsplit_kernel<<<dim3(DMODEL / 32, DMODEL / 32), dim3(32, 8)>>>(wo, woh, wol, DMODEL, DMODEL);
    }

    // projections on HMMA tensor path
    hmma_gemm_kernel<<<dim3(DMODEL / 128, MTOT / 128), 256, GSMEM>>>(
        xh, xl, wqh, wql, qp, MTOT, DMODEL, DMODEL);
    hmma_gemm_kernel<<<dim3(NKVD / 128, MTOT / 128), 256, GSMEM>>>(
        xh, xl, wkh, wkl, kp, MTOT, NKVD, DMODEL);
    hmma_gemm_kernel<<<dim3(NKVD / 128, MTOT / 128), 256, GSMEM>>>(
        xh, xl, wvh, wvl, vp, MTOT, NKVD, DMODEL);

    // RoPE
    const int rthreads = BATCH * SEQ * (DHEAD / 2);
    rope_kernel<<<(rthreads + 255) / 256, 256>>>(qp, NHEADS);
    rope_kernel<<<(rthreads + 255) / 256, 256>>>(kp, NKV);

    // attention (fp32 SIMT)
    attn_kernel<<<dim3(SEQ / 64, NHEADS, BATCH), 128, ATT_SMEM>>>(tp);

    // output projection
    {
        int n4 = MTOT * DMODEL / 4;
        split_kernel<<<(n4 + 255) / 256, 256>>>((const float4*)op, (uint2*)oh, (uint2*)ol, n4);
    }
    hmma_gemm_kernel<<<dim3(DMODEL / 128, MTOT / 128), 256, GSMEM>>>(
        oh, ol, woh, wol, out, MTOT, DMODEL, DMODEL);
}

// round 4
// speedup vs baseline: 3.7046x; 2.1334x over previous
#include <cuda_runtime.h>
#include <cuda_bf16.h>
#include <cuda_fp16.h>
#include <math.h>
#include <stdint.h>

#define BATCH   4
#define SEQ     2048
#define DMODEL  2048
#define NHEADS  16
#define NKV     4
#define DHEAD   128
#define MTOT    (BATCH * SEQ)          // 8192
#define NKVD    (NKV * DHEAD)          // 512

// ---------------- scratch (allocation-free rule: device globals) ----------
__device__ float g_q[MTOT * NHEADS * DHEAD];     // fp32 proj out (pre-rope)
__device__ float g_k[MTOT * NKVD];
__device__ float g_v[MTOT * NKVD];

__device__ __nv_bfloat16 g_qh[MTOT * DMODEL], g_ql[MTOT * DMODEL];   // roped Q hi/lo
__device__ __nv_bfloat16 g_kh[MTOT * NKVD],  g_kl[MTOT * NKVD];      // roped K hi/lo
__device__ __half        g_vf[MTOT * NKVD];                          // V fp16

__device__ __nv_bfloat16 g_xh[MTOT * DMODEL], g_xl[MTOT * DMODEL];
__device__ __nv_bfloat16 g_oh[MTOT * DMODEL], g_ol[MTOT * DMODEL];   // attn out hi/lo
__device__ __nv_bfloat16 g_wqh[DMODEL * DMODEL], g_wql[DMODEL * DMODEL];
__device__ __nv_bfloat16 g_wkh[NKVD * DMODEL],  g_wkl[NKVD * DMODEL];
__device__ __nv_bfloat16 g_wvh[NKVD * DMODEL],  g_wvl[NKVD * DMODEL];
__device__ __nv_bfloat16 g_woh[DMODEL * DMODEL], g_wol[DMODEL * DMODEL];

// ---------------- helpers ---------------------------------------------
__device__ __forceinline__ uint32_t smem_u32(const void* p) {
    uint32_t a;
    asm("{ .reg .u64 t; cvta.to.shared.u64 t, %1; cvt.u32.u64 %0, t; }"
        : "=r"(a) : "l"(p));
    return a;
}
#define SWZ128(o) ((o) ^ (((o) >> 3) & 0x70))

__device__ __forceinline__ void ldsm4(uint32_t& r0, uint32_t& r1,
                                      uint32_t& r2, uint32_t& r3, uint32_t addr) {
    asm volatile("ldmatrix.sync.aligned.m8n8.x4.shared.b16 {%0,%1,%2,%3}, [%4];"
                 : "=r"(r0), "=r"(r1), "=r"(r2), "=r"(r3) : "r"(addr));
}
__device__ __forceinline__ void ldsm4t(uint32_t& r0, uint32_t& r1,
                                       uint32_t& r2, uint32_t& r3, uint32_t addr) {
    asm volatile("ldmatrix.sync.aligned.m8n8.x4.trans.shared.b16 {%0,%1,%2,%3}, [%4];"
                 : "=r"(r0), "=r"(r1), "=r"(r2), "=r"(r3) : "r"(addr));
}
__device__ __forceinline__ void mma16816(float* c, uint32_t a0, uint32_t a1,
                                         uint32_t a2, uint32_t a3,
                                         uint32_t b0, uint32_t b1) {
    asm volatile(
        "mma.sync.aligned.m16n8k16.row.col.f32.bf16.bf16.f32 "
        "{%0,%1,%2,%3},{%4,%5,%6,%7},{%8,%9},{%0,%1,%2,%3};"
        : "+f"(c[0]), "+f"(c[1]), "+f"(c[2]), "+f"(c[3])
        : "r"(a0), "r"(a1), "r"(a2), "r"(a3), "r"(b0), "r"(b1));
}
__device__ __forceinline__ void mma16816h(float* c, uint32_t a0, uint32_t a1,
                                          uint32_t a2, uint32_t a3,
                                          uint32_t b0, uint32_t b1) {
    asm volatile(
        "mma.sync.aligned.m16n8k16.row.col.f32.f16.f16.f32 "
        "{%0,%1,%2,%3},{%4,%5,%6,%7},{%8,%9},{%0,%1,%2,%3};"
        : "+f"(c[0]), "+f"(c[1]), "+f"(c[2]), "+f"(c[3])
        : "r"(a0), "r"(a1), "r"(a2), "r"(a3), "r"(b0), "r"(b1));
}
__device__ __forceinline__ uint32_t packf16(float hi, float lo) {
    uint32_t r;
    asm("cvt.rn.f16x2.f32 %0, %1, %2;" : "=r"(r) : "f"(hi), "f"(lo));
    return r;
}
__device__ __forceinline__ uint32_t exp2_f16x2(uint32_t x) {
    uint32_t r;
    asm("ex2.approx.f16x2 %0, %1;" : "=r"(r) : "r"(x));
    return r;
}

// ---------------------------------------------------------------------------
// HMMA split-bf16 GEMM: C[M,N] = A[M,K] @ B[N,K]^T (unchanged from round 3)
// ---------------------------------------------------------------------------
#define GKC      64
#define TILEB    16384
#define STAGEB   (4 * TILEB)
#define GSMEM    (2 * STAGEB)

__device__ __forceinline__ void gemm_issue_loads(
    uint32_t sb, int stage, int it,
    const __nv_bfloat16* __restrict__ Ah, const __nv_bfloat16* __restrict__ Al,
    const __nv_bfloat16* __restrict__ Bh, const __nv_bfloat16* __restrict__ Bl,
    int m0, int n0, int K, int tid)
{
    const int k0 = it * GKC;
    const __nv_bfloat16* srcs[4] = { Ah, Al, Bh, Bl };
#pragma unroll
    for (int mtx = 0; mtx < 4; mtx++) {
        const __nv_bfloat16* src = srcs[mtx];
        const int rowbase = (mtx < 2) ? m0 : n0;
        const uint32_t smb = sb + stage * STAGEB + mtx * TILEB;
#pragma unroll
        for (int j = 0; j < 4; j++) {
            int chunk = tid + j * 256;
            int row = chunk >> 3;
            int c16 = chunk & 7;
            const void* gp = src + (size_t)(rowbase + row) * K + k0 + c16 * 8;
            uint32_t sp = smb + SWZ128(row * 128 + c16 * 16);
            asm volatile("cp.async.cg.shared.global [%0], [%1], 16;"
                         :: "r"(sp), "l"(gp));
        }
    }
    asm volatile("cp.async.commit_group;" ::: "memory");
}

__global__ __launch_bounds__(256, 1) void hmma_gemm_kernel(
    const __nv_bfloat16* __restrict__ Ah, const __nv_bfloat16* __restrict__ Al,
    const __nv_bfloat16* __restrict__ Bh, const __nv_bfloat16* __restrict__ Bl,
    float* __restrict__ C, int M, int N, int K)
{
    extern __shared__ char smem[];
    const uint32_t sb = smem_u32(smem);
    const int tid = threadIdx.x;
    const int wid = tid >> 5;
    const int l   = tid & 31;
    const int wm  = wid >> 2;
    const int wn  = wid & 3;
    const int m0  = blockIdx.y * 128;
    const int n0  = blockIdx.x * 128;

    float acc[4][4][4];
#pragma unroll
    for (int i = 0; i < 4; i++)
#pragma unroll
        for (int j = 0; j < 4; j++)
#pragma unroll
            for (int f = 0; f < 4; f++) acc[i][j][f] = 0.f;

    const int a_row_l = (l & 7) + (l & 8);
    const int a_col_l = ((l >> 4) & 1) * 16;
    const int b_row_l = (l & 7) + ((l >> 4) & 1) * 8;
    const int b_col_l = ((l >> 3) & 1) * 16;

    const int niter = K / GKC;
    gemm_issue_loads(sb, 0, 0, Ah, Al, Bh, Bl, m0, n0, K, tid);

    for (int it = 0; it < niter; it++) {
        if (it + 1 < niter) {
            gemm_issue_loads(sb, (it + 1) & 1, it + 1, Ah, Al, Bh, Bl, m0, n0, K, tid);
            asm volatile("cp.async.wait_group 1;" ::: "memory");
        } else {
            asm volatile("cp.async.wait_group 0;" ::: "memory");
        }
        __syncthreads();

        const uint32_t stg = sb + (it & 1) * STAGEB;
        const uint32_t sAh = stg;
        const uint32_t sAl = stg + TILEB;
        const uint32_t sBh = stg + 2 * TILEB;
        const uint32_t sBl = stg + 3 * TILEB;

#pragma unroll
        for (int kk = 0; kk < 4; kk++) {
            const int kb = kk * 32;
            uint32_t ah[4][4], al[4][4], bh[8], bl[8];
#pragma unroll
            for (int mt = 0; mt < 4; mt++) {
                int row = wm * 64 + mt * 16 + a_row_l;
                uint32_t off = SWZ128(row * 128 + kb + a_col_l);
                ldsm4(ah[mt][0], ah[mt][1], ah[mt][2], ah[mt][3], sAh + off);
                ldsm4(al[mt][0], al[mt][1], al[mt][2], al[mt][3], sAl + off);
            }
#pragma unroll
            for (int nt2 = 0; nt2 < 2; nt2++) {
                int row = wn * 32 + nt2 * 16 + b_row_l;
                uint32_t off = SWZ128(row * 128 + kb + b_col_l);
                ldsm4(bh[nt2 * 4 + 0], bh[nt2 * 4 + 1], bh[nt2 * 4 + 2], bh[nt2 * 4 + 3], sBh + off);
                ldsm4(bl[nt2 * 4 + 0], bl[nt2 * 4 + 1], bl[nt2 * 4 + 2], bl[nt2 * 4 + 3], sBl + off);
            }
#pragma unroll
            for (int mt = 0; mt < 4; mt++)
#pragma unroll
                for (int nt = 0; nt < 4; nt++) {
                    uint32_t b0h = bh[(nt >> 1) * 4 + (nt & 1) * 2];
                    uint32_t b1h = bh[(nt >> 1) * 4 + (nt & 1) * 2 + 1];
                    uint32_t b0l = bl[(nt >> 1) * 4 + (nt & 1) * 2];
                    uint32_t b1l = bl[(nt >> 1) * 4 + (nt & 1) * 2 + 1];
                    mma16816(acc[mt][nt], ah[mt][0], ah[mt][1], ah[mt][2], ah[mt][3], b0h, b1h);
                    mma16816(acc[mt][nt], ah[mt][0], ah[mt][1], ah[mt][2], ah[mt][3], b0l, b1l);
                    mma16816(acc[mt][nt], al[mt][0], al[mt][1], al[mt][2], al[mt][3], b0h, b1h);
                }
        }
        __syncthreads();
    }

#pragma unroll
    for (int mt = 0; mt < 4; mt++) {
        int r0 = m0 + wm * 64 + mt * 16 + (l >> 2);
        int r1 = r0 + 8;
#pragma unroll
        for (int nt = 0; nt < 4; nt++) {
            int c = n0 + wn * 32 + nt * 8 + (l & 3) * 2;
            *(float2*)(C + (size_t)r0 * N + c) = make_float2(acc[mt][nt][0], acc[mt][nt][1]);
            *(float2*)(C + (size_t)r1 * N + c) = make_float2(acc[mt][nt][2], acc[mt][nt][3]);
        }
    }
}

// ---------------------------------------------------------------------------
// fp32 -> (bf16 hi, bf16 lo) elementwise split
// ---------------------------------------------------------------------------
__global__ void split_kernel(const float4* __restrict__ in,
                             uint2* __restrict__ hi, uint2* __restrict__ lo, int n4)
{
    int i = blockIdx.x * blockDim.x + threadIdx.x;
    if (i >= n4) return;
    float4 v = in[i];
    __nv_bfloat16 h[4], lw[4];
    float x[4] = { v.x, v.y, v.z, v.w };
#pragma unroll
    for (int j = 0; j < 4; j++) {
        h[j] = __float2bfloat16(x[j]);
        lw[j] = __float2bfloat16(x[j] - __bfloat162float(h[j]));
    }
    hi[i] = *(uint2*)h;
    lo[i] = *(uint2*)lw;
}

// fp32 -> fp16 elementwise
__global__ void f16conv_kernel(const float4* __restrict__ in,
                               __half2* __restrict__ out, int n4)
{
    int i = blockIdx.x * blockDim.x + threadIdx.x;
    if (i >= n4) return;
    float4 v = in[i];
    out[2 * i]     = __floats2half2_rn(v.x, v.y);
    out[2 * i + 1] = __floats2half2_rn(v.z, v.w);
}

// ---------------------------------------------------------------------------
// weight transpose + split: w[K,N] fp32 -> Wh/Wl[N,K] bf16
// ---------------------------------------------------------------------------
__global__ void tsplit_kernel(const float* __restrict__ w,
                              __nv_bfloat16* __restrict__ th,
                              __nv_bfloat16* __restrict__ tl, int Kd, int Nd)
{
    __shared__ float tile[32][33];
    int n0 = blockIdx.x * 32, k0 = blockIdx.y * 32;
    int tx = threadIdx.x, ty = threadIdx.y;
#pragma unroll
    for (int j = 0; j < 32; j += 8)
        tile[ty + j][tx] = w[(size_t)(k0 + ty + j) * Nd + n0 + tx];
    __syncthreads();
#pragma unroll
    for (int j = 0; j < 32; j += 8) {
        float x = tile[tx][ty + j];
        __nv_bfloat16 h = __float2bfloat16(x);
        size_t idx = (size_t)(n0 + ty + j) * Kd + k0 + tx;
        th[idx] = h;
        tl[idx] = __float2bfloat16(x - __bfloat162float(h));
    }
}

// ---------------------------------------------------------------------------
// RoPE + hi/lo bf16 split: reads fp32 [B*S, heads, 128], writes hi/lo bf16
// ---------------------------------------------------------------------------
__global__ void rope_split_kernel(const float* __restrict__ src,
                                  __nv_bfloat16* __restrict__ hi,
                                  __nv_bfloat16* __restrict__ lo, int heads)
{
    int idx = blockIdx.x * blockDim.x + threadIdx.x;
    const int total = BATCH * SEQ * (DHEAD / 2);
    if (idx >= total) return;
    int i   = idx & 63;
    int row = idx >> 6;
    int s   = row & (SEQ - 1);
    double inv = exp(-0.14391156831212787 * (double)i);
    double sd, cd;
    sincos((double)s * inv, &sd, &cd);
    float c = (float)cd, sn = (float)sd;
    const float* p = src + (size_t)row * heads * DHEAD;
    __nv_bfloat16* ph = hi + (size_t)row * heads * DHEAD;
    __nv_bfloat16* pl = lo + (size_t)row * heads * DHEAD;
    for (int hh = 0; hh < heads; hh++, p += DHEAD, ph += DHEAD, pl += DHEAD) {
        float x1 = p[i], x2 = p[i + 64];
        float y1 = x1 * c - x2 * sn;
        float y2 = x2 * c + x1 * sn;
        __nv_bfloat16 h1 = __float2bfloat16(y1);
        __nv_bfloat16 h2 = __float2bfloat16(y2);
        ph[i]      = h1;  pl[i]      = __float2bfloat16(y1 - __bfloat162float(h1));
        ph[i + 64] = h2;  pl[i + 64] = __float2bfloat16(y2 - __bfloat162float(h2));
    }
}

// ---------------------------------------------------------------------------
// HMMA flash attention.
// CTA: 128 queries x (64-key tiles), 8 warps, warp = 16 q rows.
// QK: bf16 hi/lo x K hi/lo (3 products). exp: ex2.approx.f16x2 -> P fp16.
// PV: fp16 single product. Row sums l via MMA with ones-vector.
// smem: Qh/Ql [128][128]bf16 (2 d-halves of [128][128B], SW128),
//       2 stages x { Kh, Kl [64][128]bf16, V [64][128]f16 } same half layout.
// ---------------------------------------------------------------------------
#define AT_SMEM 163840
#define AT_STAGE0 65536
#define AT_STAGEB 49152

__device__ __forceinline__ void attn_issue_kv(
    uint32_t stbase, const __nv_bfloat16* khg, const __nv_bfloat16* klg,
    const __half* vg, int k0, int tid)
{
    const char* bases[3] = { (const char*)khg, (const char*)klg, (const char*)vg };
#pragma unroll
    for (int arr = 0; arr < 3; arr++) {
        const char* base = bases[arr];
        uint32_t soff = stbase + arr * 16384;
#pragma unroll
        for (int i = 0; i < 4; i++) {
            int chunk = tid + i * 256;
            int row = chunk >> 4, cc = chunk & 15;
            const void* gp = base + ((size_t)(k0 + row) * NKVD + cc * 8) * 2;
            uint32_t sp = soff + (cc >> 3) * 8192 + SWZ128(row * 128 + (cc & 7) * 16);
            asm volatile("cp.async.cg.shared.global [%0], [%1], 16;"
                         :: "r"(sp), "l"(gp));
        }
    }
}

__global__ __launch_bounds__(256, 1) void hmma_attn_kernel(const float* __restrict__ tptr)
{
    extern __shared__ char smem[];
    const uint32_t sb = smem_u32(smem);
    const int tid = threadIdx.x, w = tid >> 5, l = tid & 31;
    const int qt = blockIdx.x, h = blockIdx.y, b = blockIdx.z;
    const int kv = h >> 2;
    const int q0 = qt * 128;
    const int qw0 = q0 + w * 16;
    const float scale = 0.08838834764831845f / fmaxf(fabsf(tptr[0]), 1e-6f);
    const float sl = scale * 1.4426950408889634f;   // scale * log2(e)

    const uint32_t sQh = sb, sQl = sb + 32768;

    const __nv_bfloat16* qhg = g_qh + ((size_t)(b * SEQ) + q0) * DMODEL + h * DHEAD;
    const __nv_bfloat16* qlg = g_ql + ((size_t)(b * SEQ) + q0) * DMODEL + h * DHEAD;
    const __nv_bfloat16* khg = g_kh + (size_t)(b * SEQ) * NKVD + kv * DHEAD;
    const __nv_bfloat16* klg = g_kl + (size_t)(b * SEQ) * NKVD + kv * DHEAD;
    const __half*        vg  = g_vf + (size_t)(b * SEQ) * NKVD + kv * DHEAD;

    // ---- preload Q + stage 0 ----
    {
        const char* qb2[2] = { (const char*)qhg, (const char*)qlg };
#pragma unroll
        for (int arr = 0; arr < 2; arr++) {
            uint32_t soff = (arr == 0) ? sQh : sQl;
#pragma unroll
            for (int i = 0; i < 8; i++) {
                int chunk = tid + i * 256;
                int row = chunk >> 4, cc = chunk & 15;
                const void* gp = qb2[arr] + ((size_t)row * DMODEL + cc * 8) * 2;
                uint32_t sp = soff + (cc >> 3) * 16384 + SWZ128(row * 128 + (cc & 7) * 16);
                asm volatile("cp.async.cg.shared.global [%0], [%1], 16;"
                             :: "r"(sp), "l"(gp));
            }
        }
        attn_issue_kv(sb + AT_STAGE0, khg, klg, vg, 0, tid);
        asm volatile("cp.async.commit_group;" ::: "memory");
    }

    // fragment lane mappings (must match usage conventions)
    const int a_row_l = (l & 7) + (l & 8);
    const int a_col_l = ((l >> 4) & 1) * 16;
    const int b_row_l = (l & 7) + ((l >> 4) & 1) * 8;
    const int b_col_l = ((l >> 3) & 1) * 16;
    const int v_row_l = (l & 7) + ((l >> 3) & 1) * 8;
    const int v_col_l = ((l >> 4) & 1) * 16;

    float oacc[16][4];
    float lacc[4] = {0.f, 0.f, 0.f, 0.f};
#pragma unroll
    for (int i = 0; i < 16; i++)
#pragma unroll
        for (int f = 0; f < 4; f++) oacc[i][f] = 0.f;
    float m0 = -3.0e38f, m1 = -3.0e38f;

    const int nkt = 2 * qt + 2;
    for (int kt = 0; kt < nkt; kt++) {
        if (kt + 1 < nkt) {
            attn_issue_kv(sb + AT_STAGE0 + ((kt + 1) & 1) * AT_STAGEB,
                          khg, klg, vg, (kt + 1) * 64, tid);
            asm volatile("cp.async.commit_group;" ::: "memory");
            asm volatile("cp.async.wait_group 1;" ::: "memory");
        } else {
            asm volatile("cp.async.wait_group 0;" ::: "memory");
        }
        __syncthreads();

        const int k0 = kt * 64;
        const uint32_t st = sb + AT_STAGE0 + (kt & 1) * AT_STAGEB;

        if (k0 <= qw0 + 15) {   // not fully masked for this warp
            // ---- S = Q K^T (split bf16) ----
            float sacc[8][4];
#pragma unroll
            for (int i = 0; i < 8; i++)
#pragma unroll
                for (int f = 0; f < 4; f++) sacc[i][f] = 0.f;

#pragma unroll
            for (int ks = 0; ks < 8; ks++) {
                uint32_t qoff = (ks >> 2) * 16384 +
                    SWZ128((w * 16 + a_row_l) * 128 + (ks & 3) * 32 + a_col_l);
                uint32_t qa[4], qb_[4];
                ldsm4(qa[0], qa[1], qa[2], qa[3], sQh + qoff);
                ldsm4(qb_[0], qb_[1], qb_[2], qb_[3], sQl + qoff);
#pragma unroll
                for (int np = 0; np < 4; np++) {
                    uint32_t koff = st + (ks >> 2) * 8192 +
                        SWZ128((np * 16 + b_row_l) * 128 + (ks & 3) * 32 + b_col_l);
                    uint32_t kh4[4], kl4[4];
                    ldsm4(kh4[0], kh4[1], kh4[2], kh4[3], koff);
                    ldsm4(kl4[0], kl4[1], kl4[2], kl4[3], koff + 16384);
                    mma16816(sacc[2 * np],     qa[0], qa[1], qa[2], qa[3], kh4[0], kh4[1]);
                    mma16816(sacc[2 * np],     qa[0], qa[1], qa[2], qa[3], kl4[0], kl4[1]);
                    mma16816(sacc[2 * np],     qb_[0], qb_[1], qb_[2], qb_[3], kh4[0], kh4[1]);
                    mma16816(sacc[2 * np + 1], qa[0], qa[1], qa[2], qa[3], kh4[2], kh4[3]);
                    mma16816(sacc[2 * np + 1], qa[0], qa[1], qa[2], qa[3], kl4[2], kl4[3]);
                    mma16816(sacc[2 * np + 1], qb_[0], qb_[1], qb_[2], qb_[3], kh4[2], kh4[3]);
                }
            }

            // ---- causal mask ----
            if (k0 + 63 > qw0) {
                int qa0 = qw0 + (l >> 2), qa1 = qa0 + 8;
                int kc0 = k0 + 2 * (l & 3);
#pragma unroll
                for (int nt = 0; nt < 8; nt++) {
                    int kc = kc0 + nt * 8;
                    if (kc     > qa0) sacc[nt][0] = -3.0e38f;
                    if (kc + 1 > qa0) sacc[nt][1] = -3.0e38f;
                    if (kc     > qa1) sacc[nt][2] = -3.0e38f;
                    if (kc + 1 > qa1) sacc[nt][3] = -3.0e38f;
                }
            }

            // ---- online softmax ----
            float mx0 = -3.0e38f, mx1 = -3.0e38f;
#pragma unroll
            for (int nt = 0; nt < 8; nt++) {
                mx0 = fmaxf(mx0, fmaxf(sacc[nt][0], sacc[nt][1]));
                mx1 = fmaxf(mx1, fmaxf(sacc[nt][2], sacc[nt][3]));
            }
            mx0 = fmaxf(mx0, __shfl_xor_sync(0xffffffffu, mx0, 1));
            mx0 = fmaxf(mx0, __shfl_xor_sync(0xffffffffu, mx0, 2));
            mx1 = fmaxf(mx1, __shfl_xor_sync(0xffffffffu, mx1, 1));
            mx1 = fmaxf(mx1, __shfl_xor_sync(0xffffffffu, mx1, 2));
            float mn0 = fmaxf(m0, mx0), mn1 = fmaxf(m1, mx1);
            bool ch = (mn0 > m0) || (mn1 > m1);
            if (__any_sync(0xffffffffu, ch)) {
                float a0 = exp2f((m0 - mn0) * sl);
                float a1 = exp2f((m1 - mn1) * sl);
#pragma unroll
                for (int nt = 0; nt < 16; nt++) {
                    oacc[nt][0] *= a0; oacc[nt][1] *= a0;
                    oacc[nt][2] *= a1; oacc[nt][3] *= a1;
                }
                lacc[0] *= a0; lacc[1] *= a0; lacc[2] *= a1; lacc[3] *= a1;
            }
            m0 = mn0; m1 = mn1;
            const float bb0 = mn0 * sl, bb1 = mn1 * sl;

            uint32_t pp[8][2];
#pragma unroll
            for (int nt = 0; nt < 8; nt++) {
                float t0 = fmaf(sacc[nt][0], sl, -bb0);
                float t1 = fmaf(sacc[nt][1], sl, -bb0);
                float t2 = fmaf(sacc[nt][2], sl, -bb1);
                float t3 = fmaf(sacc[nt][3], sl, -bb1);
                pp[nt][0] = exp2_f16x2(packf16(t1, t0));
                pp[nt][1] = exp2_f16x2(packf16(t3, t2));
            }

            // ---- l += P * ones ; O += P * V ----
#pragma unroll
            for (int ks = 0; ks < 4; ks++) {
                uint32_t pa0 = pp[2 * ks][0], pa1 = pp[2 * ks][1];
                uint32_t pa2 = pp[2 * ks + 1][0], pa3 = pp[2 * ks + 1][1];
                mma16816h(lacc, pa0, pa1, pa2, pa3, 0x3C003C00u, 0x3C003C00u);
#pragma unroll
                for (int jp = 0; jp < 8; jp++) {
                    uint32_t voff = st + 32768 + (jp >> 2) * 8192 +
                        SWZ128((ks * 16 + v_row_l) * 128 + (jp & 3) * 32 + v_col_l);
                    uint32_t v4[4];
                    ldsm4t(v4[0], v4[1], v4[2], v4[3], voff);
                    mma16816h(oacc[2 * jp],     pa0, pa1, pa2, pa3, v4[0], v4[1]);
                    mma16816h(oacc[2 * jp + 1], pa0, pa1, pa2, pa3, v4[2], v4[3]);
                }
            }
        }
        __syncthreads();
    }

    // ---- epilogue: normalize + hi/lo bf16 split store ----
    const float inv0 = 1.0f / lacc[0];
    const float inv1 = 1.0f / lacc[2];
    const size_t r0g = (size_t)(b * SEQ) + qw0 + (l >> 2);
    const size_t r1g = r0g + 8;
    __nv_bfloat16* ohp = g_oh;
    __nv_bfloat16* olp = g_ol;
#pragma unroll
    for (int nt = 0; nt < 16; nt++) {
        int col = h * DHEAD + nt * 8 + 2 * (l & 3);
        float v0 = oacc[nt][0] * inv0, v1 = oacc[nt][1] * inv0;
        float v2 = oacc[nt][2] * inv1, v3 = oacc[nt][3] * inv1;
        __nv_bfloat16 h0 = __float2bfloat16(v0), h1 = __float2bfloat16(v1);
        __nv_bfloat16 h2 = __float2bfloat16(v2), h3 = __float2bfloat16(v3);
        __nv_bfloat162 hp0; hp0.x = h0; hp0.y = h1;
        __nv_bfloat162 hp1; hp1.x = h2; hp1.y = h3;
        __nv_bfloat162 lp0;
        lp0.x = __float2bfloat16(v0 - __bfloat162float(h0));
        lp0.y = __float2bfloat16(v1 - __bfloat162float(h1));
        __nv_bfloat162 lp1;
        lp1.x = __float2bfloat16(v2 - __bfloat162float(h2));
        lp1.y = __float2bfloat16(v3 - __bfloat162float(h3));
        *(__nv_bfloat162*)(ohp + r0g * DMODEL + col) = hp0;
        *(__nv_bfloat162*)(olp + r0g * DMODEL + col) = lp0;
        *(__nv_bfloat162*)(ohp + r1g * DMODEL + col) = hp1;
        *(__nv_bfloat162*)(olp + r1g * DMODEL + col) = lp1;
    }
}

// ---------------------------------------------------------------------------
extern "C" void kernel_launch(void* const* d_in, const int* in_sizes, int n_in,
                              void* d_out, int out_size)
{
    const float* x  = (const float*)d_in[0];
    const float* wq = (const float*)d_in[1];
    const float* wk = (const float*)d_in[2];
    const float* wv = (const float*)d_in[3];
    const float* wo = (const float*)d_in[4];
    const float* tp = (const float*)d_in[5];
    float* out = (float*)d_out;

    float *qp, *kp, *vp;
    cudaGetSymbolAddress((void**)&qp, g_q);
    cudaGetSymbolAddress((void**)&kp, g_k);
    cudaGetSymbolAddress((void**)&vp, g_v);
    __nv_bfloat16 *xh, *xl, *oh, *ol, *wqh, *wql, *wkh, *wkl, *wvh, *wvl, *woh, *wol;
    __nv_bfloat16 *qh, *ql, *kh, *kl;
    __half *vf;
    cudaGetSymbolAddress((void**)&xh, g_xh);   cudaGetSymbolAddress((void**)&xl, g_xl);
    cudaGetSymbolAddress((void**)&oh, g_oh);   cudaGetSymbolAddress((void**)&ol, g_ol);
    cudaGetSymbolAddress((void**)&wqh, g_wqh); cudaGetSymbolAddress((void**)&wql, g_wql);
    cudaGetSymbolAddress((void**)&wkh, g_wkh); cudaGetSymbolAddress((void**)&wkl, g_wkl);
    cudaGetSymbolAddress((void**)&wvh, g_wvh); cudaGetSymbolAddress((void**)&wvl, g_wvl);
    cudaGetSymbolAddress((void**)&woh, g_woh); cudaGetSymbolAddress((void**)&wol, g_wol);
    cudaGetSymbolAddress((void**)&qh, g_qh);   cudaGetSymbolAddress((void**)&ql, g_ql);
    cudaGetSymbolAddress((void**)&kh, g_kh);   cudaGetSymbolAddress((void**)&kl, g_kl);
    cudaGetSymbolAddress((void**)&vf, g_vf);

    cudaFuncSetAttribute(hmma_gemm_kernel, cudaFuncAttributeMaxDynamicSharedMemorySize, GSMEM);
    cudaFuncSetAttribute(hmma_attn_kernel, cudaFuncAttributeMaxDynamicSharedMemorySize, AT_SMEM);

    // split x; transpose+split weights
    {
        int n4 = MTOT * DMODEL / 4;
        split_kernel<<<(n4 + 255) / 256, 256>>>((const float4*)x, (uint2*)xh, (uint2*)xl, n4);
        tsplit_kernel<<<dim3(DMODEL / 32, DMODEL / 32), dim3(32, 8)>>>(wq, wqh, wql, DMODEL, DMODEL);
        tsplit_kernel<<<dim3(NKVD / 32, DMODEL / 32), dim3(32, 8)>>>(wk, wkh, wkl, DMODEL, NKVD);
        tsplit_kernel<<<dim3(NKVD / 32, DMODEL / 32), dim3(32, 8)>>>(wv, wvh, wvl, DMODEL, NKVD);
        tsplit_kernel<<<dim3(DMODEL / 32, DMODEL / 32), dim3(32, 8)>>>(wo, woh, wol, DMODEL, DMODEL);
    }

    // projections (HMMA)
    hmma_gemm_kernel<<<dim3(DMODEL / 128, MTOT / 128), 256, GSMEM>>>(
        xh, xl, wqh, wql, qp, MTOT, DMODEL, DMODEL);
    hmma_gemm_kernel<<<dim3(NKVD / 128, MTOT / 128), 256, GSMEM>>>(
        xh, xl, wkh, wkl, kp, MTOT, NKVD, DMODEL);
    hmma_gemm_kernel<<<dim3(NKVD / 128, MTOT / 128), 256, GSMEM>>>(
        xh, xl, wvh, wvl, vp, MTOT, NKVD, DMODEL);

    // RoPE + split to bf16 hi/lo; V -> fp16
    const int rthreads = BATCH * SEQ * (DHEAD / 2);
    rope_split_kernel<<<(rthreads + 255) / 256, 256>>>(qp, qh, ql, NHEADS);
    rope_split_kernel<<<(rthreads + 255) / 256, 256>>>(kp, kh, kl, NKV);
    {
        int n4 = MTOT * NKVD / 4;
        f16conv_kernel<<<(n4 + 255) / 256, 256>>>((const float4*)vp, (__half2*)vf, n4);
    }

    // flash attention (HMMA), writes oh/ol bf16 hi/lo directly
    hmma_attn_kernel<<<dim3(SEQ / 128, NHEADS, BATCH), 256, AT_SMEM>>>(tp);

    // output projection
    hmma_gemm_kernel<<<dim3(DMODEL / 128, MTOT / 128), 256, GSMEM>>>(
        oh, ol, woh, wol, out, MTOT, DMODEL, DMODEL);
}

// round 5
// speedup vs baseline: 4.4925x; 1.2127x over previous
#include <cuda_runtime.h>
#include <cuda_bf16.h>
#include <cuda_fp16.h>
#include <math.h>
#include <stdint.h>

#define BATCH   4
#define SEQ     2048
#define DMODEL  2048
#define NHEADS  16
#define NKV     4
#define DHEAD   128
#define MTOT    (BATCH * SEQ)          // 8192
#define NKVD    (NKV * DHEAD)          // 512

// ---------------- scratch (allocation-free rule: device globals) ----------
__device__ float g_q[MTOT * NHEADS * DHEAD];     // fp32 proj out (pre-rope)
__device__ float g_k[MTOT * NKVD];
__device__ float g_v[MTOT * NKVD];

__device__ __nv_bfloat16 g_qh[MTOT * DMODEL], g_ql[MTOT * DMODEL];   // roped Q hi/lo
__device__ __nv_bfloat16 g_kh[MTOT * NKVD],  g_kl[MTOT * NKVD];      // roped K hi/lo
__device__ __half        g_vf[MTOT * NKVD];                          // V fp16

__device__ __half g_xh[MTOT * DMODEL], g_xl[MTOT * DMODEL];          // x hi/lo f16
__device__ __half g_ofh[MTOT * DMODEL], g_ofl[MTOT * DMODEL];        // attn out hi/lo f16
__device__ __half g_wqf[DMODEL * DMODEL];                            // W^T single f16
__device__ __half g_wkf[NKVD * DMODEL];
__device__ __half g_wvf[NKVD * DMODEL];
__device__ __half g_wof[DMODEL * DMODEL];

// ---------------- helpers ---------------------------------------------
__device__ __forceinline__ uint32_t smem_u32(const void* p) {
    uint32_t a;
    asm("{ .reg .u64 t; cvta.to.shared.u64 t, %1; cvt.u32.u64 %0, t; }"
        : "=r"(a) : "l"(p));
    return a;
}
#define SWZ128(o) ((o) ^ (((o) >> 3) & 0x70))

__device__ __forceinline__ void ldsm4(uint32_t& r0, uint32_t& r1,
                                      uint32_t& r2, uint32_t& r3, uint32_t addr) {
    asm volatile("ldmatrix.sync.aligned.m8n8.x4.shared.b16 {%0,%1,%2,%3}, [%4];"
                 : "=r"(r0), "=r"(r1), "=r"(r2), "=r"(r3) : "r"(addr));
}
__device__ __forceinline__ void ldsm4t(uint32_t& r0, uint32_t& r1,
                                       uint32_t& r2, uint32_t& r3, uint32_t addr) {
    asm volatile("ldmatrix.sync.aligned.m8n8.x4.trans.shared.b16 {%0,%1,%2,%3}, [%4];"
                 : "=r"(r0), "=r"(r1), "=r"(r2), "=r"(r3) : "r"(addr));
}
__device__ __forceinline__ void mma16816(float* c, uint32_t a0, uint32_t a1,
                                         uint32_t a2, uint32_t a3,
                                         uint32_t b0, uint32_t b1) {
    asm volatile(
        "mma.sync.aligned.m16n8k16.row.col.f32.bf16.bf16.f32 "
        "{%0,%1,%2,%3},{%4,%5,%6,%7},{%8,%9},{%0,%1,%2,%3};"
        : "+f"(c[0]), "+f"(c[1]), "+f"(c[2]), "+f"(c[3])
        : "r"(a0), "r"(a1), "r"(a2), "r"(a3), "r"(b0), "r"(b1));
}
__device__ __forceinline__ void mma16816h(float* c, uint32_t a0, uint32_t a1,
                                          uint32_t a2, uint32_t a3,
                                          uint32_t b0, uint32_t b1) {
    asm volatile(
        "mma.sync.aligned.m16n8k16.row.col.f32.f16.f16.f32 "
        "{%0,%1,%2,%3},{%4,%5,%6,%7},{%8,%9},{%0,%1,%2,%3};"
        : "+f"(c[0]), "+f"(c[1]), "+f"(c[2]), "+f"(c[3])
        : "r"(a0), "r"(a1), "r"(a2), "r"(a3), "r"(b0), "r"(b1));
}
__device__ __forceinline__ uint32_t packf16(float hi, float lo) {
    uint32_t r;
    asm("cvt.rn.f16x2.f32 %0, %1, %2;" : "=r"(r) : "f"(hi), "f"(lo));
    return r;
}
__device__ __forceinline__ uint32_t exp2_f16x2(uint32_t x) {
    uint32_t r;
    asm("ex2.approx.f16x2 %0, %1;" : "=r"(r) : "r"(x));
    return r;
}

// ---------------------------------------------------------------------------
// fp16 2-product GEMM: C[M,N] = (Ah+Al)[M,K] @ Bf[N,K]^T, fp32 accum.
// CTA 128x128, 8 warps (2x4), warp tile 64x32, BK=64, 2-stage cp.async.
// ---------------------------------------------------------------------------
#define GKC      64
#define TILEB    16384                    // 128 rows x 128B
#define STAGEB2  (3 * TILEB)              // Ah, Al, Bf
#define GSMEM2   (2 * STAGEB2)            // 98304

__device__ __forceinline__ void gemm2_issue_loads(
    uint32_t sb, int stage, int it,
    const __half* __restrict__ Ah, const __half* __restrict__ Al,
    const __half* __restrict__ Bf,
    int m0, int n0, int K, int tid)
{
    const int k0 = it * GKC;
    const __half* srcs[3] = { Ah, Al, Bf };
#pragma unroll
    for (int mtx = 0; mtx < 3; mtx++) {
        const __half* src = srcs[mtx];
        const int rowbase = (mtx < 2) ? m0 : n0;
        const uint32_t smb = sb + stage * STAGEB2 + mtx * TILEB;
#pragma unroll
        for (int j = 0; j < 4; j++) {
            int chunk = tid + j * 256;          // 0..1023
            int row = chunk >> 3;               // 0..127
            int c16 = chunk & 7;                // 16B units
            const void* gp = src + (size_t)(rowbase + row) * K + k0 + c16 * 8;
            uint32_t sp = smb + SWZ128(row * 128 + c16 * 16);
            asm volatile("cp.async.cg.shared.global [%0], [%1], 16;"
                         :: "r"(sp), "l"(gp));
        }
    }
    asm volatile("cp.async.commit_group;" ::: "memory");
}

__global__ __launch_bounds__(256) void hmma_gemm2_kernel(
    const __half* __restrict__ Ah, const __half* __restrict__ Al,
    const __half* __restrict__ Bf,
    float* __restrict__ C, int M, int N, int K)
{
    extern __shared__ char smem[];
    const uint32_t sb = smem_u32(smem);
    const int tid = threadIdx.x;
    const int wid = tid >> 5;
    const int l   = tid & 31;
    const int wm  = wid >> 2;
    const int wn  = wid & 3;
    const int m0  = blockIdx.y * 128;
    const int n0  = blockIdx.x * 128;

    float acc[4][4][4];
#pragma unroll
    for (int i = 0; i < 4; i++)
#pragma unroll
        for (int j = 0; j < 4; j++)
#pragma unroll
            for (int f = 0; f < 4; f++) acc[i][j][f] = 0.f;

    const int a_row_l = (l & 7) + (l & 8);
    const int a_col_l = ((l >> 4) & 1) * 16;
    const int b_row_l = (l & 7) + ((l >> 4) & 1) * 8;
    const int b_col_l = ((l >> 3) & 1) * 16;

    const int niter = K / GKC;
    gemm2_issue_loads(sb, 0, 0, Ah, Al, Bf, m0, n0, K, tid);

    for (int it = 0; it < niter; it++) {
        if (it + 1 < niter) {
            gemm2_issue_loads(sb, (it + 1) & 1, it + 1, Ah, Al, Bf, m0, n0, K, tid);
            asm volatile("cp.async.wait_group 1;" ::: "memory");
        } else {
            asm volatile("cp.async.wait_group 0;" ::: "memory");
        }
        __syncthreads();

        const uint32_t stg = sb + (it & 1) * STAGEB2;
        const uint32_t sAh = stg;
        const uint32_t sAl = stg + TILEB;
        const uint32_t sBf = stg + 2 * TILEB;

#pragma unroll
        for (int kk = 0; kk < 4; kk++) {
            const int kb = kk * 32;
            uint32_t ah[4][4], al[4][4], bf4[8];
#pragma unroll
            for (int mt = 0; mt < 4; mt++) {
                int row = wm * 64 + mt * 16 + a_row_l;
                uint32_t off = SWZ128(row * 128 + kb + a_col_l);
                ldsm4(ah[mt][0], ah[mt][1], ah[mt][2], ah[mt][3], sAh + off);
                ldsm4(al[mt][0], al[mt][1], al[mt][2], al[mt][3], sAl + off);
            }
#pragma unroll
            for (int nt2 = 0; nt2 < 2; nt2++) {
                int row = wn * 32 + nt2 * 16 + b_row_l;
                uint32_t off = SWZ128(row * 128 + kb + b_col_l);
                ldsm4(bf4[nt2 * 4 + 0], bf4[nt2 * 4 + 1],
                      bf4[nt2 * 4 + 2], bf4[nt2 * 4 + 3], sBf + off);
            }
#pragma unroll
            for (int mt = 0; mt < 4; mt++)
#pragma unroll
                for (int nt = 0; nt < 4; nt++) {
                    uint32_t b0 = bf4[(nt >> 1) * 4 + (nt & 1) * 2];
                    uint32_t b1 = bf4[(nt >> 1) * 4 + (nt & 1) * 2 + 1];
                    mma16816h(acc[mt][nt], ah[mt][0], ah[mt][1], ah[mt][2], ah[mt][3], b0, b1);
                    mma16816h(acc[mt][nt], al[mt][0], al[mt][1], al[mt][2], al[mt][3], b0, b1);
                }
        }
        __syncthreads();
    }

#pragma unroll
    for (int mt = 0; mt < 4; mt++) {
        int r0 = m0 + wm * 64 + mt * 16 + (l >> 2);
        int r1 = r0 + 8;
#pragma unroll
        for (int nt = 0; nt < 4; nt++) {
            int c = n0 + wn * 32 + nt * 8 + (l & 3) * 2;
            *(float2*)(C + (size_t)r0 * N + c) = make_float2(acc[mt][nt][0], acc[mt][nt][1]);
            *(float2*)(C + (size_t)r1 * N + c) = make_float2(acc[mt][nt][2], acc[mt][nt][3]);
        }
    }
}

// ---------------------------------------------------------------------------
// fp32 -> (f16 hi, f16 lo) elementwise split
// ---------------------------------------------------------------------------
__global__ void split16_kernel(const float4* __restrict__ in,
                               uint2* __restrict__ hi, uint2* __restrict__ lo, int n4)
{
    int i = blockIdx.x * blockDim.x + threadIdx.x;
    if (i >= n4) return;
    float4 v = in[i];
    __half h[4], lw[4];
    float x[4] = { v.x, v.y, v.z, v.w };
#pragma unroll
    for (int j = 0; j < 4; j++) {
        h[j] = __float2half(x[j]);
        lw[j] = __float2half(x[j] - __half2float(h[j]));
    }
    hi[i] = *(uint2*)h;
    lo[i] = *(uint2*)lw;
}

// fp32 -> fp16 elementwise
__global__ void f16conv_kernel(const float4* __restrict__ in,
                               __half2* __restrict__ out, int n4)
{
    int i = blockIdx.x * blockDim.x + threadIdx.x;
    if (i >= n4) return;
    float4 v = in[i];
    out[2 * i]     = __floats2half2_rn(v.x, v.y);
    out[2 * i + 1] = __floats2half2_rn(v.z, v.w);
}

// ---------------------------------------------------------------------------
// weight transpose: w[K,N] fp32 -> Wf[N,K] f16 (single rounding)
// ---------------------------------------------------------------------------
__global__ void tconv_kernel(const float* __restrict__ w,
                             __half* __restrict__ tf, int Kd, int Nd)
{
    __shared__ float tile[32][33];
    int n0 = blockIdx.x * 32, k0 = blockIdx.y * 32;
    int tx = threadIdx.x, ty = threadIdx.y;
#pragma unroll
    for (int j = 0; j < 32; j += 8)
        tile[ty + j][tx] = w[(size_t)(k0 + ty + j) * Nd + n0 + tx];
    __syncthreads();
#pragma unroll
    for (int j = 0; j < 32; j += 8) {
        float x = tile[tx][ty + j];
        tf[(size_t)(n0 + ty + j) * Kd + k0 + tx] = __float2half(x);
    }
}

// ---------------------------------------------------------------------------
// RoPE + hi/lo bf16 split: reads fp32 [B*S, heads, 128], writes hi/lo bf16
// ---------------------------------------------------------------------------
__global__ void rope_split_kernel(const float* __restrict__ src,
                                  __nv_bfloat16* __restrict__ hi,
                                  __nv_bfloat16* __restrict__ lo, int heads)
{
    int idx = blockIdx.x * blockDim.x + threadIdx.x;
    const int total = BATCH * SEQ * (DHEAD / 2);
    if (idx >= total) return;
    int i   = idx & 63;
    int row = idx >> 6;
    int s   = row & (SEQ - 1);
    double inv = exp(-0.14391156831212787 * (double)i);
    double sd, cd;
    sincos((double)s * inv, &sd, &cd);
    float c = (float)cd, sn = (float)sd;
    const float* p = src + (size_t)row * heads * DHEAD;
    __nv_bfloat16* ph = hi + (size_t)row * heads * DHEAD;
    __nv_bfloat16* pl = lo + (size_t)row * heads * DHEAD;
    for (int hh = 0; hh < heads; hh++, p += DHEAD, ph += DHEAD, pl += DHEAD) {
        float x1 = p[i], x2 = p[i + 64];
        float y1 = x1 * c - x2 * sn;
        float y2 = x2 * c + x1 * sn;
        __nv_bfloat16 h1 = __float2bfloat16(y1);
        __nv_bfloat16 h2 = __float2bfloat16(y2);
        ph[i]      = h1;  pl[i]      = __float2bfloat16(y1 - __bfloat162float(h1));
        ph[i + 64] = h2;  pl[i + 64] = __float2bfloat16(y2 - __bfloat162float(h2));
    }
}

// ---------------------------------------------------------------------------
// HMMA flash attention (unchanged core; epilogue writes f16 hi/lo).
// ---------------------------------------------------------------------------
#define AT_SMEM 163840
#define AT_STAGE0 65536
#define AT_STAGEB 49152

__device__ __forceinline__ void attn_issue_kv(
    uint32_t stbase, const __nv_bfloat16* khg, const __nv_bfloat16* klg,
    const __half* vg, int k0, int tid)
{
    const char* bases[3] = { (const char*)khg, (const char*)klg, (const char*)vg };
#pragma unroll
    for (int arr = 0; arr < 3; arr++) {
        const char* base = bases[arr];
        uint32_t soff = stbase + arr * 16384;
#pragma unroll
        for (int i = 0; i < 4; i++) {
            int chunk = tid + i * 256;
            int row = chunk >> 4, cc = chunk & 15;
            const void* gp = base + ((size_t)(k0 + row) * NKVD + cc * 8) * 2;
            uint32_t sp = soff + (cc >> 3) * 8192 + SWZ128(row * 128 + (cc & 7) * 16);
            asm volatile("cp.async.cg.shared.global [%0], [%1], 16;"
                         :: "r"(sp), "l"(gp));
        }
    }
}

__global__ __launch_bounds__(256, 1) void hmma_attn_kernel(const float* __restrict__ tptr)
{
    extern __shared__ char smem[];
    const uint32_t sb = smem_u32(smem);
    const int tid = threadIdx.x, w = tid >> 5, l = tid & 31;
    const int qt = blockIdx.x, h = blockIdx.y, b = blockIdx.z;
    const int kv = h >> 2;
    const int q0 = qt * 128;
    const int qw0 = q0 + w * 16;
    const float scale = 0.08838834764831845f / fmaxf(fabsf(tptr[0]), 1e-6f);
    const float sl = scale * 1.4426950408889634f;

    const uint32_t sQh = sb, sQl = sb + 32768;

    const __nv_bfloat16* qhg = g_qh + ((size_t)(b * SEQ) + q0) * DMODEL + h * DHEAD;
    const __nv_bfloat16* qlg = g_ql + ((size_t)(b * SEQ) + q0) * DMODEL + h * DHEAD;
    const __nv_bfloat16* khg = g_kh + (size_t)(b * SEQ) * NKVD + kv * DHEAD;
    const __nv_bfloat16* klg = g_kl + (size_t)(b * SEQ) * NKVD + kv * DHEAD;
    const __half*        vg  = g_vf + (size_t)(b * SEQ) * NKVD + kv * DHEAD;

    {
        const char* qb2[2] = { (const char*)qhg, (const char*)qlg };
#pragma unroll
        for (int arr = 0; arr < 2; arr++) {
            uint32_t soff = (arr == 0) ? sQh : sQl;
#pragma unroll
            for (int i = 0; i < 8; i++) {
                int chunk = tid + i * 256;
                int row = chunk >> 4, cc = chunk & 15;
                const void* gp = qb2[arr] + ((size_t)row * DMODEL + cc * 8) * 2;
                uint32_t sp = soff + (cc >> 3) * 16384 + SWZ128(row * 128 + (cc & 7) * 16);
                asm volatile("cp.async.cg.shared.global [%0], [%1], 16;"
                             :: "r"(sp), "l"(gp));
            }
        }
        attn_issue_kv(sb + AT_STAGE0, khg, klg, vg, 0, tid);
        asm volatile("cp.async.commit_group;" ::: "memory");
    }

    const int a_row_l = (l & 7) + (l & 8);
    const int a_col_l = ((l >> 4) & 1) * 16;
    const int b_row_l = (l & 7) + ((l >> 4) & 1) * 8;
    const int b_col_l = ((l >> 3) & 1) * 16;
    const int v_row_l = (l & 7) + ((l >> 3) & 1) * 8;
    const int v_col_l = ((l >> 4) & 1) * 16;

    float oacc[16][4];
    float lacc[4] = {0.f, 0.f, 0.f, 0.f};
#pragma unroll
    for (int i = 0; i < 16; i++)
#pragma unroll
        for (int f = 0; f < 4; f++) oacc[i][f] = 0.f;
    float m0 = -3.0e38f, m1 = -3.0e38f;

    const int nkt = 2 * qt + 2;
    for (int kt = 0; kt < nkt; kt++) {
        if (kt + 1 < nkt) {
            attn_issue_kv(sb + AT_STAGE0 + ((kt + 1) & 1) * AT_STAGEB,
                          khg, klg, vg, (kt + 1) * 64, tid);
            asm volatile("cp.async.commit_group;" ::: "memory");
            asm volatile("cp.async.wait_group 1;" ::: "memory");
        } else {
            asm volatile("cp.async.wait_group 0;" ::: "memory");
        }
        __syncthreads();

        const int k0 = kt * 64;
        const uint32_t st = sb + AT_STAGE0 + (kt & 1) * AT_STAGEB;

        if (k0 <= qw0 + 15) {
            float sacc[8][4];
#pragma unroll
            for (int i = 0; i < 8; i++)
#pragma unroll
                for (int f = 0; f < 4; f++) sacc[i][f] = 0.f;

#pragma unroll
            for (int ks = 0; ks < 8; ks++) {
                uint32_t qoff = (ks >> 2) * 16384 +
                    SWZ128((w * 16 + a_row_l) * 128 + (ks & 3) * 32 + a_col_l);
                uint32_t qa[4], qb_[4];
                ldsm4(qa[0], qa[1], qa[2], qa[3], sQh + qoff);
                ldsm4(qb_[0], qb_[1], qb_[2], qb_[3], sQl + qoff);
#pragma unroll
                for (int np = 0; np < 4; np++) {
                    uint32_t koff = st + (ks >> 2) * 8192 +
                        SWZ128((np * 16 + b_row_l) * 128 + (ks & 3) * 32 + b_col_l);
                    uint32_t kh4[4], kl4[4];
                    ldsm4(kh4[0], kh4[1], kh4[2], kh4[3], koff);
                    ldsm4(kl4[0], kl4[1], kl4[2], kl4[3], koff + 16384);
                    mma16816(sacc[2 * np],     qa[0], qa[1], qa[2], qa[3], kh4[0], kh4[1]);
                    mma16816(sacc[2 * np],     qa[0], qa[1], qa[2], qa[3], kl4[0], kl4[1]);
                    mma16816(sacc[2 * np],     qb_[0], qb_[1], qb_[2], qb_[3], kh4[0], kh4[1]);
                    mma16816(sacc[2 * np + 1], qa[0], qa[1], qa[2], qa[3], kh4[2], kh4[3]);
                    mma16816(sacc[2 * np + 1], qa[0], qa[1], qa[2], qa[3], kl4[2], kl4[3]);
                    mma16816(sacc[2 * np + 1], qb_[0], qb_[1], qb_[2], qb_[3], kh4[2], kh4[3]);
                }
            }

            if (k0 + 63 > qw0) {
                int qa0 = qw0 + (l >> 2), qa1 = qa0 + 8;
                int kc0 = k0 + 2 * (l & 3);
#pragma unroll
                for (int nt = 0; nt < 8; nt++) {
                    int kc = kc0 + nt * 8;
                    if (kc     > qa0) sacc[nt][0] = -3.0e38f;
                    if (kc + 1 > qa0) sacc[nt][1] = -3.0e38f;
                    if (kc     > qa1) sacc[nt][2] = -3.0e38f;
                    if (kc + 1 > qa1) sacc[nt][3] = -3.0e38f;
                }
            }

            float mx0 = -3.0e38f, mx1 = -3.0e38f;
#pragma unroll
            for (int nt = 0; nt < 8; nt++) {
                mx0 = fmaxf(mx0, fmaxf(sacc[nt][0], sacc[nt][1]));
                mx1 = fmaxf(mx1, fmaxf(sacc[nt][2], sacc[nt][3]));
            }
            mx0 = fmaxf(mx0, __shfl_xor_sync(0xffffffffu, mx0, 1));
            mx0 = fmaxf(mx0, __shfl_xor_sync(0xffffffffu, mx0, 2));
            mx1 = fmaxf(mx1, __shfl_xor_sync(0xffffffffu, mx1, 1));
            mx1 = fmaxf(mx1, __shfl_xor_sync(0xffffffffu, mx1, 2));
            float mn0 = fmaxf(m0, mx0), mn1 = fmaxf(m1, mx1);
            bool ch = (mn0 > m0) || (mn1 > m1);
            if (__any_sync(0xffffffffu, ch)) {
                float a0 = exp2f((m0 - mn0) * sl);
                float a1 = exp2f((m1 - mn1) * sl);
#pragma unroll
                for (int nt = 0; nt < 16; nt++) {
                    oacc[nt][0] *= a0; oacc[nt][1] *= a0;
                    oacc[nt][2] *= a1; oacc[nt][3] *= a1;
                }
                lacc[0] *= a0; lacc[1] *= a0; lacc[2] *= a1; lacc[3] *= a1;
            }
            m0 = mn0; m1 = mn1;
            const float bb0 = mn0 * sl, bb1 = mn1 * sl;

            uint32_t pp[8][2];
#pragma unroll
            for (int nt = 0; nt < 8; nt++) {
                float t0 = fmaf(sacc[nt][0], sl, -bb0);
                float t1 = fmaf(sacc[nt][1], sl, -bb0);
                float t2 = fmaf(sacc[nt][2], sl, -bb1);
                float t3 = fmaf(sacc[nt][3], sl, -bb1);
                pp[nt][0] = exp2_f16x2(packf16(t1, t0));
                pp[nt][1] = exp2_f16x2(packf16(t3, t2));
            }

#pragma unroll
            for (int ks = 0; ks < 4; ks++) {
                uint32_t pa0 = pp[2 * ks][0], pa1 = pp[2 * ks][1];
                uint32_t pa2 = pp[2 * ks + 1][0], pa3 = pp[2 * ks + 1][1];
                mma16816h(lacc, pa0, pa1, pa2, pa3, 0x3C003C00u, 0x3C003C00u);
#pragma unroll
                for (int jp = 0; jp < 8; jp++) {
                    uint32_t voff = st + 32768 + (jp >> 2) * 8192 +
                        SWZ128((ks * 16 + v_row_l) * 128 + (jp & 3) * 32 + v_col_l);
                    uint32_t v4[4];
                    ldsm4t(v4[0], v4[1], v4[2], v4[3], voff);
                    mma16816h(oacc[2 * jp],     pa0, pa1, pa2, pa3, v4[0], v4[1]);
                    mma16816h(oacc[2 * jp + 1], pa0, pa1, pa2, pa3, v4[2], v4[3]);
                }
            }
        }
        __syncthreads();
    }

    // ---- epilogue: normalize + f16 hi/lo split store ----
    const float inv0 = 1.0f / lacc[0];
    const float inv1 = 1.0f / lacc[2];
    const size_t r0g = (size_t)(b * SEQ) + qw0 + (l >> 2);
    const size_t r1g = r0g + 8;
#pragma unroll
    for (int nt = 0; nt < 16; nt++) {
        int col = h * DHEAD + nt * 8 + 2 * (l & 3);
        float v0 = oacc[nt][0] * inv0, v1 = oacc[nt][1] * inv0;
        float v2 = oacc[nt][2] * inv1, v3 = oacc[nt][3] * inv1;
        __half h0 = __float2half(v0), h1 = __float2half(v1);
        __half h2 = __float2half(v2), h3 = __float2half(v3);
        __half2 hp0; hp0.x = h0; hp0.y = h1;
        __half2 hp1; hp1.x = h2; hp1.y = h3;
        __half2 lp0;
        lp0.x = __float2half(v0 - __half2float(h0));
        lp0.y = __float2half(v1 - __half2float(h1));
        __half2 lp1;
        lp1.x = __float2half(v2 - __half2float(h2));
        lp1.y = __float2half(v3 - __half2float(h3));
        *(__half2*)(g_ofh + r0g * DMODEL + col) = hp0;
        *(__half2*)(g_ofl + r0g * DMODEL + col) = lp0;
        *(__half2*)(g_ofh + r1g * DMODEL + col) = hp1;
        *(__half2*)(g_ofl + r1g * DMODEL + col) = lp1;
    }
}

// ---------------------------------------------------------------------------
extern "C" void kernel_launch(void* const* d_in, const int* in_sizes, int n_in,
                              void* d_out, int out_size)
{
    const float* x  = (const float*)d_in[0];
    const float* wq = (const float*)d_in[1];
    const float* wk = (const float*)d_in[2];
    const float* wv = (const float*)d_in[3];
    const float* wo = (const float*)d_in[4];
    const float* tp = (const float*)d_in[5];
    float* out = (float*)d_out;

    float *qp, *kp, *vp;
    cudaGetSymbolAddress((void**)&qp, g_q);
    cudaGetSymbolAddress((void**)&kp, g_k);
    cudaGetSymbolAddress((void**)&vp, g_v);
    __nv_bfloat16 *qh, *ql, *kh, *kl;
    __half *vf, *xh, *xl, *ofh, *ofl, *wqf, *wkf, *wvf, *wof;
    cudaGetSymbolAddress((void**)&qh, g_qh);   cudaGetSymbolAddress((void**)&ql, g_ql);
    cudaGetSymbolAddress((void**)&kh, g_kh);   cudaGetSymbolAddress((void**)&kl, g_kl);
    cudaGetSymbolAddress((void**)&vf, g_vf);
    cudaGetSymbolAddress((void**)&xh, g_xh);   cudaGetSymbolAddress((void**)&xl, g_xl);
    cudaGetSymbolAddress((void**)&ofh, g_ofh); cudaGetSymbolAddress((void**)&ofl, g_ofl);
    cudaGetSymbolAddress((void**)&wqf, g_wqf); cudaGetSymbolAddress((void**)&wkf, g_wkf);
    cudaGetSymbolAddress((void**)&wvf, g_wvf); cudaGetSymbolAddress((void**)&wof, g_wof);

    cudaFuncSetAttribute(hmma_gemm2_kernel, cudaFuncAttributeMaxDynamicSharedMemorySize, GSMEM2);
    cudaFuncSetAttribute(hmma_attn_kernel, cudaFuncAttributeMaxDynamicSharedMemorySize, AT_SMEM);

    // split x (f16 hi/lo); transpose+round weights (f16)
    {
        int n4 = MTOT * DMODEL / 4;
        split16_kernel<<<(n4 + 255) / 256, 256>>>((const float4*)x, (uint2*)xh, (uint2*)xl, n4);
        tconv_kernel<<<dim3(DMODEL / 32, DMODEL / 32), dim3(32, 8)>>>(wq, wqf, DMODEL, DMODEL);
        tconv_kernel<<<dim3(NKVD / 32, DMODEL / 32), dim3(32, 8)>>>(wk, wkf, DMODEL, NKVD);
        tconv_kernel<<<dim3(NKVD / 32, DMODEL / 32), dim3(32, 8)>>>(wv, wvf, DMODEL, NKVD);
        tconv_kernel<<<dim3(DMODEL / 32, DMODEL / 32), dim3(32, 8)>>>(wo, wof, DMODEL, DMODEL);
    }

    // projections (fp16 2-product HMMA)
    hmma_gemm2_kernel<<<dim3(DMODEL / 128, MTOT / 128), 256, GSMEM2>>>(
        xh, xl, wqf, qp, MTOT, DMODEL, DMODEL);
    hmma_gemm2_kernel<<<dim3(NKVD / 128, MTOT / 128), 256, GSMEM2>>>(
        xh, xl, wkf, kp, MTOT, NKVD, DMODEL);
    hmma_gemm2_kernel<<<dim3(NKVD / 128, MTOT / 128), 256, GSMEM2>>>(
        xh, xl, wvf, vp, MTOT, NKVD, DMODEL);

    // RoPE + split to bf16 hi/lo; V -> fp16
    const int rthreads = BATCH * SEQ * (DHEAD / 2);
    rope_split_kernel<<<(rthreads + 255) / 256, 256>>>(qp, qh, ql, NHEADS);
    rope_split_kernel<<<(rthreads + 255) / 256, 256>>>(kp, kh, kl, NKV);
    {
        int n4 = MTOT * NKVD / 4;
        f16conv_kernel<<<(n4 + 255) / 256, 256>>>((const float4*)vp, (__half2*)vf, n4);
    }

    // flash attention (HMMA), writes f16 hi/lo attn-out
    hmma_attn_kernel<<<dim3(SEQ / 128, NHEADS, BATCH), 256, AT_SMEM>>>(tp);

    // output projection (fp16 2-product HMMA)
    hmma_gemm2_kernel<<<dim3(DMODEL / 128, MTOT / 128), 256, GSMEM2>>>(
        ofh, ofl, wof, out, MTOT, DMODEL, DMODEL);
}

// round 6
// speedup vs baseline: 4.7240x; 1.0515x over previous
#include <cuda_runtime.h>
#include <cuda_bf16.h>
#include <cuda_fp16.h>
#include <math.h>
#include <stdint.h>

#define BATCH   4
#define SEQ     2048
#define DMODEL  2048
#define NHEADS  16
#define NKV     4
#define DHEAD   128
#define MTOT    (BATCH * SEQ)          // 8192
#define NKVD    (NKV * DHEAD)          // 512
#define NQKV    (DMODEL + 2 * NKVD)    // 3072

// ---------------- scratch ----------
__device__ float g_q[MTOT * NHEADS * DHEAD];     // fp32 proj out (pre-rope)
__device__ float g_k[MTOT * NKVD];

__device__ __nv_bfloat16 g_qh[MTOT * DMODEL], g_ql[MTOT * DMODEL];   // roped Q hi/lo
__device__ __nv_bfloat16 g_kh[MTOT * NKVD],  g_kl[MTOT * NKVD];      // roped K hi/lo
__device__ __half        g_vf[MTOT * NKVD];                          // V fp16

__device__ __half g_xh[MTOT * DMODEL], g_xl[MTOT * DMODEL];          // x hi/lo f16
__device__ __half g_ofh[MTOT * DMODEL], g_ofl[MTOT * DMODEL];        // attn out hi/lo f16
__device__ __half g_wqkv[NQKV * DMODEL];                             // [Wq;Wk;Wv]^T f16
__device__ __half g_wof[DMODEL * DMODEL];

__device__ float g_ropec[SEQ * 64], g_ropes[SEQ * 64];

// ---------------- helpers ---------------------------------------------
__device__ __forceinline__ uint32_t smem_u32(const void* p) {
    uint32_t a;
    asm("{ .reg .u64 t; cvta.to.shared.u64 t, %1; cvt.u32.u64 %0, t; }"
        : "=r"(a) : "l"(p));
    return a;
}
#define SWZ128(o) ((o) ^ (((o) >> 3) & 0x70))

__device__ __forceinline__ void ldsm4(uint32_t& r0, uint32_t& r1,
                                      uint32_t& r2, uint32_t& r3, uint32_t addr) {
    asm volatile("ldmatrix.sync.aligned.m8n8.x4.shared.b16 {%0,%1,%2,%3}, [%4];"
                 : "=r"(r0), "=r"(r1), "=r"(r2), "=r"(r3) : "r"(addr));
}
__device__ __forceinline__ void ldsm4t(uint32_t& r0, uint32_t& r1,
                                       uint32_t& r2, uint32_t& r3, uint32_t addr) {
    asm volatile("ldmatrix.sync.aligned.m8n8.x4.trans.shared.b16 {%0,%1,%2,%3}, [%4];"
                 : "=r"(r0), "=r"(r1), "=r"(r2), "=r"(r3) : "r"(addr));
}
__device__ __forceinline__ void mma16816(float* c, uint32_t a0, uint32_t a1,
                                         uint32_t a2, uint32_t a3,
                                         uint32_t b0, uint32_t b1) {
    asm volatile(
        "mma.sync.aligned.m16n8k16.row.col.f32.bf16.bf16.f32 "
        "{%0,%1,%2,%3},{%4,%5,%6,%7},{%8,%9},{%0,%1,%2,%3};"
        : "+f"(c[0]), "+f"(c[1]), "+f"(c[2]), "+f"(c[3])
        : "r"(a0), "r"(a1), "r"(a2), "r"(a3), "r"(b0), "r"(b1));
}
__device__ __forceinline__ void mma16816h(float* c, uint32_t a0, uint32_t a1,
                                          uint32_t a2, uint32_t a3,
                                          uint32_t b0, uint32_t b1) {
    asm volatile(
        "mma.sync.aligned.m16n8k16.row.col.f32.f16.f16.f32 "
        "{%0,%1,%2,%3},{%4,%5,%6,%7},{%8,%9},{%0,%1,%2,%3};"
        : "+f"(c[0]), "+f"(c[1]), "+f"(c[2]), "+f"(c[3])
        : "r"(a0), "r"(a1), "r"(a2), "r"(a3), "r"(b0), "r"(b1));
}
__device__ __forceinline__ uint32_t packf16(float hi, float lo) {
    uint32_t r;
    asm("cvt.rn.f16x2.f32 %0, %1, %2;" : "=r"(r) : "f"(hi), "f"(lo));
    return r;
}
__device__ __forceinline__ uint32_t exp2_f16x2(uint32_t x) {
    uint32_t r;
    asm("ex2.approx.f16x2 %0, %1;" : "=r"(r) : "r"(x));
    return r;
}

// ---------------------------------------------------------------------------
// fp16 2-product GEMM core: C[M,3072 or 2048] = (Ah+Al)[M,2048] @ B[N,2048]^T
// CTA 128x128, 8 warps, warp 64x32, BK=64, 3-stage cp.async pipeline.
// ---------------------------------------------------------------------------
#define GKC      64
#define GK       2048
#define GNITER   (GK / GKC)               // 32
#define TILEB    16384                    // 128 rows x 128B
#define STAGEB   (3 * TILEB)              // Ah, Al, Bf
#define GSMEM3   (3 * STAGEB)             // 147456

__device__ __forceinline__ void gemm_issue(
    uint32_t sb, int stage, int it,
    const __half* __restrict__ Ah, const __half* __restrict__ Al,
    const __half* __restrict__ Bf, int m0, int n0, int tid)
{
    const int k0 = it * GKC;
    const __half* srcs[3] = { Ah, Al, Bf };
#pragma unroll
    for (int mtx = 0; mtx < 3; mtx++) {
        const __half* src = srcs[mtx];
        const int rowbase = (mtx < 2) ? m0 : n0;
        const uint32_t smb = sb + stage * STAGEB + mtx * TILEB;
#pragma unroll
        for (int j = 0; j < 4; j++) {
            int chunk = tid + j * 256;
            int row = chunk >> 3;
            int c16 = chunk & 7;
            const void* gp = src + (size_t)(rowbase + row) * GK + k0 + c16 * 8;
            uint32_t sp = smb + SWZ128(row * 128 + c16 * 16);
            asm volatile("cp.async.cg.shared.global [%0], [%1], 16;"
                         :: "r"(sp), "l"(gp));
        }
    }
    asm volatile("cp.async.commit_group;" ::: "memory");
}

__device__ __forceinline__ void gemm_mainloop(
    uint32_t sb, const __half* __restrict__ Ah, const __half* __restrict__ Al,
    const __half* __restrict__ Bf, int m0, int n0, int tid,
    float acc[4][4][4])
{
    const int wid = tid >> 5, l = tid & 31;
    const int wm = wid >> 2, wn = wid & 3;
    const int a_row_l = (l & 7) + (l & 8);
    const int a_col_l = ((l >> 4) & 1) * 16;
    const int b_row_l = (l & 7) + ((l >> 4) & 1) * 8;
    const int b_col_l = ((l >> 3) & 1) * 16;

    gemm_issue(sb, 0, 0, Ah, Al, Bf, m0, n0, tid);
    gemm_issue(sb, 1, 1, Ah, Al, Bf, m0, n0, tid);

    for (int it = 0; it < GNITER; it++) {
        if (it + 1 < GNITER) {
            asm volatile("cp.async.wait_group 1;" ::: "memory");
        } else {
            asm volatile("cp.async.wait_group 0;" ::: "memory");
        }
        __syncthreads();
        if (it + 2 < GNITER)
            gemm_issue(sb, (it + 2) % 3, it + 2, Ah, Al, Bf, m0, n0, tid);

        const uint32_t stg = sb + (it % 3) * STAGEB;
        const uint32_t sAh = stg;
        const uint32_t sAl = stg + TILEB;
        const uint32_t sBf = stg + 2 * TILEB;

#pragma unroll
        for (int kk = 0; kk < 4; kk++) {
            const int kb = kk * 32;
            uint32_t ah[4][4], al[4][4], bf4[8];
#pragma unroll
            for (int mt = 0; mt < 4; mt++) {
                int row = wm * 64 + mt * 16 + a_row_l;
                uint32_t off = SWZ128(row * 128 + kb + a_col_l);
                ldsm4(ah[mt][0], ah[mt][1], ah[mt][2], ah[mt][3], sAh + off);
                ldsm4(al[mt][0], al[mt][1], al[mt][2], al[mt][3], sAl + off);
            }
#pragma unroll
            for (int nt2 = 0; nt2 < 2; nt2++) {
                int row = wn * 32 + nt2 * 16 + b_row_l;
                uint32_t off = SWZ128(row * 128 + kb + b_col_l);
                ldsm4(bf4[nt2 * 4 + 0], bf4[nt2 * 4 + 1],
                      bf4[nt2 * 4 + 2], bf4[nt2 * 4 + 3], sBf + off);
            }
#pragma unroll
            for (int mt = 0; mt < 4; mt++)
#pragma unroll
                for (int nt = 0; nt < 4; nt++) {
                    uint32_t b0 = bf4[(nt >> 1) * 4 + (nt & 1) * 2];
                    uint32_t b1 = bf4[(nt >> 1) * 4 + (nt & 1) * 2 + 1];
                    mma16816h(acc[mt][nt], ah[mt][0], ah[mt][1], ah[mt][2], ah[mt][3], b0, b1);
                    mma16816h(acc[mt][nt], al[mt][0], al[mt][1], al[mt][2], al[mt][3], b0, b1);
                }
        }
    }
}

// Fused QKV projection: N = 3072 (cols 0..2047 -> q fp32, 2048..2559 -> k fp32,
// 2560..3071 -> v fp16)
__global__ __launch_bounds__(256) void qkv_gemm_kernel(
    const __half* __restrict__ xh, const __half* __restrict__ xl,
    const __half* __restrict__ wqkv,
    float* __restrict__ qp, float* __restrict__ kp, __half* __restrict__ vfp)
{
    extern __shared__ char smem[];
    const uint32_t sb = smem_u32(smem);
    const int tid = threadIdx.x, wid = tid >> 5, l = tid & 31;
    const int wm = wid >> 2, wn = wid & 3;
    const int m0 = blockIdx.y * 128;
    const int n0 = blockIdx.x * 128;

    float acc[4][4][4];
#pragma unroll
    for (int i = 0; i < 4; i++)
#pragma unroll
        for (int j = 0; j < 4; j++)
#pragma unroll
            for (int f = 0; f < 4; f++) acc[i][j][f] = 0.f;

    gemm_mainloop(sb, xh, xl, wqkv, m0, n0, tid, acc);

    if (n0 < DMODEL) {
#pragma unroll
        for (int mt = 0; mt < 4; mt++) {
            int r0 = m0 + wm * 64 + mt * 16 + (l >> 2);
#pragma unroll
            for (int nt = 0; nt < 4; nt++) {
                int c = n0 + wn * 32 + nt * 8 + (l & 3) * 2;
                *(float2*)(qp + (size_t)r0 * DMODEL + c) =
                    make_float2(acc[mt][nt][0], acc[mt][nt][1]);
                *(float2*)(qp + (size_t)(r0 + 8) * DMODEL + c) =
                    make_float2(acc[mt][nt][2], acc[mt][nt][3]);
            }
        }
    } else if (n0 < DMODEL + NKVD) {
        int nb = n0 - DMODEL;
#pragma unroll
        for (int mt = 0; mt < 4; mt++) {
            int r0 = m0 + wm * 64 + mt * 16 + (l >> 2);
#pragma unroll
            for (int nt = 0; nt < 4; nt++) {
                int c = nb + wn * 32 + nt * 8 + (l & 3) * 2;
                *(float2*)(kp + (size_t)r0 * NKVD + c) =
                    make_float2(acc[mt][nt][0], acc[mt][nt][1]);
                *(float2*)(kp + (size_t)(r0 + 8) * NKVD + c) =
                    make_float2(acc[mt][nt][2], acc[mt][nt][3]);
            }
        }
    } else {
        int nb = n0 - DMODEL - NKVD;
#pragma unroll
        for (int mt = 0; mt < 4; mt++) {
            int r0 = m0 + wm * 64 + mt * 16 + (l >> 2);
#pragma unroll
            for (int nt = 0; nt < 4; nt++) {
                int c = nb + wn * 32 + nt * 8 + (l & 3) * 2;
                *(__half2*)(vfp + (size_t)r0 * NKVD + c) =
                    __floats2half2_rn(acc[mt][nt][0], acc[mt][nt][1]);
                *(__half2*)(vfp + (size_t)(r0 + 8) * NKVD + c) =
                    __floats2half2_rn(acc[mt][nt][2], acc[mt][nt][3]);
            }
        }
    }
}

// Output projection: N = 2048, fp32 out
__global__ __launch_bounds__(256) void oproj_gemm_kernel(
    const __half* __restrict__ Ah, const __half* __restrict__ Al,
    const __half* __restrict__ Bf, float* __restrict__ C)
{
    extern __shared__ char smem[];
    const uint32_t sb = smem_u32(smem);
    const int tid = threadIdx.x, wid = tid >> 5, l = tid & 31;
    const int wm = wid >> 2, wn = wid & 3;
    const int m0 = blockIdx.y * 128;
    const int n0 = blockIdx.x * 128;

    float acc[4][4][4];
#pragma unroll
    for (int i = 0; i < 4; i++)
#pragma unroll
        for (int j = 0; j < 4; j++)
#pragma unroll
            for (int f = 0; f < 4; f++) acc[i][j][f] = 0.f;

    gemm_mainloop(sb, Ah, Al, Bf, m0, n0, tid, acc);

#pragma unroll
    for (int mt = 0; mt < 4; mt++) {
        int r0 = m0 + wm * 64 + mt * 16 + (l >> 2);
#pragma unroll
        for (int nt = 0; nt < 4; nt++) {
            int c = n0 + wn * 32 + nt * 8 + (l & 3) * 2;
            *(float2*)(C + (size_t)r0 * DMODEL + c) =
                make_float2(acc[mt][nt][0], acc[mt][nt][1]);
            *(float2*)(C + (size_t)(r0 + 8) * DMODEL + c) =
                make_float2(acc[mt][nt][2], acc[mt][nt][3]);
        }
    }
}

// ---------------------------------------------------------------------------
// elementwise converters
// ---------------------------------------------------------------------------
__global__ void split16_kernel(const float4* __restrict__ in,
                               uint2* __restrict__ hi, uint2* __restrict__ lo, int n4)
{
    int i = blockIdx.x * blockDim.x + threadIdx.x;
    if (i >= n4) return;
    float4 v = in[i];
    __half h[4], lw[4];
    float x[4] = { v.x, v.y, v.z, v.w };
#pragma unroll
    for (int j = 0; j < 4; j++) {
        h[j] = __float2half(x[j]);
        lw[j] = __float2half(x[j] - __half2float(h[j]));
    }
    hi[i] = *(uint2*)h;
    lo[i] = *(uint2*)lw;
}

// weight transpose: w[K,N] fp32 -> tf[N,K] f16 (tf pre-offset by caller)
__global__ void tconv_kernel(const float* __restrict__ w,
                             __half* __restrict__ tf, int Kd, int Nd)
{
    __shared__ float tile[32][33];
    int n0 = blockIdx.x * 32, k0 = blockIdx.y * 32;
    int tx = threadIdx.x, ty = threadIdx.y;
#pragma unroll
    for (int j = 0; j < 32; j += 8)
        tile[ty + j][tx] = w[(size_t)(k0 + ty + j) * Nd + n0 + tx];
    __syncthreads();
#pragma unroll
    for (int j = 0; j < 32; j += 8) {
        float x = tile[tx][ty + j];
        tf[(size_t)(n0 + ty + j) * Kd + k0 + tx] = __float2half(x);
    }
}

// RoPE table precompute (fp64 trig, computed once)
__global__ void rope_table_kernel()
{
    int idx = blockIdx.x * blockDim.x + threadIdx.x;
    if (idx >= SEQ * 64) return;
    int i = idx & 63, s = idx >> 6;
    double inv = exp(-0.14391156831212787 * (double)i);
    double sd, cd;
    sincos((double)s * inv, &sd, &cd);
    g_ropec[idx] = (float)cd;
    g_ropes[idx] = (float)sd;
}

// RoPE + hi/lo bf16 split (table-driven)
__global__ void rope_split_kernel(const float* __restrict__ src,
                                  __nv_bfloat16* __restrict__ hi,
                                  __nv_bfloat16* __restrict__ lo, int heads)
{
    int idx = blockIdx.x * blockDim.x + threadIdx.x;
    const int total = BATCH * SEQ * (DHEAD / 2);
    if (idx >= total) return;
    int i   = idx & 63;
    int row = idx >> 6;
    int s   = row & (SEQ - 1);
    float c  = g_ropec[s * 64 + i];
    float sn = g_ropes[s * 64 + i];
    const float* p = src + (size_t)row * heads * DHEAD;
    __nv_bfloat16* ph = hi + (size_t)row * heads * DHEAD;
    __nv_bfloat16* pl = lo + (size_t)row * heads * DHEAD;
    for (int hh = 0; hh < heads; hh++, p += DHEAD, ph += DHEAD, pl += DHEAD) {
        float x1 = p[i], x2 = p[i + 64];
        float y1 = x1 * c - x2 * sn;
        float y2 = x2 * c + x1 * sn;
        __nv_bfloat16 h1 = __float2bfloat16(y1);
        __nv_bfloat16 h2 = __float2bfloat16(y2);
        ph[i]      = h1;  pl[i]      = __float2bfloat16(y1 - __bfloat162float(h1));
        ph[i + 64] = h2;  pl[i + 64] = __float2bfloat16(y2 - __bfloat162float(h2));
    }
}

// ---------------------------------------------------------------------------
// HMMA flash attention (3-stage KV pipeline)
// ---------------------------------------------------------------------------
#define AT_STAGE0 65536
#define AT_STAGEB 49152
#define AT_SMEM   (AT_STAGE0 + 3 * AT_STAGEB)   // 212992

__device__ __forceinline__ void attn_issue_kv(
    uint32_t stbase, const __nv_bfloat16* khg, const __nv_bfloat16* klg,
    const __half* vg, int k0, int tid)
{
    const char* bases[3] = { (const char*)khg, (const char*)klg, (const char*)vg };
#pragma unroll
    for (int arr = 0; arr < 3; arr++) {
        const char* base = bases[arr];
        uint32_t soff = stbase + arr * 16384;
#pragma unroll
        for (int i = 0; i < 4; i++) {
            int chunk = tid + i * 256;
            int row = chunk >> 4, cc = chunk & 15;
            const void* gp = base + ((size_t)(k0 + row) * NKVD + cc * 8) * 2;
            uint32_t sp = soff + (cc >> 3) * 8192 + SWZ128(row * 128 + (cc & 7) * 16);
            asm volatile("cp.async.cg.shared.global [%0], [%1], 16;"
                         :: "r"(sp), "l"(gp));
        }
    }
    asm volatile("cp.async.commit_group;" ::: "memory");
}

__global__ __launch_bounds__(256, 1) void hmma_attn_kernel(const float* __restrict__ tptr)
{
    extern __shared__ char smem[];
    const uint32_t sb = smem_u32(smem);
    const int tid = threadIdx.x, w = tid >> 5, l = tid & 31;
    const int qt = blockIdx.x, h = blockIdx.y, b = blockIdx.z;
    const int kv = h >> 2;
    const int q0 = qt * 128;
    const int qw0 = q0 + w * 16;
    const float scale = 0.08838834764831845f / fmaxf(fabsf(tptr[0]), 1e-6f);
    const float sl = scale * 1.4426950408889634f;

    const uint32_t sQh = sb, sQl = sb + 32768;

    const __nv_bfloat16* qhg = g_qh + ((size_t)(b * SEQ) + q0) * DMODEL + h * DHEAD;
    const __nv_bfloat16* qlg = g_ql + ((size_t)(b * SEQ) + q0) * DMODEL + h * DHEAD;
    const __nv_bfloat16* khg = g_kh + (size_t)(b * SEQ) * NKVD + kv * DHEAD;
    const __nv_bfloat16* klg = g_kl + (size_t)(b * SEQ) * NKVD + kv * DHEAD;
    const __half*        vg  = g_vf + (size_t)(b * SEQ) * NKVD + kv * DHEAD;

    const int nkt = 2 * qt + 2;

    // prologue: group0 = Q + kv0, group1 = kv1
    {
        const char* qb2[2] = { (const char*)qhg, (const char*)qlg };
#pragma unroll
        for (int arr = 0; arr < 2; arr++) {
            uint32_t soff = (arr == 0) ? sQh : sQl;
#pragma unroll
            for (int i = 0; i < 8; i++) {
                int chunk = tid + i * 256;
                int row = chunk >> 4, cc = chunk & 15;
                const void* gp = qb2[arr] + ((size_t)row * DMODEL + cc * 8) * 2;
                uint32_t sp = soff + (cc >> 3) * 16384 + SWZ128(row * 128 + (cc & 7) * 16);
                asm volatile("cp.async.cg.shared.global [%0], [%1], 16;"
                             :: "r"(sp), "l"(gp));
            }
        }
        attn_issue_kv(sb + AT_STAGE0, khg, klg, vg, 0, tid);       // commits group 0
        attn_issue_kv(sb + AT_STAGE0 + AT_STAGEB, khg, klg, vg, 64, tid); // group 1
    }

    const int a_row_l = (l & 7) + (l & 8);
    const int a_col_l = ((l >> 4) & 1) * 16;
    const int b_row_l = (l & 7) + ((l >> 4) & 1) * 8;
    const int b_col_l = ((l >> 3) & 1) * 16;
    const int v_row_l = (l & 7) + ((l >> 3) & 1) * 8;
    const int v_col_l = ((l >> 4) & 1) * 16;

    float oacc[16][4];
    float lacc[4] = {0.f, 0.f, 0.f, 0.f};
#pragma unroll
    for (int i = 0; i < 16; i++)
#pragma unroll
        for (int f = 0; f < 4; f++) oacc[i][f] = 0.f;
    float m0 = -3.0e38f, m1 = -3.0e38f;

    for (int kt = 0; kt < nkt; kt++) {
        if (kt + 1 < nkt) {
            asm volatile("cp.async.wait_group 1;" ::: "memory");
        } else {
            asm volatile("cp.async.wait_group 0;" ::: "memory");
        }
        __syncthreads();
        if (kt + 2 < nkt)
            attn_issue_kv(sb + AT_STAGE0 + ((kt + 2) % 3) * AT_STAGEB,
                          khg, klg, vg, (kt + 2) * 64, tid);

        const int k0 = kt * 64;
        const uint32_t st = sb + AT_STAGE0 + (kt % 3) * AT_STAGEB;

        if (k0 <= qw0 + 15) {
            float sacc[8][4];
#pragma unroll
            for (int i = 0; i < 8; i++)
#pragma unroll
                for (int f = 0; f < 4; f++) sacc[i][f] = 0.f;

#pragma unroll
            for (int ks = 0; ks < 8; ks++) {
                uint32_t qoff = (ks >> 2) * 16384 +
                    SWZ128((w * 16 + a_row_l) * 128 + (ks & 3) * 32 + a_col_l);
                uint32_t qa[4], qb_[4];
                ldsm4(qa[0], qa[1], qa[2], qa[3], sQh + qoff);
                ldsm4(qb_[0], qb_[1], qb_[2], qb_[3], sQl + qoff);
#pragma unroll
                for (int np = 0; np < 4; np++) {
                    uint32_t koff = st + (ks >> 2) * 8192 +
                        SWZ128((np * 16 + b_row_l) * 128 + (ks & 3) * 32 + b_col_l);
                    uint32_t kh4[4], kl4[4];
                    ldsm4(kh4[0], kh4[1], kh4[2], kh4[3], koff);
                    ldsm4(kl4[0], kl4[1], kl4[2], kl4[3], koff + 16384);
                    mma16816(sacc[2 * np],     qa[0], qa[1], qa[2], qa[3], kh4[0], kh4[1]);
                    mma16816(sacc[2 * np],     qa[0], qa[1], qa[2], qa[3], kl4[0], kl4[1]);
                    mma16816(sacc[2 * np],     qb_[0], qb_[1], qb_[2], qb_[3], kh4[0], kh4[1]);
                    mma16816(sacc[2 * np + 1], qa[0], qa[1], qa[2], qa[3], kh4[2], kh4[3]);
                    mma16816(sacc[2 * np + 1], qa[0], qa[1], qa[2], qa[3], kl4[2], kl4[3]);
                    mma16816(sacc[2 * np + 1], qb_[0], qb_[1], qb_[2], qb_[3], kh4[2], kh4[3]);
                }
            }

            if (k0 + 63 > qw0) {
                int qa0 = qw0 + (l >> 2), qa1 = qa0 + 8;
                int kc0 = k0 + 2 * (l & 3);
#pragma unroll
                for (int nt = 0; nt < 8; nt++) {
                    int kc = kc0 + nt * 8;
                    if (kc     > qa0) sacc[nt][0] = -3.0e38f;
                    if (kc + 1 > qa0) sacc[nt][1] = -3.0e38f;
                    if (kc     > qa1) sacc[nt][2] = -3.0e38f;
                    if (kc + 1 > qa1) sacc[nt][3] = -3.0e38f;
                }
            }

            float mx0 = -3.0e38f, mx1 = -3.0e38f;
#pragma unroll
            for (int nt = 0; nt < 8; nt++) {
                mx0 = fmaxf(mx0, fmaxf(sacc[nt][0], sacc[nt][1]));
                mx1 = fmaxf(mx1, fmaxf(sacc[nt][2], sacc[nt][3]));
            }
            mx0 = fmaxf(mx0, __shfl_xor_sync(0xffffffffu, mx0, 1));
            mx0 = fmaxf(mx0, __shfl_xor_sync(0xffffffffu, mx0, 2));
            mx1 = fmaxf(mx1, __shfl_xor_sync(0xffffffffu, mx1, 1));
            mx1 = fmaxf(mx1, __shfl_xor_sync(0xffffffffu, mx1, 2));
            float mn0 = fmaxf(m0, mx0), mn1 = fmaxf(m1, mx1);
            bool ch = (mn0 > m0) || (mn1 > m1);
            if (__any_sync(0xffffffffu, ch)) {
                float a0 = exp2f((m0 - mn0) * sl);
                float a1 = exp2f((m1 - mn1) * sl);
#pragma unroll
                for (int nt = 0; nt < 16; nt++) {
                    oacc[nt][0] *= a0; oacc[nt][1] *= a0;
                    oacc[nt][2] *= a1; oacc[nt][3] *= a1;
                }
                lacc[0] *= a0; lacc[1] *= a0; lacc[2] *= a1; lacc[3] *= a1;
            }
            m0 = mn0; m1 = mn1;
            const float bb0 = mn0 * sl, bb1 = mn1 * sl;

            uint32_t pp[8][2];
#pragma unroll
            for (int nt = 0; nt < 8; nt++) {
                float t0 = fmaf(sacc[nt][0], sl, -bb0);
                float t1 = fmaf(sacc[nt][1], sl, -bb0);
                float t2 = fmaf(sacc[nt][2], sl, -bb1);
                float t3 = fmaf(sacc[nt][3], sl, -bb1);
                pp[nt][0] = exp2_f16x2(packf16(t1, t0));
                pp[nt][1] = exp2_f16x2(packf16(t3, t2));
            }

#pragma unroll
            for (int ks = 0; ks < 4; ks++) {
                uint32_t pa0 = pp[2 * ks][0], pa1 = pp[2 * ks][1];
                uint32_t pa2 = pp[2 * ks + 1][0], pa3 = pp[2 * ks + 1][1];
                mma16816h(lacc, pa0, pa1, pa2, pa3, 0x3C003C00u, 0x3C003C00u);
#pragma unroll
                for (int jp = 0; jp < 8; jp++) {
                    uint32_t voff = st + 32768 + (jp >> 2) * 8192 +
                        SWZ128((ks * 16 + v_row_l) * 128 + (jp & 3) * 32 + v_col_l);
                    uint32_t v4[4];
                    ldsm4t(v4[0], v4[1], v4[2], v4[3], voff);
                    mma16816h(oacc[2 * jp],     pa0, pa1, pa2, pa3, v4[0], v4[1]);
                    mma16816h(oacc[2 * jp + 1], pa0, pa1, pa2, pa3, v4[2], v4[3]);
                }
            }
        }
    }

    // epilogue: normalize + f16 hi/lo split store
    const float inv0 = 1.0f / lacc[0];
    const float inv1 = 1.0f / lacc[2];
    const size_t r0g = (size_t)(b * SEQ) + qw0 + (l >> 2);
    const size_t r1g = r0g + 8;
#pragma unroll
    for (int nt = 0; nt < 16; nt++) {
        int col = h * DHEAD + nt * 8 + 2 * (l & 3);
        float v0 = oacc[nt][0] * inv0, v1 = oacc[nt][1] * inv0;
        float v2 = oacc[nt][2] * inv1, v3 = oacc[nt][3] * inv1;
        __half h0 = __float2half(v0), h1 = __float2half(v1);
        __half h2 = __float2half(v2), h3 = __float2half(v3);
        __half2 hp0; hp0.x = h0; hp0.y = h1;
        __half2 hp1; hp1.x = h2; hp1.y = h3;
        __half2 lp0;
        lp0.x = __float2half(v0 - __half2float(h0));
        lp0.y = __float2half(v1 - __half2float(h1));
        __half2 lp1;
        lp1.x = __float2half(v2 - __half2float(h2));
        lp1.y = __float2half(v3 - __half2float(h3));
        *(__half2*)(g_ofh + r0g * DMODEL + col) = hp0;
        *(__half2*)(g_ofl + r0g * DMODEL + col) = lp0;
        *(__half2*)(g_ofh + r1g * DMODEL + col) = hp1;
        *(__half2*)(g_ofl + r1g * DMODEL + col) = lp1;
    }
}

// ---------------------------------------------------------------------------
extern "C" void kernel_launch(void* const* d_in, const int* in_sizes, int n_in,
                              void* d_out, int out_size)
{
    const float* x  = (const float*)d_in[0];
    const float* wq = (const float*)d_in[1];
    const float* wk = (const float*)d_in[2];
    const float* wv = (const float*)d_in[3];
    const float* wo = (const float*)d_in[4];
    const float* tp = (const float*)d_in[5];
    float* out = (float*)d_out;

    float *qp, *kp;
    cudaGetSymbolAddress((void**)&qp, g_q);
    cudaGetSymbolAddress((void**)&kp, g_k);
    __nv_bfloat16 *qh, *ql, *kh, *kl;
    __half *vf, *xh, *xl, *ofh, *ofl, *wqkv, *wof;
    cudaGetSymbolAddress((void**)&qh, g_qh);   cudaGetSymbolAddress((void**)&ql, g_ql);
    cudaGetSymbolAddress((void**)&kh, g_kh);   cudaGetSymbolAddress((void**)&kl, g_kl);
    cudaGetSymbolAddress((void**)&vf, g_vf);
    cudaGetSymbolAddress((void**)&xh, g_xh);   cudaGetSymbolAddress((void**)&xl, g_xl);
    cudaGetSymbolAddress((void**)&ofh, g_ofh); cudaGetSymbolAddress((void**)&ofl, g_ofl);
    cudaGetSymbolAddress((void**)&wqkv, g_wqkv);
    cudaGetSymbolAddress((void**)&wof, g_wof);

    cudaFuncSetAttribute(qkv_gemm_kernel, cudaFuncAttributeMaxDynamicSharedMemorySize, GSMEM3);
    cudaFuncSetAttribute(oproj_gemm_kernel, cudaFuncAttributeMaxDynamicSharedMemorySize, GSMEM3);
    cudaFuncSetAttribute(hmma_attn_kernel, cudaFuncAttributeMaxDynamicSharedMemorySize, AT_SMEM);

    // converters + rope table
    rope_table_kernel<<<(SEQ * 64 + 255) / 256, 256>>>();
    {
        int n4 = MTOT * DMODEL / 4;
        split16_kernel<<<(n4 + 255) / 256, 256>>>((const float4*)x, (uint2*)xh, (uint2*)xl, n4);
        tconv_kernel<<<dim3(DMODEL / 32, DMODEL / 32), dim3(32, 8)>>>(wq, wqkv, DMODEL, DMODEL);
        tconv_kernel<<<dim3(NKVD / 32, DMODEL / 32), dim3(32, 8)>>>(
            wk, wqkv + (size_t)DMODEL * DMODEL, DMODEL, NKVD);
        tconv_kernel<<<dim3(NKVD / 32, DMODEL / 32), dim3(32, 8)>>>(
            wv, wqkv + (size_t)(DMODEL + NKVD) * DMODEL, DMODEL, NKVD);
        tconv_kernel<<<dim3(DMODEL / 32, DMODEL / 32), dim3(32, 8)>>>(wo, wof, DMODEL, DMODEL);
    }

    // fused QKV projection (V written as f16 directly)
    qkv_gemm_kernel<<<dim3(NQKV / 128, MTOT / 128), 256, GSMEM3>>>(
        xh, xl, wqkv, qp, kp, vf);

    // RoPE + split to bf16 hi/lo
    const int rthreads = BATCH * SEQ * (DHEAD / 2);
    rope_split_kernel<<<(rthreads + 255) / 256, 256>>>(qp, qh, ql, NHEADS);
    rope_split_kernel<<<(rthreads + 255) / 256, 256>>>(kp, kh, kl, NKV);

    // flash attention
    hmma_attn_kernel<<<dim3(SEQ / 128, NHEADS, BATCH), 256, AT_SMEM>>>(tp);

    // output projection
    oproj_gemm_kernel<<<dim3(DMODEL / 128, MTOT / 128), 256, GSMEM3>>>(
        ofh, ofl, wof, out);
}

// round 7
// speedup vs baseline: 5.0668x; 1.0726x over previous
#include <cuda_runtime.h>
#include <cuda_bf16.h>
#include <cuda_fp16.h>
#include <math.h>
#include <stdint.h>

#define BATCH   4
#define SEQ     2048
#define DMODEL  2048
#define NHEADS  16
#define NKV     4
#define DHEAD   128
#define MTOT    (BATCH * SEQ)          // 8192
#define NKVD    (NKV * DHEAD)          // 512
#define NQKV    (DMODEL + 2 * NKVD)    // 3072

// ---------------- scratch ----------
__device__ __half g_qh[MTOT * DMODEL], g_ql[MTOT * DMODEL];  // roped Q hi/lo f16
__device__ __half g_kf[MTOT * NKVD];                         // roped K f16
__device__ __half g_vf[MTOT * NKVD];                         // V f16

__device__ __half g_xh[MTOT * DMODEL], g_xl[MTOT * DMODEL];  // x hi/lo f16
__device__ __half g_ofh[MTOT * DMODEL], g_ofl[MTOT * DMODEL];// attn out hi/lo f16
__device__ __half g_wqkv[NQKV * DMODEL];                     // [Wq;Wk;Wv]^T f16
__device__ __half g_wof[DMODEL * DMODEL];

__device__ float g_ropec[SEQ * 64], g_ropes[SEQ * 64];

// ---------------- helpers ---------------------------------------------
__device__ __forceinline__ uint32_t smem_u32(const void* p) {
    uint32_t a;
    asm("{ .reg .u64 t; cvta.to.shared.u64 t, %1; cvt.u32.u64 %0, t; }"
        : "=r"(a) : "l"(p));
    return a;
}
#define SWZ128(o) ((o) ^ (((o) >> 3) & 0x70))

__device__ __forceinline__ void ldsm4(uint32_t& r0, uint32_t& r1,
                                      uint32_t& r2, uint32_t& r3, uint32_t addr) {
    asm volatile("ldmatrix.sync.aligned.m8n8.x4.shared.b16 {%0,%1,%2,%3}, [%4];"
                 : "=r"(r0), "=r"(r1), "=r"(r2), "=r"(r3) : "r"(addr));
}
__device__ __forceinline__ void ldsm4t(uint32_t& r0, uint32_t& r1,
                                       uint32_t& r2, uint32_t& r3, uint32_t addr) {
    asm volatile("ldmatrix.sync.aligned.m8n8.x4.trans.shared.b16 {%0,%1,%2,%3}, [%4];"
                 : "=r"(r0), "=r"(r1), "=r"(r2), "=r"(r3) : "r"(addr));
}
__device__ __forceinline__ void mma16816h(float* c, uint32_t a0, uint32_t a1,
                                          uint32_t a2, uint32_t a3,
                                          uint32_t b0, uint32_t b1) {
    asm volatile(
        "mma.sync.aligned.m16n8k16.row.col.f32.f16.f16.f32 "
        "{%0,%1,%2,%3},{%4,%5,%6,%7},{%8,%9},{%0,%1,%2,%3};"
        : "+f"(c[0]), "+f"(c[1]), "+f"(c[2]), "+f"(c[3])
        : "r"(a0), "r"(a1), "r"(a2), "r"(a3), "r"(b0), "r"(b1));
}
__device__ __forceinline__ uint32_t packf16(float hi, float lo) {
    uint32_t r;
    asm("cvt.rn.f16x2.f32 %0, %1, %2;" : "=r"(r) : "f"(hi), "f"(lo));
    return r;
}
__device__ __forceinline__ uint32_t exp2_f16x2(uint32_t x) {
    uint32_t r;
    asm("ex2.approx.f16x2 %0, %1;" : "=r"(r) : "r"(x));
    return r;
}

// ---------------------------------------------------------------------------
// fp16 2-product GEMM core (3-stage cp.async)
// ---------------------------------------------------------------------------
#define GKC      64
#define GK       2048
#define GNITER   (GK / GKC)               // 32
#define TILEB    16384                    // 128 rows x 128B
#define STAGEB   (3 * TILEB)
#define GSMEM3   (3 * STAGEB)             // 147456

__device__ __forceinline__ void gemm_issue(
    uint32_t sb, int stage, int it,
    const __half* __restrict__ Ah, const __half* __restrict__ Al,
    const __half* __restrict__ Bf, int m0, int n0, int tid)
{
    const int k0 = it * GKC;
    const __half* srcs[3] = { Ah, Al, Bf };
#pragma unroll
    for (int mtx = 0; mtx < 3; mtx++) {
        const __half* src = srcs[mtx];
        const int rowbase = (mtx < 2) ? m0 : n0;
        const uint32_t smb = sb + stage * STAGEB + mtx * TILEB;
#pragma unroll
        for (int j = 0; j < 4; j++) {
            int chunk = tid + j * 256;
            int row = chunk >> 3;
            int c16 = chunk & 7;
            const void* gp = src + (size_t)(rowbase + row) * GK + k0 + c16 * 8;
            uint32_t sp = smb + SWZ128(row * 128 + c16 * 16);
            asm volatile("cp.async.cg.shared.global [%0], [%1], 16;"
                         :: "r"(sp), "l"(gp));
        }
    }
    asm volatile("cp.async.commit_group;" ::: "memory");
}

__device__ __forceinline__ void gemm_mainloop(
    uint32_t sb, const __half* __restrict__ Ah, const __half* __restrict__ Al,
    const __half* __restrict__ Bf, int m0, int n0, int tid,
    float acc[4][4][4])
{
    const int wid = tid >> 5, l = tid & 31;
    const int wm = wid >> 2, wn = wid & 3;
    const int a_row_l = (l & 7) + (l & 8);
    const int a_col_l = ((l >> 4) & 1) * 16;
    const int b_row_l = (l & 7) + ((l >> 4) & 1) * 8;
    const int b_col_l = ((l >> 3) & 1) * 16;

    gemm_issue(sb, 0, 0, Ah, Al, Bf, m0, n0, tid);
    gemm_issue(sb, 1, 1, Ah, Al, Bf, m0, n0, tid);

    for (int it = 0; it < GNITER; it++) {
        if (it + 1 < GNITER) {
            asm volatile("cp.async.wait_group 1;" ::: "memory");
        } else {
            asm volatile("cp.async.wait_group 0;" ::: "memory");
        }
        __syncthreads();
        if (it + 2 < GNITER)
            gemm_issue(sb, (it + 2) % 3, it + 2, Ah, Al, Bf, m0, n0, tid);

        const uint32_t stg = sb + (it % 3) * STAGEB;
        const uint32_t sAh = stg;
        const uint32_t sAl = stg + TILEB;
        const uint32_t sBf = stg + 2 * TILEB;

#pragma unroll
        for (int kk = 0; kk < 4; kk++) {
            const int kb = kk * 32;
            uint32_t ah[4][4], al[4][4], bf4[8];
#pragma unroll
            for (int mt = 0; mt < 4; mt++) {
                int row = wm * 64 + mt * 16 + a_row_l;
                uint32_t off = SWZ128(row * 128 + kb + a_col_l);
                ldsm4(ah[mt][0], ah[mt][1], ah[mt][2], ah[mt][3], sAh + off);
                ldsm4(al[mt][0], al[mt][1], al[mt][2], al[mt][3], sAl + off);
            }
#pragma unroll
            for (int nt2 = 0; nt2 < 2; nt2++) {
                int row = wn * 32 + nt2 * 16 + b_row_l;
                uint32_t off = SWZ128(row * 128 + kb + b_col_l);
                ldsm4(bf4[nt2 * 4 + 0], bf4[nt2 * 4 + 1],
                      bf4[nt2 * 4 + 2], bf4[nt2 * 4 + 3], sBf + off);
            }
#pragma unroll
            for (int mt = 0; mt < 4; mt++)
#pragma unroll
                for (int nt = 0; nt < 4; nt++) {
                    uint32_t b0 = bf4[(nt >> 1) * 4 + (nt & 1) * 2];
                    uint32_t b1 = bf4[(nt >> 1) * 4 + (nt & 1) * 2 + 1];
                    mma16816h(acc[mt][nt], ah[mt][0], ah[mt][1], ah[mt][2], ah[mt][3], b0, b1);
                    mma16816h(acc[mt][nt], al[mt][0], al[mt][1], al[mt][2], al[mt][3], b0, b1);
                }
        }
    }
}

// Fused QKV projection + RoPE.
// cols [0,2048): Q -> rope -> f16 hi/lo; [2048,2560): K -> rope -> f16;
// [2560,3072): V -> f16.
#define SROW 136   // fp32 staging row stride
__global__ __launch_bounds__(256) void qkv_gemm_kernel(
    const __half* __restrict__ xh, const __half* __restrict__ xl,
    const __half* __restrict__ wqkv)
{
    extern __shared__ char smem[];
    const uint32_t sb = smem_u32(smem);
    const int tid = threadIdx.x, wid = tid >> 5, l = tid & 31;
    const int wm = wid >> 2, wn = wid & 3;
    const int m0 = blockIdx.y * 128;
    const int n0 = blockIdx.x * 128;

    float acc[4][4][4];
#pragma unroll
    for (int i = 0; i < 4; i++)
#pragma unroll
        for (int j = 0; j < 4; j++)
#pragma unroll
            for (int f = 0; f < 4; f++) acc[i][j][f] = 0.f;

    gemm_mainloop(sb, xh, xl, wqkv, m0, n0, tid, acc);

    if (n0 >= DMODEL + NKVD) {
        // V: direct f16 store
        int nb = n0 - DMODEL - NKVD;
#pragma unroll
        for (int mt = 0; mt < 4; mt++) {
            int r0 = m0 + wm * 64 + mt * 16 + (l >> 2);
#pragma unroll
            for (int nt = 0; nt < 4; nt++) {
                int c = nb + wn * 32 + nt * 8 + (l & 3) * 2;
                *(__half2*)(g_vf + (size_t)r0 * NKVD + c) =
                    __floats2half2_rn(acc[mt][nt][0], acc[mt][nt][1]);
                *(__half2*)(g_vf + (size_t)(r0 + 8) * NKVD + c) =
                    __floats2half2_rn(acc[mt][nt][2], acc[mt][nt][3]);
            }
        }
        return;
    }

    // Q or K: stage fp32 tile in smem, apply RoPE, convert, store
    float* sst = (float*)smem;
    __syncthreads();   // mainloop smem no longer needed
#pragma unroll
    for (int mt = 0; mt < 4; mt++) {
        int r0 = wm * 64 + mt * 16 + (l >> 2);
#pragma unroll
        for (int nt = 0; nt < 4; nt++) {
            int c = wn * 32 + nt * 8 + (l & 3) * 2;
            *(float2*)&sst[r0 * SROW + c] = make_float2(acc[mt][nt][0], acc[mt][nt][1]);
            *(float2*)&sst[(r0 + 8) * SROW + c] = make_float2(acc[mt][nt][2], acc[mt][nt][3]);
        }
    }
    __syncthreads();

    const bool isQ = (n0 < DMODEL);
#pragma unroll
    for (int j = 0; j < 4; j++) {
        int rl = (tid >> 3) + j * 32;
        int c8 = (tid & 7) * 8;
        int grow = m0 + rl;
        int s = grow & (SEQ - 1);
        float x1[8], x2[8];
        *(float4*)(x1)     = *(float4*)&sst[rl * SROW + c8];
        *(float4*)(x1 + 4) = *(float4*)&sst[rl * SROW + c8 + 4];
        *(float4*)(x2)     = *(float4*)&sst[rl * SROW + c8 + 64];
        *(float4*)(x2 + 4) = *(float4*)&sst[rl * SROW + c8 + 68];
        const float* tc = g_ropec + s * 64 + c8;
        const float* ts = g_ropes + s * 64 + c8;
        float y1[8], y2[8];
#pragma unroll
        for (int u = 0; u < 8; u++) {
            float c = tc[u], sn = ts[u];
            y1[u] = x1[u] * c - x2[u] * sn;
            y2[u] = x2[u] * c + x1[u] * sn;
        }
        if (isQ) {
            __half h1[8], h2[8], lo1[8], lo2[8];
#pragma unroll
            for (int u = 0; u < 8; u++) {
                h1[u] = __float2half(y1[u]);
                lo1[u] = __float2half(y1[u] - __half2float(h1[u]));
                h2[u] = __float2half(y2[u]);
                lo2[u] = __float2half(y2[u] - __half2float(h2[u]));
            }
            size_t base = (size_t)grow * DMODEL + n0 + c8;
            *(uint4*)(g_qh + base)      = *(uint4*)h1;
            *(uint4*)(g_qh + base + 64) = *(uint4*)h2;
            *(uint4*)(g_ql + base)      = *(uint4*)lo1;
            *(uint4*)(g_ql + base + 64) = *(uint4*)lo2;
        } else {
            __half h1[8], h2[8];
#pragma unroll
            for (int u = 0; u < 8; u++) {
                h1[u] = __float2half(y1[u]);
                h2[u] = __float2half(y2[u]);
            }
            size_t base = (size_t)grow * NKVD + (n0 - DMODEL) + c8;
            *(uint4*)(g_kf + base)      = *(uint4*)h1;
            *(uint4*)(g_kf + base + 64) = *(uint4*)h2;
        }
    }
}

// Output projection: N = 2048, fp32 out
__global__ __launch_bounds__(256) void oproj_gemm_kernel(
    const __half* __restrict__ Ah, const __half* __restrict__ Al,
    const __half* __restrict__ Bf, float* __restrict__ C)
{
    extern __shared__ char smem[];
    const uint32_t sb = smem_u32(smem);
    const int tid = threadIdx.x, wid = tid >> 5, l = tid & 31;
    const int wm = wid >> 2, wn = wid & 3;
    const int m0 = blockIdx.y * 128;
    const int n0 = blockIdx.x * 128;

    float acc[4][4][4];
#pragma unroll
    for (int i = 0; i < 4; i++)
#pragma unroll
        for (int j = 0; j < 4; j++)
#pragma unroll
            for (int f = 0; f < 4; f++) acc[i][j][f] = 0.f;

    gemm_mainloop(sb, Ah, Al, Bf, m0, n0, tid, acc);

#pragma unroll
    for (int mt = 0; mt < 4; mt++) {
        int r0 = m0 + wm * 64 + mt * 16 + (l >> 2);
#pragma unroll
        for (int nt = 0; nt < 4; nt++) {
            int c = n0 + wn * 32 + nt * 8 + (l & 3) * 2;
            *(float2*)(C + (size_t)r0 * DMODEL + c) =
                make_float2(acc[mt][nt][0], acc[mt][nt][1]);
            *(float2*)(C + (size_t)(r0 + 8) * DMODEL + c) =
                make_float2(acc[mt][nt][2], acc[mt][nt][3]);
        }
    }
}

// ---------------------------------------------------------------------------
// elementwise converters
// ---------------------------------------------------------------------------
__global__ void split16_kernel(const float4* __restrict__ in,
                               uint2* __restrict__ hi, uint2* __restrict__ lo, int n4)
{
    int i = blockIdx.x * blockDim.x + threadIdx.x;
    if (i >= n4) return;
    float4 v = in[i];
    __half h[4], lw[4];
    float x[4] = { v.x, v.y, v.z, v.w };
#pragma unroll
    for (int j = 0; j < 4; j++) {
        h[j] = __float2half(x[j]);
        lw[j] = __float2half(x[j] - __half2float(h[j]));
    }
    hi[i] = *(uint2*)h;
    lo[i] = *(uint2*)lw;
}

// weight transpose: w[K,N] fp32 -> tf[N,K] f16
__global__ void tconv_kernel(const float* __restrict__ w,
                             __half* __restrict__ tf, int Kd, int Nd)
{
    __shared__ float tile[32][33];
    int n0 = blockIdx.x * 32, k0 = blockIdx.y * 32;
    int tx = threadIdx.x, ty = threadIdx.y;
#pragma unroll
    for (int j = 0; j < 32; j += 8)
        tile[ty + j][tx] = w[(size_t)(k0 + ty + j) * Nd + n0 + tx];
    __syncthreads();
#pragma unroll
    for (int j = 0; j < 32; j += 8) {
        float x = tile[tx][ty + j];
        tf[(size_t)(n0 + ty + j) * Kd + k0 + tx] = __float2half(x);
    }
}

// RoPE table precompute (fp64 trig)
__global__ void rope_table_kernel()
{
    int idx = blockIdx.x * blockDim.x + threadIdx.x;
    if (idx >= SEQ * 64) return;
    int i = idx & 63, s = idx >> 6;
    double inv = exp(-0.14391156831212787 * (double)i);
    double sd, cd;
    sincos((double)s * inv, &sd, &cd);
    g_ropec[idx] = (float)cd;
    g_ropes[idx] = (float)sd;
}

// ---------------------------------------------------------------------------
// HMMA flash attention: Q f16 hi/lo, K single f16 (2-product QK), V f16.
// 3-stage KV pipeline, stage = {Kf 16KB, V 16KB}.
// ---------------------------------------------------------------------------
#define AT_STAGE0 65536
#define AT_STAGEB 32768
#define AT_SMEM   (AT_STAGE0 + 3 * AT_STAGEB)   // 163840

__device__ __forceinline__ void attn_issue_kv(
    uint32_t stbase, const __half* kfg, const __half* vg, int k0, int tid)
{
    const char* bases[2] = { (const char*)kfg, (const char*)vg };
#pragma unroll
    for (int arr = 0; arr < 2; arr++) {
        const char* base = bases[arr];
        uint32_t soff = stbase + arr * 16384;
#pragma unroll
        for (int i = 0; i < 4; i++) {
            int chunk = tid + i * 256;
            int row = chunk >> 4, cc = chunk & 15;
            const void* gp = base + ((size_t)(k0 + row) * NKVD + cc * 8) * 2;
            uint32_t sp = soff + (cc >> 3) * 8192 + SWZ128(row * 128 + (cc & 7) * 16);
            asm volatile("cp.async.cg.shared.global [%0], [%1], 16;"
                         :: "r"(sp), "l"(gp));
        }
    }
    asm volatile("cp.async.commit_group;" ::: "memory");
}

__global__ __launch_bounds__(256, 1) void hmma_attn_kernel(const float* __restrict__ tptr)
{
    extern __shared__ char smem[];
    const uint32_t sb = smem_u32(smem);
    const int tid = threadIdx.x, w = tid >> 5, l = tid & 31;
    const int qt = blockIdx.x, h = blockIdx.y, b = blockIdx.z;
    const int kv = h >> 2;
    const int q0 = qt * 128;
    const int qw0 = q0 + w * 16;
    const float scale = 0.08838834764831845f / fmaxf(fabsf(tptr[0]), 1e-6f);
    const float sl = scale * 1.4426950408889634f;

    const uint32_t sQh = sb, sQl = sb + 32768;

    const __half* qhg = g_qh + ((size_t)(b * SEQ) + q0) * DMODEL + h * DHEAD;
    const __half* qlg = g_ql + ((size_t)(b * SEQ) + q0) * DMODEL + h * DHEAD;
    const __half* kfg = g_kf + (size_t)(b * SEQ) * NKVD + kv * DHEAD;
    const __half* vg  = g_vf + (size_t)(b * SEQ) * NKVD + kv * DHEAD;

    const int nkt = 2 * qt + 2;

    // prologue: group0 = Q + kv0, group1 = kv1
    {
        const char* qb2[2] = { (const char*)qhg, (const char*)qlg };
#pragma unroll
        for (int arr = 0; arr < 2; arr++) {
            uint32_t soff = (arr == 0) ? sQh : sQl;
#pragma unroll
            for (int i = 0; i < 8; i++) {
                int chunk = tid + i * 256;
                int row = chunk >> 4, cc = chunk & 15;
                const void* gp = qb2[arr] + ((size_t)row * DMODEL + cc * 8) * 2;
                uint32_t sp = soff + (cc >> 3) * 16384 + SWZ128(row * 128 + (cc & 7) * 16);
                asm volatile("cp.async.cg.shared.global [%0], [%1], 16;"
                             :: "r"(sp), "l"(gp));
            }
        }
        attn_issue_kv(sb + AT_STAGE0, kfg, vg, 0, tid);                  // group 0
        attn_issue_kv(sb + AT_STAGE0 + AT_STAGEB, kfg, vg, 64, tid);     // group 1
    }

    const int a_row_l = (l & 7) + (l & 8);
    const int a_col_l = ((l >> 4) & 1) * 16;
    const int b_row_l = (l & 7) + ((l >> 4) & 1) * 8;
    const int b_col_l = ((l >> 3) & 1) * 16;
    const int v_row_l = (l & 7) + ((l >> 3) & 1) * 8;
    const int v_col_l = ((l >> 4) & 1) * 16;

    float oacc[16][4];
    float lacc[4] = {0.f, 0.f, 0.f, 0.f};
#pragma unroll
    for (int i = 0; i < 16; i++)
#pragma unroll
        for (int f = 0; f < 4; f++) oacc[i][f] = 0.f;
    float m0 = -3.0e38f, m1 = -3.0e38f;

    for (int kt = 0; kt < nkt; kt++) {
        if (kt + 1 < nkt) {
            asm volatile("cp.async.wait_group 1;" ::: "memory");
        } else {
            asm volatile("cp.async.wait_group 0;" ::: "memory");
        }
        __syncthreads();
        if (kt + 2 < nkt)
            attn_issue_kv(sb + AT_STAGE0 + ((kt + 2) % 3) * AT_STAGEB,
                          kfg, vg, (kt + 2) * 64, tid);

        const int k0 = kt * 64;
        const uint32_t st = sb + AT_STAGE0 + (kt % 3) * AT_STAGEB;

        if (k0 <= qw0 + 15) {
            float sacc[8][4];
#pragma unroll
            for (int i = 0; i < 8; i++)
#pragma unroll
                for (int f = 0; f < 4; f++) sacc[i][f] = 0.f;

#pragma unroll
            for (int ks = 0; ks < 8; ks++) {
                uint32_t qoff = (ks >> 2) * 16384 +
                    SWZ128((w * 16 + a_row_l) * 128 + (ks & 3) * 32 + a_col_l);
                uint32_t qa[4], qb_[4];
                ldsm4(qa[0], qa[1], qa[2], qa[3], sQh + qoff);
                ldsm4(qb_[0], qb_[1], qb_[2], qb_[3], sQl + qoff);
#pragma unroll
                for (int np = 0; np < 4; np++) {
                    uint32_t koff = st + (ks >> 2) * 8192 +
                        SWZ128((np * 16 + b_row_l) * 128 + (ks & 3) * 32 + b_col_l);
                    uint32_t kf4[4];
                    ldsm4(kf4[0], kf4[1], kf4[2], kf4[3], koff);
                    mma16816h(sacc[2 * np],     qa[0], qa[1], qa[2], qa[3], kf4[0], kf4[1]);
                    mma16816h(sacc[2 * np],     qb_[0], qb_[1], qb_[2], qb_[3], kf4[0], kf4[1]);
                    mma16816h(sacc[2 * np + 1], qa[0], qa[1], qa[2], qa[3], kf4[2], kf4[3]);
                    mma16816h(sacc[2 * np + 1], qb_[0], qb_[1], qb_[2], qb_[3], kf4[2], kf4[3]);
                }
            }

            if (k0 + 63 > qw0) {
                int qa0 = qw0 + (l >> 2), qa1 = qa0 + 8;
                int kc0 = k0 + 2 * (l & 3);
#pragma unroll
                for (int nt = 0; nt < 8; nt++) {
                    int kc = kc0 + nt * 8;
                    if (kc     > qa0) sacc[nt][0] = -3.0e38f;
                    if (kc + 1 > qa0) sacc[nt][1] = -3.0e38f;
                    if (kc     > qa1) sacc[nt][2] = -3.0e38f;
                    if (kc + 1 > qa1) sacc[nt][3] = -3.0e38f;
                }
            }

            float mx0 = -3.0e38f, mx1 = -3.0e38f;
#pragma unroll
            for (int nt = 0; nt < 8; nt++) {
                mx0 = fmaxf(mx0, fmaxf(sacc[nt][0], sacc[nt][1]));
                mx1 = fmaxf(mx1, fmaxf(sacc[nt][2], sacc[nt][3]));
            }
            mx0 = fmaxf(mx0, __shfl_xor_sync(0xffffffffu, mx0, 1));
            mx0 = fmaxf(mx0, __shfl_xor_sync(0xffffffffu, mx0, 2));
            mx1 = fmaxf(mx1, __shfl_xor_sync(0xffffffffu, mx1, 1));
            mx1 = fmaxf(mx1, __shfl_xor_sync(0xffffffffu, mx1, 2));
            float mn0 = fmaxf(m0, mx0), mn1 = fmaxf(m1, mx1);
            bool ch = (mn0 > m0) || (mn1 > m1);
            if (__any_sync(0xffffffffu, ch)) {
                float a0 = exp2f((m0 - mn0) * sl);
                float a1 = exp2f((m1 - mn1) * sl);
#pragma unroll
                for (int nt = 0; nt < 16; nt++) {
                    oacc[nt][0] *= a0; oacc[nt][1] *= a0;
                    oacc[nt][2] *= a1; oacc[nt][3] *= a1;
                }
                lacc[0] *= a0; lacc[1] *= a0; lacc[2] *= a1; lacc[3] *= a1;
            }
            m0 = mn0; m1 = mn1;
            const float bb0 = mn0 * sl, bb1 = mn1 * sl;

            uint32_t pp[8][2];
#pragma unroll
            for (int nt = 0; nt < 8; nt++) {
                float t0 = fmaf(sacc[nt][0], sl, -bb0);
                float t1 = fmaf(sacc[nt][1], sl, -bb0);
                float t2 = fmaf(sacc[nt][2], sl, -bb1);
                float t3 = fmaf(sacc[nt][3], sl, -bb1);
                pp[nt][0] = exp2_f16x2(packf16(t1, t0));
                pp[nt][1] = exp2_f16x2(packf16(t3, t2));
            }

#pragma unroll
            for (int ks = 0; ks < 4; ks++) {
                uint32_t pa0 = pp[2 * ks][0], pa1 = pp[2 * ks][1];
                uint32_t pa2 = pp[2 * ks + 1][0], pa3 = pp[2 * ks + 1][1];
                mma16816h(lacc, pa0, pa1, pa2, pa3, 0x3C003C00u, 0x3C003C00u);
#pragma unroll
                for (int jp = 0; jp < 8; jp++) {
                    uint32_t voff = st + 16384 + (jp >> 2) * 8192 +
                        SWZ128((ks * 16 + v_row_l) * 128 + (jp & 3) * 32 + v_col_l);
                    uint32_t v4[4];
                    ldsm4t(v4[0], v4[1], v4[2], v4[3], voff);
                    mma16816h(oacc[2 * jp],     pa0, pa1, pa2, pa3, v4[0], v4[1]);
                    mma16816h(oacc[2 * jp + 1], pa0, pa1, pa2, pa3, v4[2], v4[3]);
                }
            }
        }
    }

    // epilogue: normalize + f16 hi/lo split store
    const float inv0 = 1.0f / lacc[0];
    const float inv1 = 1.0f / lacc[2];
    const size_t r0g = (size_t)(b * SEQ) + qw0 + (l >> 2);
    const size_t r1g = r0g + 8;
#pragma unroll
    for (int nt = 0; nt < 16; nt++) {
        int col = h * DHEAD + nt * 8 + 2 * (l & 3);
        float v0 = oacc[nt][0] * inv0, v1 = oacc[nt][1] * inv0;
        float v2 = oacc[nt][2] * inv1, v3 = oacc[nt][3] * inv1;
        __half h0 = __float2half(v0), h1 = __float2half(v1);
        __half h2 = __float2half(v2), h3 = __float2half(v3);
        __half2 hp0; hp0.x = h0; hp0.y = h1;
        __half2 hp1; hp1.x = h2; hp1.y = h3;
        __half2 lp0;
        lp0.x = __float2half(v0 - __half2float(h0));
        lp0.y = __float2half(v1 - __half2float(h1));
        __half2 lp1;
        lp1.x = __float2half(v2 - __half2float(h2));
        lp1.y = __float2half(v3 - __half2float(h3));
        *(__half2*)(g_ofh + r0g * DMODEL + col) = hp0;
        *(__half2*)(g_ofl + r0g * DMODEL + col) = lp0;
        *(__half2*)(g_ofh + r1g * DMODEL + col) = hp1;
        *(__half2*)(g_ofl + r1g * DMODEL + col) = lp1;
    }
}

// ---------------------------------------------------------------------------
extern "C" void kernel_launch(void* const* d_in, const int* in_sizes, int n_in,
                              void* d_out, int out_size)
{
    const float* x  = (const float*)d_in[0];
    const float* wq = (const float*)d_in[1];
    const float* wk = (const float*)d_in[2];
    const float* wv = (const float*)d_in[3];
    const float* wo = (const float*)d_in[4];
    const float* tp = (const float*)d_in[5];
    float* out = (float*)d_out;

    __half *xh, *xl, *ofh, *ofl, *wqkv, *wof;
    cudaGetSymbolAddress((void**)&xh, g_xh);   cudaGetSymbolAddress((void**)&xl, g_xl);
    cudaGetSymbolAddress((void**)&ofh, g_ofh); cudaGetSymbolAddress((void**)&ofl, g_ofl);
    cudaGetSymbolAddress((void**)&wqkv, g_wqkv);
    cudaGetSymbolAddress((void**)&wof, g_wof);

    cudaFuncSetAttribute(qkv_gemm_kernel, cudaFuncAttributeMaxDynamicSharedMemorySize, GSMEM3);
    cudaFuncSetAttribute(oproj_gemm_kernel, cudaFuncAttributeMaxDynamicSharedMemorySize, GSMEM3);
    cudaFuncSetAttribute(hmma_attn_kernel, cudaFuncAttributeMaxDynamicSharedMemorySize, AT_SMEM);

    // converters + rope table
    rope_table_kernel<<<(SEQ * 64 + 255) / 256, 256>>>();
    {
        int n4 = MTOT * DMODEL / 4;
        split16_kernel<<<(n4 + 255) / 256, 256>>>((const float4*)x, (uint2*)xh, (uint2*)xl, n4);
        tconv_kernel<<<dim3(DMODEL / 32, DMODEL / 32), dim3(32, 8)>>>(wq, wqkv, DMODEL, DMODEL);
        tconv_kernel<<<dim3(NKVD / 32, DMODEL / 32), dim3(32, 8)>>>(
            wk, wqkv + (size_t)DMODEL * DMODEL, DMODEL, NKVD);
        tconv_kernel<<<dim3(NKVD / 32, DMODEL / 32), dim3(32, 8)>>>(
            wv, wqkv + (size_t)(DMODEL + NKVD) * DMODEL, DMODEL, NKVD);
        tconv_kernel<<<dim3(DMODEL / 32, DMODEL / 32), dim3(32, 8)>>>(wo, wof, DMODEL, DMODEL);
    }

    // fused QKV projection + RoPE (Q/K roped f16 out, V f16 out)
    qkv_gemm_kernel<<<dim3(NQKV / 128, MTOT / 128), 256, GSMEM3>>>(xh, xl, wqkv);

    // flash attention
    hmma_attn_kernel<<<dim3(SEQ / 128, NHEADS, BATCH), 256, AT_SMEM>>>(tp);

    // output projection
    oproj_gemm_kernel<<<dim3(DMODEL / 128, MTOT / 128), 256, GSMEM3>>>(
        ofh, ofl, wof, out);
}

// round 8
// speedup vs baseline: 7.7835x; 1.5362x over previous
#include <cuda_runtime.h>
#include <cuda_bf16.h>
#include <cuda_fp16.h>
#include <math.h>
#include <stdint.h>

#define BATCH   4
#define SEQ     2048
#define DMODEL  2048
#define NHEADS  16
#define NKV     4
#define DHEAD   128
#define MTOT    (BATCH * SEQ)          // 8192
#define NKVD    (NKV * DHEAD)          // 512
#define NQKV    (DMODEL + 2 * NKVD)    // 3072

// ---------------- scratch ----------
__device__ __half g_qh[MTOT * DMODEL], g_ql[MTOT * DMODEL];  // roped Q hi/lo f16
__device__ __half g_kf[MTOT * NKVD];                         // roped K f16
__device__ __half g_vf[MTOT * NKVD];                         // V f16

__device__ __half g_xf[MTOT * DMODEL];                       // x f16
__device__ __half g_of[MTOT * DMODEL];                       // attn out f16
__device__ __half g_wqkv[NQKV * DMODEL];                     // [Wq;Wk;Wv]^T f16
__device__ __half g_wof[DMODEL * DMODEL];

__device__ float g_ropec[SEQ * 64], g_ropes[SEQ * 64];

// ---------------- helpers ---------------------------------------------
__device__ __forceinline__ uint32_t smem_u32(const void* p) {
    uint32_t a;
    asm("{ .reg .u64 t; cvta.to.shared.u64 t, %1; cvt.u32.u64 %0, t; }"
        : "=r"(a) : "l"(p));
    return a;
}
#define SWZ128(o) ((o) ^ (((o) >> 3) & 0x70))

__device__ __forceinline__ void ldsm4(uint32_t& r0, uint32_t& r1,
                                      uint32_t& r2, uint32_t& r3, uint32_t addr) {
    asm volatile("ldmatrix.sync.aligned.m8n8.x4.shared.b16 {%0,%1,%2,%3}, [%4];"
                 : "=r"(r0), "=r"(r1), "=r"(r2), "=r"(r3) : "r"(addr));
}
__device__ __forceinline__ void ldsm4t(uint32_t& r0, uint32_t& r1,
                                       uint32_t& r2, uint32_t& r3, uint32_t addr) {
    asm volatile("ldmatrix.sync.aligned.m8n8.x4.trans.shared.b16 {%0,%1,%2,%3}, [%4];"
                 : "=r"(r0), "=r"(r1), "=r"(r2), "=r"(r3) : "r"(addr));
}
__device__ __forceinline__ void mma16816h(float* c, uint32_t a0, uint32_t a1,
                                          uint32_t a2, uint32_t a3,
                                          uint32_t b0, uint32_t b1) {
    asm volatile(
        "mma.sync.aligned.m16n8k16.row.col.f32.f16.f16.f32 "
        "{%0,%1,%2,%3},{%4,%5,%6,%7},{%8,%9},{%0,%1,%2,%3};"
        : "+f"(c[0]), "+f"(c[1]), "+f"(c[2]), "+f"(c[3])
        : "r"(a0), "r"(a1), "r"(a2), "r"(a3), "r"(b0), "r"(b1));
}
__device__ __forceinline__ uint32_t packf16(float hi, float lo) {
    uint32_t r;
    asm("cvt.rn.f16x2.f32 %0, %1, %2;" : "=r"(r) : "f"(hi), "f"(lo));
    return r;
}
__device__ __forceinline__ uint32_t exp2_f16x2(uint32_t x) {
    uint32_t r;
    asm("ex2.approx.f16x2 %0, %1;" : "=r"(r) : "r"(x));
    return r;
}

// ---------------------------------------------------------------------------
// fp16 single-product GEMM core: C[M,N] = Af[M,K] @ Bf[N,K]^T, fp32 accum.
// CTA 128x128, 8 warps, warp 64x32, BK=64, 3-stage cp.async pipeline.
// ---------------------------------------------------------------------------
#define GKC      64
#define GK       2048
#define GNITER   (GK / GKC)               // 32
#define TILEB    16384                    // 128 rows x 128B
#define STAGEB   (2 * TILEB)              // Af, Bf
#define GSMEM3   (3 * STAGEB)             // 98304

__device__ __forceinline__ void gemm_issue(
    uint32_t sb, int stage, int it,
    const __half* __restrict__ Af, const __half* __restrict__ Bf,
    int m0, int n0, int tid)
{
    const int k0 = it * GKC;
    const __half* srcs[2] = { Af, Bf };
#pragma unroll
    for (int mtx = 0; mtx < 2; mtx++) {
        const __half* src = srcs[mtx];
        const int rowbase = (mtx == 0) ? m0 : n0;
        const uint32_t smb = sb + stage * STAGEB + mtx * TILEB;
#pragma unroll
        for (int j = 0; j < 4; j++) {
            int chunk = tid + j * 256;
            int row = chunk >> 3;
            int c16 = chunk & 7;
            const void* gp = src + (size_t)(rowbase + row) * GK + k0 + c16 * 8;
            uint32_t sp = smb + SWZ128(row * 128 + c16 * 16);
            asm volatile("cp.async.cg.shared.global [%0], [%1], 16;"
                         :: "r"(sp), "l"(gp));
        }
    }
    asm volatile("cp.async.commit_group;" ::: "memory");
}

__device__ __forceinline__ void gemm_mainloop(
    uint32_t sb, const __half* __restrict__ Af, const __half* __restrict__ Bf,
    int m0, int n0, int tid, float acc[4][4][4])
{
    const int wid = tid >> 5, l = tid & 31;
    const int wm = wid >> 2, wn = wid & 3;
    const int a_row_l = (l & 7) + (l & 8);
    const int a_col_l = ((l >> 4) & 1) * 16;
    const int b_row_l = (l & 7) + ((l >> 4) & 1) * 8;
    const int b_col_l = ((l >> 3) & 1) * 16;

    gemm_issue(sb, 0, 0, Af, Bf, m0, n0, tid);
    gemm_issue(sb, 1, 1, Af, Bf, m0, n0, tid);

    for (int it = 0; it < GNITER; it++) {
        if (it + 1 < GNITER) {
            asm volatile("cp.async.wait_group 1;" ::: "memory");
        } else {
            asm volatile("cp.async.wait_group 0;" ::: "memory");
        }
        __syncthreads();
        if (it + 2 < GNITER)
            gemm_issue(sb, (it + 2) % 3, it + 2, Af, Bf, m0, n0, tid);

        const uint32_t stg = sb + (it % 3) * STAGEB;
        const uint32_t sAf = stg;
        const uint32_t sBf = stg + TILEB;

#pragma unroll
        for (int kk = 0; kk < 4; kk++) {
            const int kb = kk * 32;
            uint32_t af4[4][4], bf4[8];
#pragma unroll
            for (int mt = 0; mt < 4; mt++) {
                int row = wm * 64 + mt * 16 + a_row_l;
                uint32_t off = SWZ128(row * 128 + kb + a_col_l);
                ldsm4(af4[mt][0], af4[mt][1], af4[mt][2], af4[mt][3], sAf + off);
            }
#pragma unroll
            for (int nt2 = 0; nt2 < 2; nt2++) {
                int row = wn * 32 + nt2 * 16 + b_row_l;
                uint32_t off = SWZ128(row * 128 + kb + b_col_l);
                ldsm4(bf4[nt2 * 4 + 0], bf4[nt2 * 4 + 1],
                      bf4[nt2 * 4 + 2], bf4[nt2 * 4 + 3], sBf + off);
            }
#pragma unroll
            for (int mt = 0; mt < 4; mt++)
#pragma unroll
                for (int nt = 0; nt < 4; nt++) {
                    uint32_t b0 = bf4[(nt >> 1) * 4 + (nt & 1) * 2];
                    uint32_t b1 = bf4[(nt >> 1) * 4 + (nt & 1) * 2 + 1];
                    mma16816h(acc[mt][nt], af4[mt][0], af4[mt][1],
                              af4[mt][2], af4[mt][3], b0, b1);
                }
        }
    }
}

// Fused QKV projection + RoPE.
// cols [0,2048): Q -> rope -> f16 hi/lo; [2048,2560): K -> rope -> f16;
// [2560,3072): V -> f16.
#define SROW 136   // fp32 staging row stride
__global__ __launch_bounds__(256) void qkv_gemm_kernel(
    const __half* __restrict__ xf, const __half* __restrict__ wqkv)
{
    extern __shared__ char smem[];
    const uint32_t sb = smem_u32(smem);
    const int tid = threadIdx.x, wid = tid >> 5, l = tid & 31;
    const int wm = wid >> 2, wn = wid & 3;
    const int m0 = blockIdx.y * 128;
    const int n0 = blockIdx.x * 128;

    float acc[4][4][4];
#pragma unroll
    for (int i = 0; i < 4; i++)
#pragma unroll
        for (int j = 0; j < 4; j++)
#pragma unroll
            for (int f = 0; f < 4; f++) acc[i][j][f] = 0.f;

    gemm_mainloop(sb, xf, wqkv, m0, n0, tid, acc);

    if (n0 >= DMODEL + NKVD) {
        // V: direct f16 store
        int nb = n0 - DMODEL - NKVD;
#pragma unroll
        for (int mt = 0; mt < 4; mt++) {
            int r0 = m0 + wm * 64 + mt * 16 + (l >> 2);
#pragma unroll
            for (int nt = 0; nt < 4; nt++) {
                int c = nb + wn * 32 + nt * 8 + (l & 3) * 2;
                *(__half2*)(g_vf + (size_t)r0 * NKVD + c) =
                    __floats2half2_rn(acc[mt][nt][0], acc[mt][nt][1]);
                *(__half2*)(g_vf + (size_t)(r0 + 8) * NKVD + c) =
                    __floats2half2_rn(acc[mt][nt][2], acc[mt][nt][3]);
            }
        }
        return;
    }

    // Q or K: stage fp32 tile in smem, apply RoPE, convert, store
    float* sst = (float*)smem;
    __syncthreads();   // mainloop smem no longer needed
#pragma unroll
    for (int mt = 0; mt < 4; mt++) {
        int r0 = wm * 64 + mt * 16 + (l >> 2);
#pragma unroll
        for (int nt = 0; nt < 4; nt++) {
            int c = wn * 32 + nt * 8 + (l & 3) * 2;
            *(float2*)&sst[r0 * SROW + c] = make_float2(acc[mt][nt][0], acc[mt][nt][1]);
            *(float2*)&sst[(r0 + 8) * SROW + c] = make_float2(acc[mt][nt][2], acc[mt][nt][3]);
        }
    }
    __syncthreads();

    const bool isQ = (n0 < DMODEL);
#pragma unroll
    for (int j = 0; j < 4; j++) {
        int rl = (tid >> 3) + j * 32;
        int c8 = (tid & 7) * 8;
        int grow = m0 + rl;
        int s = grow & (SEQ - 1);
        float x1[8], x2[8];
        *(float4*)(x1)     = *(float4*)&sst[rl * SROW + c8];
        *(float4*)(x1 + 4) = *(float4*)&sst[rl * SROW + c8 + 4];
        *(float4*)(x2)     = *(float4*)&sst[rl * SROW + c8 + 64];
        *(float4*)(x2 + 4) = *(float4*)&sst[rl * SROW + c8 + 68];
        const float* tc = g_ropec + s * 64 + c8;
        const float* ts = g_ropes + s * 64 + c8;
        float y1[8], y2[8];
#pragma unroll
        for (int u = 0; u < 8; u++) {
            float c = tc[u], sn = ts[u];
            y1[u] = x1[u] * c - x2[u] * sn;
            y2[u] = x2[u] * c + x1[u] * sn;
        }
        if (isQ) {
            __half h1[8], h2[8], lo1[8], lo2[8];
#pragma unroll
            for (int u = 0; u < 8; u++) {
                h1[u] = __float2half(y1[u]);
                lo1[u] = __float2half(y1[u] - __half2float(h1[u]));
                h2[u] = __float2half(y2[u]);
                lo2[u] = __float2half(y2[u] - __half2float(h2[u]));
            }
            size_t base = (size_t)grow * DMODEL + n0 + c8;
            *(uint4*)(g_qh + base)      = *(uint4*)h1;
            *(uint4*)(g_qh + base + 64) = *(uint4*)h2;
            *(uint4*)(g_ql + base)      = *(uint4*)lo1;
            *(uint4*)(g_ql + base + 64) = *(uint4*)lo2;
        } else {
            __half h1[8], h2[8];
#pragma unroll
            for (int u = 0; u < 8; u++) {
                h1[u] = __float2half(y1[u]);
                h2[u] = __float2half(y2[u]);
            }
            size_t base = (size_t)grow * NKVD + (n0 - DMODEL) + c8;
            *(uint4*)(g_kf + base)      = *(uint4*)h1;
            *(uint4*)(g_kf + base + 64) = *(uint4*)h2;
        }
    }
}

// Output projection: N = 2048, fp32 out, single-product
__global__ __launch_bounds__(256) void oproj_gemm_kernel(
    const __half* __restrict__ Af, const __half* __restrict__ Bf,
    float* __restrict__ C)
{
    extern __shared__ char smem[];
    const uint32_t sb = smem_u32(smem);
    const int tid = threadIdx.x, wid = tid >> 5, l = tid & 31;
    const int wm = wid >> 2, wn = wid & 3;
    const int m0 = blockIdx.y * 128;
    const int n0 = blockIdx.x * 128;

    float acc[4][4][4];
#pragma unroll
    for (int i = 0; i < 4; i++)
#pragma unroll
        for (int j = 0; j < 4; j++)
#pragma unroll
            for (int f = 0; f < 4; f++) acc[i][j][f] = 0.f;

    gemm_mainloop(sb, Af, Bf, m0, n0, tid, acc);

#pragma unroll
    for (int mt = 0; mt < 4; mt++) {
        int r0 = m0 + wm * 64 + mt * 16 + (l >> 2);
#pragma unroll
        for (int nt = 0; nt < 4; nt++) {
            int c = n0 + wn * 32 + nt * 8 + (l & 3) * 2;
            *(float2*)(C + (size_t)r0 * DMODEL + c) =
                make_float2(acc[mt][nt][0], acc[mt][nt][1]);
            *(float2*)(C + (size_t)(r0 + 8) * DMODEL + c) =
                make_float2(acc[mt][nt][2], acc[mt][nt][3]);
        }
    }
}

// ---------------------------------------------------------------------------
// elementwise converters
// ---------------------------------------------------------------------------
__global__ void f16conv_kernel(const float4* __restrict__ in,
                               __half2* __restrict__ out, int n4)
{
    int i = blockIdx.x * blockDim.x + threadIdx.x;
    if (i >= n4) return;
    float4 v = in[i];
    out[2 * i]     = __floats2half2_rn(v.x, v.y);
    out[2 * i + 1] = __floats2half2_rn(v.z, v.w);
}

// weight transpose: w[K,N] fp32 -> tf[N,K] f16
__global__ void tconv_kernel(const float* __restrict__ w,
                             __half* __restrict__ tf, int Kd, int Nd)
{
    __shared__ float tile[32][33];
    int n0 = blockIdx.x * 32, k0 = blockIdx.y * 32;
    int tx = threadIdx.x, ty = threadIdx.y;
#pragma unroll
    for (int j = 0; j < 32; j += 8)
        tile[ty + j][tx] = w[(size_t)(k0 + ty + j) * Nd + n0 + tx];
    __syncthreads();
#pragma unroll
    for (int j = 0; j < 32; j += 8) {
        float x = tile[tx][ty + j];
        tf[(size_t)(n0 + ty + j) * Kd + k0 + tx] = __float2half(x);
    }
}

// RoPE table precompute (fp64 trig)
__global__ void rope_table_kernel()
{
    int idx = blockIdx.x * blockDim.x + threadIdx.x;
    if (idx >= SEQ * 64) return;
    int i = idx & 63, s = idx >> 6;
    double inv = exp(-0.14391156831212787 * (double)i);
    double sd, cd;
    sincos((double)s * inv, &sd, &cd);
    g_ropec[idx] = (float)cd;
    g_ropes[idx] = (float)sd;
}

// ---------------------------------------------------------------------------
// HMMA flash attention: Q f16 hi/lo, K single f16 (2-product QK), V f16.
// 3-stage KV pipeline; epilogue writes single f16 attn-out.
// ---------------------------------------------------------------------------
#define AT_STAGE0 65536
#define AT_STAGEB 32768
#define AT_SMEM   (AT_STAGE0 + 3 * AT_STAGEB)   // 163840

__device__ __forceinline__ void attn_issue_kv(
    uint32_t stbase, const __half* kfg, const __half* vg, int k0, int tid)
{
    const char* bases[2] = { (const char*)kfg, (const char*)vg };
#pragma unroll
    for (int arr = 0; arr < 2; arr++) {
        const char* base = bases[arr];
        uint32_t soff = stbase + arr * 16384;
#pragma unroll
        for (int i = 0; i < 4; i++) {
            int chunk = tid + i * 256;
            int row = chunk >> 4, cc = chunk & 15;
            const void* gp = base + ((size_t)(k0 + row) * NKVD + cc * 8) * 2;
            uint32_t sp = soff + (cc >> 3) * 8192 + SWZ128(row * 128 + (cc & 7) * 16);
            asm volatile("cp.async.cg.shared.global [%0], [%1], 16;"
                         :: "r"(sp), "l"(gp));
        }
    }
    asm volatile("cp.async.commit_group;" ::: "memory");
}

__global__ __launch_bounds__(256, 1) void hmma_attn_kernel(const float* __restrict__ tptr)
{
    extern __shared__ char smem[];
    const uint32_t sb = smem_u32(smem);
    const int tid = threadIdx.x, w = tid >> 5, l = tid & 31;
    const int qt = blockIdx.x, h = blockIdx.y, b = blockIdx.z;
    const int kv = h >> 2;
    const int q0 = qt * 128;
    const int qw0 = q0 + w * 16;
    const float scale = 0.08838834764831845f / fmaxf(fabsf(tptr[0]), 1e-6f);
    const float sl = scale * 1.4426950408889634f;

    const uint32_t sQh = sb, sQl = sb + 32768;

    const __half* qhg = g_qh + ((size_t)(b * SEQ) + q0) * DMODEL + h * DHEAD;
    const __half* qlg = g_ql + ((size_t)(b * SEQ) + q0) * DMODEL + h * DHEAD;
    const __half* kfg = g_kf + (size_t)(b * SEQ) * NKVD + kv * DHEAD;
    const __half* vg  = g_vf + (size_t)(b * SEQ) * NKVD + kv * DHEAD;

    const int nkt = 2 * qt + 2;

    // prologue
    {
        const char* qb2[2] = { (const char*)qhg, (const char*)qlg };
#pragma unroll
        for (int arr = 0; arr < 2; arr++) {
            uint32_t soff = (arr == 0) ? sQh : sQl;
#pragma unroll
            for (int i = 0; i < 8; i++) {
                int chunk = tid + i * 256;
                int row = chunk >> 4, cc = chunk & 15;
                const void* gp = qb2[arr] + ((size_t)row * DMODEL + cc * 8) * 2;
                uint32_t sp = soff + (cc >> 3) * 16384 + SWZ128(row * 128 + (cc & 7) * 16);
                asm volatile("cp.async.cg.shared.global [%0], [%1], 16;"
                             :: "r"(sp), "l"(gp));
            }
        }
        attn_issue_kv(sb + AT_STAGE0, kfg, vg, 0, tid);
        attn_issue_kv(sb + AT_STAGE0 + AT_STAGEB, kfg, vg, 64, tid);
    }

    const int a_row_l = (l & 7) + (l & 8);
    const int a_col_l = ((l >> 4) & 1) * 16;
    const int b_row_l = (l & 7) + ((l >> 4) & 1) * 8;
    const int b_col_l = ((l >> 3) & 1) * 16;
    const int v_row_l = (l & 7) + ((l >> 3) & 1) * 8;
    const int v_col_l = ((l >> 4) & 1) * 16;

    float oacc[16][4];
    float lacc[4] = {0.f, 0.f, 0.f, 0.f};
#pragma unroll
    for (int i = 0; i < 16; i++)
#pragma unroll
        for (int f = 0; f < 4; f++) oacc[i][f] = 0.f;
    float m0 = -3.0e38f, m1 = -3.0e38f;

    for (int kt = 0; kt < nkt; kt++) {
        if (kt + 1 < nkt) {
            asm volatile("cp.async.wait_group 1;" ::: "memory");
        } else {
            asm volatile("cp.async.wait_group 0;" ::: "memory");
        }
        __syncthreads();
        if (kt + 2 < nkt)
            attn_issue_kv(sb + AT_STAGE0 + ((kt + 2) % 3) * AT_STAGEB,
                          kfg, vg, (kt + 2) * 64, tid);

        const int k0 = kt * 64;
        const uint32_t st = sb + AT_STAGE0 + (kt % 3) * AT_STAGEB;

        if (k0 <= qw0 + 15) {
            float sacc[8][4];
#pragma unroll
            for (int i = 0; i < 8; i++)
#pragma unroll
                for (int f = 0; f < 4; f++) sacc[i][f] = 0.f;

#pragma unroll
            for (int ks = 0; ks < 8; ks++) {
                uint32_t qoff = (ks >> 2) * 16384 +
                    SWZ128((w * 16 + a_row_l) * 128 + (ks & 3) * 32 + a_col_l);
                uint32_t qa[4], qb_[4];
                ldsm4(qa[0], qa[1], qa[2], qa[3], sQh + qoff);
                ldsm4(qb_[0], qb_[1], qb_[2], qb_[3], sQl + qoff);
#pragma unroll
                for (int np = 0; np < 4; np++) {
                    uint32_t koff = st + (ks >> 2) * 8192 +
                        SWZ128((np * 16 + b_row_l) * 128 + (ks & 3) * 32 + b_col_l);
                    uint32_t kf4[4];
                    ldsm4(kf4[0], kf4[1], kf4[2], kf4[3], koff);
                    mma16816h(sacc[2 * np],     qa[0], qa[1], qa[2], qa[3], kf4[0], kf4[1]);
                    mma16816h(sacc[2 * np],     qb_[0], qb_[1], qb_[2], qb_[3], kf4[0], kf4[1]);
                    mma16816h(sacc[2 * np + 1], qa[0], qa[1], qa[2], qa[3], kf4[2], kf4[3]);
                    mma16816h(sacc[2 * np + 1], qb_[0], qb_[1], qb_[2], qb_[3], kf4[2], kf4[3]);
                }
            }

            if (k0 + 63 > qw0) {
                int qa0 = qw0 + (l >> 2), qa1 = qa0 + 8;
                int kc0 = k0 + 2 * (l & 3);
#pragma unroll
                for (int nt = 0; nt < 8; nt++) {
                    int kc = kc0 + nt * 8;
                    if (kc     > qa0) sacc[nt][0] = -3.0e38f;
                    if (kc + 1 > qa0) sacc[nt][1] = -3.0e38f;
                    if (kc     > qa1) sacc[nt][2] = -3.0e38f;
                    if (kc + 1 > qa1) sacc[nt][3] = -3.0e38f;
                }
            }

            float mx0 = -3.0e38f, mx1 = -3.0e38f;
#pragma unroll
            for (int nt = 0; nt < 8; nt++) {
                mx0 = fmaxf(mx0, fmaxf(sacc[nt][0], sacc[nt][1]));
                mx1 = fmaxf(mx1, fmaxf(sacc[nt][2], sacc[nt][3]));
            }
            mx0 = fmaxf(mx0, __shfl_xor_sync(0xffffffffu, mx0, 1));
            mx0 = fmaxf(mx0, __shfl_xor_sync(0xffffffffu, mx0, 2));
            mx1 = fmaxf(mx1, __shfl_xor_sync(0xffffffffu, mx1, 1));
            mx1 = fmaxf(mx1, __shfl_xor_sync(0xffffffffu, mx1, 2));
            float mn0 = fmaxf(m0, mx0), mn1 = fmaxf(m1, mx1);
            bool ch = (mn0 > m0) || (mn1 > m1);
            if (__any_sync(0xffffffffu, ch)) {
                float a0 = exp2f((m0 - mn0) * sl);
                float a1 = exp2f((m1 - mn1) * sl);
#pragma unroll
                for (int nt = 0; nt < 16; nt++) {
                    oacc[nt][0] *= a0; oacc[nt][1] *= a0;
                    oacc[nt][2] *= a1; oacc[nt][3] *= a1;
                }
                lacc[0] *= a0; lacc[1] *= a0; lacc[2] *= a1; lacc[3] *= a1;
            }
            m0 = mn0; m1 = mn1;
            const float bb0 = mn0 * sl, bb1 = mn1 * sl;

            uint32_t pp[8][2];
#pragma unroll
            for (int nt = 0; nt < 8; nt++) {
                float t0 = fmaf(sacc[nt][0], sl, -bb0);
                float t1 = fmaf(sacc[nt][1], sl, -bb0);
                float t2 = fmaf(sacc[nt][2], sl, -bb1);
                float t3 = fmaf(sacc[nt][3], sl, -bb1);
                pp[nt][0] = exp2_f16x2(packf16(t1, t0));
                pp[nt][1] = exp2_f16x2(packf16(t3, t2));
            }

#pragma unroll
            for (int ks = 0; ks < 4; ks++) {
                uint32_t pa0 = pp[2 * ks][0], pa1 = pp[2 * ks][1];
                uint32_t pa2 = pp[2 * ks + 1][0], pa3 = pp[2 * ks + 1][1];
                mma16816h(lacc, pa0, pa1, pa2, pa3, 0x3C003C00u, 0x3C003C00u);
#pragma unroll
                for (int jp = 0; jp < 8; jp++) {
                    uint32_t voff = st + 16384 + (jp >> 2) * 8192 +
                        SWZ128((ks * 16 + v_row_l) * 128 + (jp & 3) * 32 + v_col_l);
                    uint32_t v4[4];
                    ldsm4t(v4[0], v4[1], v4[2], v4[3], voff);
                    mma16816h(oacc[2 * jp],     pa0, pa1, pa2, pa3, v4[0], v4[1]);
                    mma16816h(oacc[2 * jp + 1], pa0, pa1, pa2, pa3, v4[2], v4[3]);
                }
            }
        }
    }

    // epilogue: normalize + single f16 store
    const float inv0 = 1.0f / lacc[0];
    const float inv1 = 1.0f / lacc[2];
    const size_t r0g = (size_t)(b * SEQ) + qw0 + (l >> 2);
    const size_t r1g = r0g + 8;
#pragma unroll
    for (int nt = 0; nt < 16; nt++) {
        int col = h * DHEAD + nt * 8 + 2 * (l & 3);
        *(__half2*)(g_of + r0g * DMODEL + col) =
            __floats2half2_rn(oacc[nt][0] * inv0, oacc[nt][1] * inv0);
        *(__half2*)(g_of + r1g * DMODEL + col) =
            __floats2half2_rn(oacc[nt][2] * inv1, oacc[nt][3] * inv1);
    }
}

// ---------------------------------------------------------------------------
extern "C" void kernel_launch(void* const* d_in, const int* in_sizes, int n_in,
                              void* d_out, int out_size)
{
    const float* x  = (const float*)d_in[0];
    const float* wq = (const float*)d_in[1];
    const float* wk = (const float*)d_in[2];
    const float* wv = (const float*)d_in[3];
    const float* wo = (const float*)d_in[4];
    const float* tp = (const float*)d_in[5];
    float* out = (float*)d_out;

    __half *xf, *of, *wqkv, *wof;
    cudaGetSymbolAddress((void**)&xf, g_xf);
    cudaGetSymbolAddress((void**)&of, g_of);
    cudaGetSymbolAddress((void**)&wqkv, g_wqkv);
    cudaGetSymbolAddress((void**)&wof, g_wof);

    cudaFuncSetAttribute(qkv_gemm_kernel, cudaFuncAttributeMaxDynamicSharedMemorySize, GSMEM3);
    cudaFuncSetAttribute(oproj_gemm_kernel, cudaFuncAttributeMaxDynamicSharedMemorySize, GSMEM3);
    cudaFuncSetAttribute(hmma_attn_kernel, cudaFuncAttributeMaxDynamicSharedMemorySize, AT_SMEM);

    // converters + rope table
    rope_table_kernel<<<(SEQ * 64 + 255) / 256, 256>>>();
    {
        int n4 = MTOT * DMODEL / 4;
        f16conv_kernel<<<(n4 + 255) / 256, 256>>>((const float4*)x, (__half2*)xf, n4);
        tconv_kernel<<<dim3(DMODEL / 32, DMODEL / 32), dim3(32, 8)>>>(wq, wqkv, DMODEL, DMODEL);
        tconv_kernel<<<dim3(NKVD / 32, DMODEL / 32), dim3(32, 8)>>>(
            wk, wqkv + (size_t)DMODEL * DMODEL, DMODEL, NKVD);
        tconv_kernel<<<dim3(NKVD / 32, DMODEL / 32), dim3(32, 8)>>>(
            wv, wqkv + (size_t)(DMODEL + NKVD) * DMODEL, DMODEL, NKVD);
        tconv_kernel<<<dim3(DMODEL / 32, DMODEL / 32), dim3(32, 8)>>>(wo, wof, DMODEL, DMODEL);
    }

    // fused QKV projection + RoPE (single-product f16)
    qkv_gemm_kernel<<<dim3(NQKV / 128, MTOT / 128), 256, GSMEM3>>>(xf, wqkv);

    // flash attention
    hmma_attn_kernel<<<dim3(SEQ / 128, NHEADS, BATCH), 256, AT_SMEM>>>(tp);

    // output projection (single-product f16)
    oproj_gemm_kernel<<<dim3(DMODEL / 128, MTOT / 128), 256, GSMEM3>>>(of, wof, out);
}

// round 9
// speedup vs baseline: 8.3905x; 1.0780x over previous
#include <cuda_runtime.h>
#include <cuda_bf16.h>
#include <cuda_fp16.h>
#include <math.h>
#include <stdint.h>

#define BATCH   4
#define SEQ     2048
#define DMODEL  2048
#define NHEADS  16
#define NKV     4
#define DHEAD   128
#define MTOT    (BATCH * SEQ)          // 8192
#define NKVD    (NKV * DHEAD)          // 512
#define NQKV    (DMODEL + 2 * NKVD)    // 3072

// ---------------- scratch ----------
__device__ __half g_qf[MTOT * DMODEL];                       // roped Q f16
__device__ __half g_kf[MTOT * NKVD];                         // roped K f16
__device__ __half g_vf[MTOT * NKVD];                         // V f16

__device__ __half g_xf[MTOT * DMODEL];                       // x f16
__device__ __half g_of[MTOT * DMODEL];                       // attn out f16
__device__ __half g_wqkv[NQKV * DMODEL];                     // [Wq;Wk;Wv]^T f16
__device__ __half g_wof[DMODEL * DMODEL];

__device__ float g_ropec[SEQ * 64], g_ropes[SEQ * 64];

// ---------------- helpers ---------------------------------------------
__device__ __forceinline__ uint32_t smem_u32(const void* p) {
    uint32_t a;
    asm("{ .reg .u64 t; cvta.to.shared.u64 t, %1; cvt.u32.u64 %0, t; }"
        : "=r"(a) : "l"(p));
    return a;
}
#define SWZ128(o) ((o) ^ (((o) >> 3) & 0x70))

__device__ __forceinline__ void ldsm4(uint32_t& r0, uint32_t& r1,
                                      uint32_t& r2, uint32_t& r3, uint32_t addr) {
    asm volatile("ldmatrix.sync.aligned.m8n8.x4.shared.b16 {%0,%1,%2,%3}, [%4];"
                 : "=r"(r0), "=r"(r1), "=r"(r2), "=r"(r3) : "r"(addr));
}
__device__ __forceinline__ void ldsm4t(uint32_t& r0, uint32_t& r1,
                                       uint32_t& r2, uint32_t& r3, uint32_t addr) {
    asm volatile("ldmatrix.sync.aligned.m8n8.x4.trans.shared.b16 {%0,%1,%2,%3}, [%4];"
                 : "=r"(r0), "=r"(r1), "=r"(r2), "=r"(r3) : "r"(addr));
}
__device__ __forceinline__ void mma16816h(float* c, uint32_t a0, uint32_t a1,
                                          uint32_t a2, uint32_t a3,
                                          uint32_t b0, uint32_t b1) {
    asm volatile(
        "mma.sync.aligned.m16n8k16.row.col.f32.f16.f16.f32 "
        "{%0,%1,%2,%3},{%4,%5,%6,%7},{%8,%9},{%0,%1,%2,%3};"
        : "+f"(c[0]), "+f"(c[1]), "+f"(c[2]), "+f"(c[3])
        : "r"(a0), "r"(a1), "r"(a2), "r"(a3), "r"(b0), "r"(b1));
}
__device__ __forceinline__ uint32_t packf16(float hi, float lo) {
    uint32_t r;
    asm("cvt.rn.f16x2.f32 %0, %1, %2;" : "=r"(r) : "f"(hi), "f"(lo));
    return r;
}
__device__ __forceinline__ uint32_t exp2_f16x2(uint32_t x) {
    uint32_t r;
    asm("ex2.approx.f16x2 %0, %1;" : "=r"(r) : "r"(x));
    return r;
}

// ---------------------------------------------------------------------------
// fp16 single-product GEMM core: C[M,N] = Af[M,K] @ Bf[N,K]^T, fp32 accum.
// CTA 128x128, 8 warps, warp 64x32, BK=64, 3-stage cp.async pipeline.
// ---------------------------------------------------------------------------
#define GKC      64
#define GK       2048
#define GNITER   (GK / GKC)               // 32
#define TILEB    16384                    // 128 rows x 128B
#define STAGEB   (2 * TILEB)              // Af, Bf
#define GSMEM3   (3 * STAGEB)             // 98304

__device__ __forceinline__ void gemm_issue(
    uint32_t sb, int stage, int it,
    const __half* __restrict__ Af, const __half* __restrict__ Bf,
    int m0, int n0, int tid)
{
    const int k0 = it * GKC;
    const __half* srcs[2] = { Af, Bf };
#pragma unroll
    for (int mtx = 0; mtx < 2; mtx++) {
        const __half* src = srcs[mtx];
        const int rowbase = (mtx == 0) ? m0 : n0;
        const uint32_t smb = sb + stage * STAGEB + mtx * TILEB;
#pragma unroll
        for (int j = 0; j < 4; j++) {
            int chunk = tid + j * 256;
            int row = chunk >> 3;
            int c16 = chunk & 7;
            const void* gp = src + (size_t)(rowbase + row) * GK + k0 + c16 * 8;
            uint32_t sp = smb + SWZ128(row * 128 + c16 * 16);
            asm volatile("cp.async.cg.shared.global [%0], [%1], 16;"
                         :: "r"(sp), "l"(gp));
        }
    }
    asm volatile("cp.async.commit_group;" ::: "memory");
}

__device__ __forceinline__ void gemm_mainloop(
    uint32_t sb, const __half* __restrict__ Af, const __half* __restrict__ Bf,
    int m0, int n0, int tid, float acc[4][4][4])
{
    const int wid = tid >> 5, l = tid & 31;
    const int wm = wid >> 2, wn = wid & 3;
    const int a_row_l = (l & 7) + (l & 8);
    const int a_col_l = ((l >> 4) & 1) * 16;
    const int b_row_l = (l & 7) + ((l >> 4) & 1) * 8;
    const int b_col_l = ((l >> 3) & 1) * 16;

    gemm_issue(sb, 0, 0, Af, Bf, m0, n0, tid);
    gemm_issue(sb, 1, 1, Af, Bf, m0, n0, tid);

    for (int it = 0; it < GNITER; it++) {
        if (it + 1 < GNITER) {
            asm volatile("cp.async.wait_group 1;" ::: "memory");
        } else {
            asm volatile("cp.async.wait_group 0;" ::: "memory");
        }
        __syncthreads();
        if (it + 2 < GNITER)
            gemm_issue(sb, (it + 2) % 3, it + 2, Af, Bf, m0, n0, tid);

        const uint32_t stg = sb + (it % 3) * STAGEB;
        const uint32_t sAf = stg;
        const uint32_t sBf = stg + TILEB;

#pragma unroll
        for (int kk = 0; kk < 4; kk++) {
            const int kb = kk * 32;
            uint32_t af4[4][4], bf4[8];
#pragma unroll
            for (int mt = 0; mt < 4; mt++) {
                int row = wm * 64 + mt * 16 + a_row_l;
                uint32_t off = SWZ128(row * 128 + kb + a_col_l);
                ldsm4(af4[mt][0], af4[mt][1], af4[mt][2], af4[mt][3], sAf + off);
            }
#pragma unroll
            for (int nt2 = 0; nt2 < 2; nt2++) {
                int row = wn * 32 + nt2 * 16 + b_row_l;
                uint32_t off = SWZ128(row * 128 + kb + b_col_l);
                ldsm4(bf4[nt2 * 4 + 0], bf4[nt2 * 4 + 1],
                      bf4[nt2 * 4 + 2], bf4[nt2 * 4 + 3], sBf + off);
            }
#pragma unroll
            for (int mt = 0; mt < 4; mt++)
#pragma unroll
                for (int nt = 0; nt < 4; nt++) {
                    uint32_t b0 = bf4[(nt >> 1) * 4 + (nt & 1) * 2];
                    uint32_t b1 = bf4[(nt >> 1) * 4 + (nt & 1) * 2 + 1];
                    mma16816h(acc[mt][nt], af4[mt][0], af4[mt][1],
                              af4[mt][2], af4[mt][3], b0, b1);
                }
        }
    }
}

// Fused QKV projection + RoPE.
// cols [0,2048): Q -> rope -> f16; [2048,2560): K -> rope -> f16;
// [2560,3072): V -> f16.
#define SROW 136   // fp32 staging row stride
__global__ __launch_bounds__(256) void qkv_gemm_kernel(
    const __half* __restrict__ xf, const __half* __restrict__ wqkv)
{
    extern __shared__ char smem[];
    const uint32_t sb = smem_u32(smem);
    const int tid = threadIdx.x, wid = tid >> 5, l = tid & 31;
    const int wm = wid >> 2, wn = wid & 3;
    const int m0 = blockIdx.y * 128;
    const int n0 = blockIdx.x * 128;

    float acc[4][4][4];
#pragma unroll
    for (int i = 0; i < 4; i++)
#pragma unroll
        for (int j = 0; j < 4; j++)
#pragma unroll
            for (int f = 0; f < 4; f++) acc[i][j][f] = 0.f;

    gemm_mainloop(sb, xf, wqkv, m0, n0, tid, acc);

    if (n0 >= DMODEL + NKVD) {
        // V: direct f16 store
        int nb = n0 - DMODEL - NKVD;
#pragma unroll
        for (int mt = 0; mt < 4; mt++) {
            int r0 = m0 + wm * 64 + mt * 16 + (l >> 2);
#pragma unroll
            for (int nt = 0; nt < 4; nt++) {
                int c = nb + wn * 32 + nt * 8 + (l & 3) * 2;
                *(__half2*)(g_vf + (size_t)r0 * NKVD + c) =
                    __floats2half2_rn(acc[mt][nt][0], acc[mt][nt][1]);
                *(__half2*)(g_vf + (size_t)(r0 + 8) * NKVD + c) =
                    __floats2half2_rn(acc[mt][nt][2], acc[mt][nt][3]);
            }
        }
        return;
    }

    // Q or K: stage fp32 tile in smem, apply RoPE, convert, store
    float* sst = (float*)smem;
    __syncthreads();   // mainloop smem no longer needed
#pragma unroll
    for (int mt = 0; mt < 4; mt++) {
        int r0 = wm * 64 + mt * 16 + (l >> 2);
#pragma unroll
        for (int nt = 0; nt < 4; nt++) {
            int c = wn * 32 + nt * 8 + (l & 3) * 2;
            *(float2*)&sst[r0 * SROW + c] = make_float2(acc[mt][nt][0], acc[mt][nt][1]);
            *(float2*)&sst[(r0 + 8) * SROW + c] = make_float2(acc[mt][nt][2], acc[mt][nt][3]);
        }
    }
    __syncthreads();

    const bool isQ = (n0 < DMODEL);
#pragma unroll
    for (int j = 0; j < 4; j++) {
        int rl = (tid >> 3) + j * 32;
        int c8 = (tid & 7) * 8;
        int grow = m0 + rl;
        int s = grow & (SEQ - 1);
        float x1[8], x2[8];
        *(float4*)(x1)     = *(float4*)&sst[rl * SROW + c8];
        *(float4*)(x1 + 4) = *(float4*)&sst[rl * SROW + c8 + 4];
        *(float4*)(x2)     = *(float4*)&sst[rl * SROW + c8 + 64];
        *(float4*)(x2 + 4) = *(float4*)&sst[rl * SROW + c8 + 68];
        const float* tc = g_ropec + s * 64 + c8;
        const float* ts = g_ropes + s * 64 + c8;
        __half h1[8], h2[8];
#pragma unroll
        for (int u = 0; u < 8; u++) {
            float c = tc[u], sn = ts[u];
            h1[u] = __float2half(x1[u] * c - x2[u] * sn);
            h2[u] = __float2half(x2[u] * c + x1[u] * sn);
        }
        if (isQ) {
            size_t base = (size_t)grow * DMODEL + n0 + c8;
            *(uint4*)(g_qf + base)      = *(uint4*)h1;
            *(uint4*)(g_qf + base + 64) = *(uint4*)h2;
        } else {
            size_t base = (size_t)grow * NKVD + (n0 - DMODEL) + c8;
            *(uint4*)(g_kf + base)      = *(uint4*)h1;
            *(uint4*)(g_kf + base + 64) = *(uint4*)h2;
        }
    }
}

// Output projection: N = 2048, fp32 out, single-product
__global__ __launch_bounds__(256) void oproj_gemm_kernel(
    const __half* __restrict__ Af, const __half* __restrict__ Bf,
    float* __restrict__ C)
{
    extern __shared__ char smem[];
    const uint32_t sb = smem_u32(smem);
    const int tid = threadIdx.x, wid = tid >> 5, l = tid & 31;
    const int wm = wid >> 2, wn = wid & 3;
    const int m0 = blockIdx.y * 128;
    const int n0 = blockIdx.x * 128;

    float acc[4][4][4];
#pragma unroll
    for (int i = 0; i < 4; i++)
#pragma unroll
        for (int j = 0; j < 4; j++)
#pragma unroll
            for (int f = 0; f < 4; f++) acc[i][j][f] = 0.f;

    gemm_mainloop(sb, Af, Bf, m0, n0, tid, acc);

#pragma unroll
    for (int mt = 0; mt < 4; mt++) {
        int r0 = m0 + wm * 64 + mt * 16 + (l >> 2);
#pragma unroll
        for (int nt = 0; nt < 4; nt++) {
            int c = n0 + wn * 32 + nt * 8 + (l & 3) * 2;
            *(float2*)(C + (size_t)r0 * DMODEL + c) =
                make_float2(acc[mt][nt][0], acc[mt][nt][1]);
            *(float2*)(C + (size_t)(r0 + 8) * DMODEL + c) =
                make_float2(acc[mt][nt][2], acc[mt][nt][3]);
        }
    }
}

// ---------------------------------------------------------------------------
// elementwise converters
// ---------------------------------------------------------------------------
__global__ void f16conv_kernel(const float4* __restrict__ in,
                               __half2* __restrict__ out, int n4)
{
    int i = blockIdx.x * blockDim.x + threadIdx.x;
    if (i >= n4) return;
    float4 v = in[i];
    out[2 * i]     = __floats2half2_rn(v.x, v.y);
    out[2 * i + 1] = __floats2half2_rn(v.z, v.w);
}

// weight transpose: w[K,N] fp32 -> tf[N,K] f16
__global__ void tconv_kernel(const float* __restrict__ w,
                             __half* __restrict__ tf, int Kd, int Nd)
{
    __shared__ float tile[32][33];
    int n0 = blockIdx.x * 32, k0 = blockIdx.y * 32;
    int tx = threadIdx.x, ty = threadIdx.y;
#pragma unroll
    for (int j = 0; j < 32; j += 8)
        tile[ty + j][tx] = w[(size_t)(k0 + ty + j) * Nd + n0 + tx];
    __syncthreads();
#pragma unroll
    for (int j = 0; j < 32; j += 8) {
        float x = tile[tx][ty + j];
        tf[(size_t)(n0 + ty + j) * Kd + k0 + tx] = __float2half(x);
    }
}

// RoPE table precompute (fp64 trig)
__global__ void rope_table_kernel()
{
    int idx = blockIdx.x * blockDim.x + threadIdx.x;
    if (idx >= SEQ * 64) return;
    int i = idx & 63, s = idx >> 6;
    double inv = exp(-0.14391156831212787 * (double)i);
    double sd, cd;
    sincos((double)s * inv, &sd, &cd);
    g_ropec[idx] = (float)cd;
    g_ropes[idx] = (float)sd;
}

// ---------------------------------------------------------------------------
// HMMA flash attention: Q, K, V all single f16 (1-product QK).
// 3-stage KV pipeline; epilogue writes single f16 attn-out.
// ---------------------------------------------------------------------------
#define AT_STAGE0 32768
#define AT_STAGEB 32768
#define AT_SMEM   (AT_STAGE0 + 3 * AT_STAGEB)   // 131072

__device__ __forceinline__ void attn_issue_kv(
    uint32_t stbase, const __half* kfg, const __half* vg, int k0, int tid)
{
    const char* bases[2] = { (const char*)kfg, (const char*)vg };
#pragma unroll
    for (int arr = 0; arr < 2; arr++) {
        const char* base = bases[arr];
        uint32_t soff = stbase + arr * 16384;
#pragma unroll
        for (int i = 0; i < 4; i++) {
            int chunk = tid + i * 256;
            int row = chunk >> 4, cc = chunk & 15;
            const void* gp = base + ((size_t)(k0 + row) * NKVD + cc * 8) * 2;
            uint32_t sp = soff + (cc >> 3) * 8192 + SWZ128(row * 128 + (cc & 7) * 16);
            asm volatile("cp.async.cg.shared.global [%0], [%1], 16;"
                         :: "r"(sp), "l"(gp));
        }
    }
    asm volatile("cp.async.commit_group;" ::: "memory");
}

__global__ __launch_bounds__(256, 1) void hmma_attn_kernel(const float* __restrict__ tptr)
{
    extern __shared__ char smem[];
    const uint32_t sb = smem_u32(smem);
    const int tid = threadIdx.x, w = tid >> 5, l = tid & 31;
    // heaviest q-tiles first (LPT scheduling)
    const int qt = gridDim.x - 1 - blockIdx.x;
    const int h = blockIdx.y, b = blockIdx.z;
    const int kv = h >> 2;
    const int q0 = qt * 128;
    const int qw0 = q0 + w * 16;
    const float scale = 0.08838834764831845f / fmaxf(fabsf(tptr[0]), 1e-6f);
    const float sl = scale * 1.4426950408889634f;

    const uint32_t sQ = sb;

    const __half* qfg = g_qf + ((size_t)(b * SEQ) + q0) * DMODEL + h * DHEAD;
    const __half* kfg = g_kf + (size_t)(b * SEQ) * NKVD + kv * DHEAD;
    const __half* vg  = g_vf + (size_t)(b * SEQ) * NKVD + kv * DHEAD;

    const int nkt = 2 * qt + 2;

    // prologue: group0 = Q + kv0, group1 = kv1
    {
#pragma unroll
        for (int i = 0; i < 8; i++) {
            int chunk = tid + i * 256;
            int row = chunk >> 4, cc = chunk & 15;
            const void* gp = (const char*)qfg + ((size_t)row * DMODEL + cc * 8) * 2;
            uint32_t sp = sQ + (cc >> 3) * 16384 + SWZ128(row * 128 + (cc & 7) * 16);
            asm volatile("cp.async.cg.shared.global [%0], [%1], 16;"
                         :: "r"(sp), "l"(gp));
        }
        attn_issue_kv(sb + AT_STAGE0, kfg, vg, 0, tid);
        attn_issue_kv(sb + AT_STAGE0 + AT_STAGEB, kfg, vg, 64, tid);
    }

    const int a_row_l = (l & 7) + (l & 8);
    const int a_col_l = ((l >> 4) & 1) * 16;
    const int b_row_l = (l & 7) + ((l >> 4) & 1) * 8;
    const int b_col_l = ((l >> 3) & 1) * 16;
    const int v_row_l = (l & 7) + ((l >> 3) & 1) * 8;
    const int v_col_l = ((l >> 4) & 1) * 16;

    float oacc[16][4];
    float lacc[4] = {0.f, 0.f, 0.f, 0.f};
#pragma unroll
    for (int i = 0; i < 16; i++)
#pragma unroll
        for (int f = 0; f < 4; f++) oacc[i][f] = 0.f;
    float m0 = -3.0e38f, m1 = -3.0e38f;

    for (int kt = 0; kt < nkt; kt++) {
        if (kt + 1 < nkt) {
            asm volatile("cp.async.wait_group 1;" ::: "memory");
        } else {
            asm volatile("cp.async.wait_group 0;" ::: "memory");
        }
        __syncthreads();
        if (kt + 2 < nkt)
            attn_issue_kv(sb + AT_STAGE0 + ((kt + 2) % 3) * AT_STAGEB,
                          kfg, vg, (kt + 2) * 64, tid);

        const int k0 = kt * 64;
        const uint32_t st = sb + AT_STAGE0 + (kt % 3) * AT_STAGEB;

        if (k0 <= qw0 + 15) {
            float sacc[8][4];
#pragma unroll
            for (int i = 0; i < 8; i++)
#pragma unroll
                for (int f = 0; f < 4; f++) sacc[i][f] = 0.f;

#pragma unroll
            for (int ks = 0; ks < 8; ks++) {
                uint32_t qoff = (ks >> 2) * 16384 +
                    SWZ128((w * 16 + a_row_l) * 128 + (ks & 3) * 32 + a_col_l);
                uint32_t qa[4];
                ldsm4(qa[0], qa[1], qa[2], qa[3], sQ + qoff);
#pragma unroll
                for (int np = 0; np < 4; np++) {
                    uint32_t koff = st + (ks >> 2) * 8192 +
                        SWZ128((np * 16 + b_row_l) * 128 + (ks & 3) * 32 + b_col_l);
                    uint32_t kf4[4];
                    ldsm4(kf4[0], kf4[1], kf4[2], kf4[3], koff);
                    mma16816h(sacc[2 * np],     qa[0], qa[1], qa[2], qa[3], kf4[0], kf4[1]);
                    mma16816h(sacc[2 * np + 1], qa[0], qa[1], qa[2], qa[3], kf4[2], kf4[3]);
                }
            }

            if (k0 + 63 > qw0) {
                int qa0 = qw0 + (l >> 2), qa1 = qa0 + 8;
                int kc0 = k0 + 2 * (l & 3);
#pragma unroll
                for (int nt = 0; nt < 8; nt++) {
                    int kc = kc0 + nt * 8;
                    if (kc     > qa0) sacc[nt][0] = -3.0e38f;
                    if (kc + 1 > qa0) sacc[nt][1] = -3.0e38f;
                    if (kc     > qa1) sacc[nt][2] = -3.0e38f;
                    if (kc + 1 > qa1) sacc[nt][3] = -3.0e38f;
                }
            }

            float mx0 = -3.0e38f, mx1 = -3.0e38f;
#pragma unroll
            for (int nt = 0; nt < 8; nt++) {
                mx0 = fmaxf(mx0, fmaxf(sacc[nt][0], sacc[nt][1]));
                mx1 = fmaxf(mx1, fmaxf(sacc[nt][2], sacc[nt][3]));
            }
            mx0 = fmaxf(mx0, __shfl_xor_sync(0xffffffffu, mx0, 1));
            mx0 = fmaxf(mx0, __shfl_xor_sync(0xffffffffu, mx0, 2));
            mx1 = fmaxf(mx1, __shfl_xor_sync(0xffffffffu, mx1, 1));
            mx1 = fmaxf(mx1, __shfl_xor_sync(0xffffffffu, mx1, 2));
            float mn0 = fmaxf(m0, mx0), mn1 = fmaxf(m1, mx1);
            bool ch = (mn0 > m0) || (mn1 > m1);
            if (__any_sync(0xffffffffu, ch)) {
                float a0 = exp2f((m0 - mn0) * sl);
                float a1 = exp2f((m1 - mn1) * sl);
#pragma unroll
                for (int nt = 0; nt < 16; nt++) {
                    oacc[nt][0] *= a0; oacc[nt][1] *= a0;
                    oacc[nt][2] *= a1; oacc[nt][3] *= a1;
                }
                lacc[0] *= a0; lacc[1] *= a0; lacc[2] *= a1; lacc[3] *= a1;
            }
            m0 = mn0; m1 = mn1;
            const float bb0 = mn0 * sl, bb1 = mn1 * sl;

            uint32_t pp[8][2];
#pragma unroll
            for (int nt = 0; nt < 8; nt++) {
                float t0 = fmaf(sacc[nt][0], sl, -bb0);
                float t1 = fmaf(sacc[nt][1], sl, -bb0);
                float t2 = fmaf(sacc[nt][2], sl, -bb1);
                float t3 = fmaf(sacc[nt][3], sl, -bb1);
                pp[nt][0] = exp2_f16x2(packf16(t1, t0));
                pp[nt][1] = exp2_f16x2(packf16(t3, t2));
            }

#pragma unroll
            for (int ks = 0; ks < 4; ks++) {
                uint32_t pa0 = pp[2 * ks][0], pa1 = pp[2 * ks][1];
                uint32_t pa2 = pp[2 * ks + 1][0], pa3 = pp[2 * ks + 1][1];
                mma16816h(lacc, pa0, pa1, pa2, pa3, 0x3C003C00u, 0x3C003C00u);
#pragma unroll
                for (int jp = 0; jp < 8; jp++) {
                    uint32_t voff = st + 16384 + (jp >> 2) * 8192 +
                        SWZ128((ks * 16 + v_row_l) * 128 + (jp & 3) * 32 + v_col_l);
                    uint32_t v4[4];
                    ldsm4t(v4[0], v4[1], v4[2], v4[3], voff);
                    mma16816h(oacc[2 * jp],     pa0, pa1, pa2, pa3, v4[0], v4[1]);
                    mma16816h(oacc[2 * jp + 1], pa0, pa1, pa2, pa3, v4[2], v4[3]);
                }
            }
        }
    }

    // epilogue: normalize + single f16 store
    const float inv0 = 1.0f / lacc[0];
    const float inv1 = 1.0f / lacc[2];
    const size_t r0g = (size_t)(b * SEQ) + qw0 + (l >> 2);
    const size_t r1g = r0g + 8;
#pragma unroll
    for (int nt = 0; nt < 16; nt++) {
        int col = h * DHEAD + nt * 8 + 2 * (l & 3);
        *(__half2*)(g_of + r0g * DMODEL + col) =
            __floats2half2_rn(oacc[nt][0] * inv0, oacc[nt][1] * inv0);
        *(__half2*)(g_of + r1g * DMODEL + col) =
            __floats2half2_rn(oacc[nt][2] * inv1, oacc[nt][3] * inv1);
    }
}

// ---------------------------------------------------------------------------
extern "C" void kernel_launch(void* const* d_in, const int* in_sizes, int n_in,
                              void* d_out, int out_size)
{
    const float* x  = (const float*)d_in[0];
    const float* wq = (const float*)d_in[1];
    const float* wk = (const float*)d_in[2];
    const float* wv = (const float*)d_in[3];
    const float* wo = (const float*)d_in[4];
    const float* tp = (const float*)d_in[5];
    float* out = (float*)d_out;

    __half *xf, *of, *wqkv, *wof;
    cudaGetSymbolAddress((void**)&xf, g_xf);
    cudaGetSymbolAddress((void**)&of, g_of);
    cudaGetSymbolAddress((void**)&wqkv, g_wqkv);
    cudaGetSymbolAddress((void**)&wof, g_wof);

    cudaFuncSetAttribute(qkv_gemm_kernel, cudaFuncAttributeMaxDynamicSharedMemorySize, GSMEM3);
    cudaFuncSetAttribute(oproj_gemm_kernel, cudaFuncAttributeMaxDynamicSharedMemorySize, GSMEM3);
    cudaFuncSetAttribute(hmma_attn_kernel, cudaFuncAttributeMaxDynamicSharedMemorySize, AT_SMEM);

    // converters + rope table
    rope_table_kernel<<<(SEQ * 64 + 255) / 256, 256>>>();
    {
        int n4 = MTOT * DMODEL / 4;
        f16conv_kernel<<<(n4 + 255) / 256, 256>>>((const float4*)x, (__half2*)xf, n4);
        tconv_kernel<<<dim3(DMODEL / 32, DMODEL / 32), dim3(32, 8)>>>(wq, wqkv, DMODEL, DMODEL);
        tconv_kernel<<<dim3(NKVD / 32, DMODEL / 32), dim3(32, 8)>>>(
            wk, wqkv + (size_t)DMODEL * DMODEL, DMODEL, NKVD);
        tconv_kernel<<<dim3(NKVD / 32, DMODEL / 32), dim3(32, 8)>>>(
            wv, wqkv + (size_t)(DMODEL + NKVD) * DMODEL, DMODEL, NKVD);
        tconv_kernel<<<dim3(DMODEL / 32, DMODEL / 32), dim3(32, 8)>>>(wo, wof, DMODEL, DMODEL);
    }

    // fused QKV projection + RoPE (single-product f16)
    qkv_gemm_kernel<<<dim3(NQKV / 128, MTOT / 128), 256, GSMEM3>>>(xf, wqkv);

    // flash attention (single-product QK)
    hmma_attn_kernel<<<dim3(SEQ / 128, NHEADS, BATCH), 256, AT_SMEM>>>(tp);

    // output projection (single-product f16)
    oproj_gemm_kernel<<<dim3(DMODEL / 128, MTOT / 128), 256, GSMEM3>>>(of, wof, out);
}